// round 14
// baseline (speedup 1.0000x reference)
#include <cuda_runtime.h>
#include <cuda_bf16.h>
#include <cstdint>

#define DD 256
static const int NE  = 50000;
static const int NO  = 100000;
static const int NN  = 150000;
static const int E1N = 400000;
static const int E2N = 800000;

// -------- device scratch --------
__device__ float    g_X  [(size_t)NN * DD];
__device__ float    g_obj[(size_t)NO * DD];
__device__ float    g_msg[(size_t)NO * DD];
__device__ float    g_Xm [(size_t)NE * DD];
__device__ float    g_H  [(size_t)NN * DD];
__device__ float    g_ef [(size_t)NE * DD];
__device__ float    g_snode[NN];
__device__ float    g_sedge[NE];
__device__ float    g_wav1[DD];
__device__ float    g_wav2[DD];
__device__ unsigned char g_Wprep[6 * 4 * 2 * 256 * 128];
// CSR structures (value-direct; edge CSR partitioned ev-front / obj-back)
__device__ int g_cntE[NE],  g_offE[NE],  g_nodeE[E2N];
__device__ int g_cntN[NN],  g_offN[NN],  g_permN[E2N], g_edN[E2N];
__device__ int g_cntO[NO],  g_offO[NO],  g_srcO[E1N];
__device__ int g_cur[NE + NN + NO];    // edge portion doubles as evCnt after fill
__device__ int g_curB[NE];
__device__ int g_bsum[512];

static const int NBE = (NE + 1023) / 1024;
static const int NBN = (NN + 1023) / 1024;
static const int NBO = (NO + 1023) / 1024;
static const int NBT = NBE + NBN + NBO;

// -------- helpers --------
__device__ __forceinline__ float lrelu_f(float x) { return x >= 0.f ? x : 0.2f * x; }

__device__ __forceinline__ uint32_t smem_to_u32(const void* p) {
    uint32_t a;
    asm("{ .reg .u64 t; cvta.to.shared.u64 t, %1; cvt.u32.u64 %0, t; }" : "=r"(a) : "l"(p));
    return a;
}
__device__ __forceinline__ void ldm_x4(uint32_t addr, uint32_t* r) {
    asm volatile("ldmatrix.sync.aligned.m8n8.x4.shared.b16 {%0,%1,%2,%3}, [%4];"
                 : "=r"(r[0]), "=r"(r[1]), "=r"(r[2]), "=r"(r[3]) : "r"(addr));
}
__device__ __forceinline__ void mma_bf16(float* c, const uint32_t* a, const uint32_t* b) {
    asm volatile("mma.sync.aligned.m16n8k16.row.col.f32.bf16.bf16.f32 "
                 "{%0,%1,%2,%3}, {%4,%5,%6,%7}, {%8,%9}, {%0,%1,%2,%3};"
                 : "+f"(c[0]), "+f"(c[1]), "+f"(c[2]), "+f"(c[3])
                 : "r"(a[0]), "r"(a[1]), "r"(a[2]), "r"(a[3]), "r"(b[0]), "r"(b[1]));
}
__device__ __forceinline__ uint32_t swz(uint32_t row, uint32_t cb) {
    return row * 128u + (cb ^ ((row & 7u) << 4));
}
__device__ __forceinline__ uint32_t swz512(uint32_t row, uint32_t cb) {
    return row * 512u + (cb ^ ((row & 7u) << 4));
}
#define CP_ASYNC16(dst, src) \
    asm volatile("cp.async.cg.shared.global [%0], [%1], 16;" :: "r"(dst), "l"(src) : "memory")
#define CP_COMMIT() asm volatile("cp.async.commit_group;" ::: "memory")
#define CP_WAIT(n)  asm volatile("cp.async.wait_group %0;" :: "n"(n) : "memory")

enum { F_SNODE = 16 };

// ======== condensed CSR build ========
__global__ void zero_misc()
{
    int g = blockIdx.x * blockDim.x + threadIdx.x;
    const int T = NE + NN + NO;
    if (g < NE) g_cntE[g] = 0;
    else if (g < NE + NN) g_cntN[g - NE] = 0;
    else if (g < T) g_cntO[g - NE - NN] = 0;
    int h = g - T;
    if (h >= 0 && h < T) g_cur[h] = 0;
    int k = g - 2 * T;
    if (k >= 0 && k < NE) g_curB[k] = 0;
}
__global__ void count_all(const int* __restrict__ he, const int* __restrict__ hn,
                          const int* __restrict__ oo)
{
    int t = blockIdx.x * blockDim.x + threadIdx.x;
    if (t < E2N) atomicAdd(&g_cntE[he[t]], 1);
    else if (t < 2 * E2N) atomicAdd(&g_cntN[hn[t - E2N]], 1);
    else if (t < 2 * E2N + E1N) atomicAdd(&g_cntO[oo[t - 2 * E2N]], 1);
}
__global__ void scan_all()
{
    __shared__ int sh[1024];
    int b = blockIdx.x;
    const int* cnt; int* off; int nseg; int lb;
    if (b < NBE)            { cnt = g_cntE; off = g_offE; nseg = NE; lb = b; }
    else if (b < NBE + NBN) { cnt = g_cntN; off = g_offN; nseg = NN; lb = b - NBE; }
    else                    { cnt = g_cntO; off = g_offO; nseg = NO; lb = b - NBE - NBN; }
    int g = lb * 1024 + threadIdx.x;
    int v = (g < nseg) ? cnt[g] : 0;
    sh[threadIdx.x] = v;
    __syncthreads();
#pragma unroll
    for (int o = 1; o < 1024; o <<= 1) {
        int t = (threadIdx.x >= o) ? sh[threadIdx.x - o] : 0;
        __syncthreads();
        sh[threadIdx.x] += t;
        __syncthreads();
    }
    if (g < nseg) off[g] = sh[threadIdx.x] - v;
    if (threadIdx.x == 1023) g_bsum[b] = sh[1023];
}
__global__ void scan_small3()
{
    int t = threadIdx.x;
    int s, e;
    if (t == 0)      { s = 0;          e = NBE; }
    else if (t == 1) { s = NBE;        e = NBE + NBN; }
    else if (t == 2) { s = NBE + NBN;  e = NBT; }
    else return;
    int run = 0;
    for (int i = s; i < e; i++) { int v = g_bsum[i]; g_bsum[i] = run; run += v; }
}
__global__ void add_off_all()
{
    int g = blockIdx.x * blockDim.x + threadIdx.x;
    if (g < NE) g_offE[g] += g_bsum[g >> 10];
    else if (g < NE + NN) {
        int l = g - NE; g_offN[l] += g_bsum[NBE + (l >> 10)];
    } else if (g < NE + NN + NO) {
        int l = g - NE - NN; g_offO[l] += g_bsum[NBE + NBN + (l >> 10)];
    }
}
// edge CSR: ev nodes fill from the front, obj nodes from the back.
// After this kernel, g_cur[e] == number of ev-node entries for edge e.
__global__ void fill_all(const int* __restrict__ he, const int* __restrict__ hn,
                         const int* __restrict__ oo, const int* __restrict__ oev)
{
    int t = blockIdx.x * blockDim.x + threadIdx.x;
    if (t < E2N) {
        int s = he[t];
        int node = hn[t];
        int pos;
        if (node < NE) pos = g_offE[s] + atomicAdd(&g_cur[s], 1);
        else           pos = g_offE[s] + g_cntE[s] - 1 - atomicAdd(&g_curB[s], 1);
        g_nodeE[pos] = node;
    } else if (t < 2 * E2N) {
        int e = t - E2N;
        int s = hn[e];
        int pos = g_offN[s] + atomicAdd(&g_cur[NE + s], 1);
        g_permN[pos] = e;
        g_edN[pos]   = he[e];
    } else if (t < 2 * E2N + E1N) {
        int e = t - 2 * E2N;
        int s = oo[e];
        int pos = g_offO[s] + atomicAdd(&g_cur[NE + NN + s], 1);
        g_srcO[pos] = oev[e];
    }
}

// -------- weight prep --------
__global__ void prep_w(const float* W0, const float* W1, const float* W2,
                       const float* W3, const float* W4, const float* W5)
{
    const float* Ws[6] = {W0, W1, W2, W3, W4, W5};
    const float* W = Ws[blockIdx.y];
    unsigned char* base = g_Wprep + (size_t)blockIdx.y * 262144;
    int g = blockIdx.x * 256 + threadIdx.x;
    int n = g >> 5, kg = g & 31, k0 = kg * 8;
    unsigned short hi[8], lo[8];
#pragma unroll
    for (int i = 0; i < 8; i++) {
        float x = W[(size_t)(k0 + i) * DD + n];
        __nv_bfloat16 h = __float2bfloat16(x);
        __nv_bfloat16 l = __float2bfloat16(x - __bfloat162float(h));
        hi[i] = *reinterpret_cast<unsigned short*>(&h);
        lo[i] = *reinterpret_cast<unsigned short*>(&l);
    }
    int chunk = k0 >> 6, kc = k0 & 63;
    uint32_t off = (uint32_t)n * 128u + (((uint32_t)kc * 2u) ^ (((uint32_t)n & 7u) << 4));
    *reinterpret_cast<uint4*>(base + (size_t)(chunk * 2 + 0) * 32768 + off) =
        *reinterpret_cast<uint4*>(hi);
    *reinterpret_cast<uint4*>(base + (size_t)(chunk * 2 + 1) * 32768 + off) =
        *reinterpret_cast<uint4*>(lo);
}

__global__ void prep_wav(const float* __restrict__ W, const float* __restrict__ a,
                         float* __restrict__ w)
{
    int k = blockIdx.x * 8 + (threadIdx.x >> 5);
    if (k >= DD) return;
    int lane = threadIdx.x & 31;
    const float4* rp = reinterpret_cast<const float4*>(W + (size_t)k * DD);
    const float4* ap = reinterpret_cast<const float4*>(a);
    float4 v0 = rp[lane], v1 = rp[lane + 32];
    float4 a0 = ap[lane], a1 = ap[lane + 32];
    float d = v0.x*a0.x + v0.y*a0.y + v0.z*a0.z + v0.w*a0.w
            + v1.x*a1.x + v1.y*a1.y + v1.z*a1.z + v1.w*a1.w;
#pragma unroll
    for (int o = 16; o; o >>= 1) d += __shfl_xor_sync(0xFFFFFFFFu, d, o);
    if (lane == 0) w[k] = d;
}

static const int SMEM_SZ = 196608;

// ======== combined projection GEMM (job select by blockIdx vs nb0) ========
__global__ __launch_bounds__(512, 1)
void proj_gemm(const float* __restrict__ A0, const unsigned char* __restrict__ Wp0,
               const float* __restrict__ bias0, const float* __restrict__ lng0,
               const float* __restrict__ lnb0, float* __restrict__ C0,
               const float* __restrict__ av0, float* __restrict__ snode0, int M0, int nb0,
               const float* __restrict__ A1, const unsigned char* __restrict__ Wp1,
               const float* __restrict__ bias1, const float* __restrict__ lng1,
               const float* __restrict__ lnb1, float* __restrict__ C1, int M1)
{
    extern __shared__ __align__(128) unsigned char smem[];
    const uint32_t sb = smem_to_u32(smem);
    const int tid = threadIdx.x, lane = tid & 31, wid = tid >> 5;
    const int warpM = wid >> 2, warpN = wid & 3;

    const float* A; const unsigned char* Wp; const float* bias;
    const float* lng; const float* lnb; float* C;
    const float* av; float* snode; int Mrows, rowBase;
    if ((int)blockIdx.x < nb0) {
        A = A0; Wp = Wp0; bias = bias0; lng = lng0; lnb = lnb0; C = C0;
        av = av0; snode = snode0; Mrows = M0; rowBase = blockIdx.x * 128;
    } else {
        A = A1; Wp = Wp1; bias = bias1; lng = lng1; lnb = lnb1; C = C1;
        av = nullptr; snode = nullptr; Mrows = M1; rowBase = (blockIdx.x - nb0) * 128;
    }

    int rA[2], cgA[2];
#pragma unroll
    for (int i = 0; i < 2; i++) {
        int g = tid + i * 512;
        rA[i] = g >> 3; cgA[i] = g & 7;
    }
    float4 pref[4];

    auto issueA = [&](int ch) {
#pragma unroll
        for (int i = 0; i < 2; i++) {
            int row = rowBase + rA[i];
            if (row < Mrows) {
                const float4* src = reinterpret_cast<const float4*>(
                    A + (size_t)row * DD + ch * 64 + cgA[i] * 8);
                pref[i * 2]     = src[0];
                pref[i * 2 + 1] = src[1];
            } else {
                pref[i * 2]     = make_float4(0.f, 0.f, 0.f, 0.f);
                pref[i * 2 + 1] = make_float4(0.f, 0.f, 0.f, 0.f);
            }
        }
    };
    auto storeA = [&](int s) {
#pragma unroll
        for (int i = 0; i < 2; i++) {
            float x[8];
            float4 v0 = pref[i * 2], v1 = pref[i * 2 + 1];
            x[0] = v0.x; x[1] = v0.y; x[2] = v0.z; x[3] = v0.w;
            x[4] = v1.x; x[5] = v1.y; x[6] = v1.z; x[7] = v1.w;
            unsigned short hi[8], lo[8];
#pragma unroll
            for (int j = 0; j < 8; j++) {
                __nv_bfloat16 h = __float2bfloat16(x[j]);
                __nv_bfloat16 l = __float2bfloat16(x[j] - __bfloat162float(h));
                hi[j] = *reinterpret_cast<unsigned short*>(&h);
                lo[j] = *reinterpret_cast<unsigned short*>(&l);
            }
            uint32_t off = s * 32768u + swz((uint32_t)rA[i], (uint32_t)cgA[i] * 16u);
            *reinterpret_cast<uint4*>(smem + off)         = *reinterpret_cast<uint4*>(hi);
            *reinterpret_cast<uint4*>(smem + 16384 + off) = *reinterpret_cast<uint4*>(lo);
        }
    };
    auto issueB = [&](int ch, int s) {
        const unsigned char* bh = Wp + (size_t)(ch * 2 + 0) * 32768;
        const unsigned char* bl = Wp + (size_t)(ch * 2 + 1) * 32768;
        uint32_t dh = sb + 65536u + (uint32_t)s * 65536u;
        uint32_t dl = dh + 32768u;
#pragma unroll
        for (int i = 0; i < 4; i++) {
            int idx = (tid + i * 512) * 16;
            CP_ASYNC16(dh + idx, bh + idx);
            CP_ASYNC16(dl + idx, bl + idx);
        }
        CP_COMMIT();
    };

    float c[2][8][4];
#pragma unroll
    for (int mt = 0; mt < 2; mt++)
#pragma unroll
        for (int nt = 0; nt < 8; nt++)
#pragma unroll
            for (int q = 0; q < 4; q++) c[mt][nt][q] = 0.f;

    issueA(0);
    issueB(0, 0);
    storeA(0);

    for (int ch = 0; ch < 4; ch++) {
        const int s = ch & 1;
        if (ch < 3) {
            issueA(ch + 1);
            issueB(ch + 1, s ^ 1);
            CP_WAIT(1);
        } else {
            CP_WAIT(0);
        }
        __syncthreads();

        const uint32_t aBase = sb + (uint32_t)s * 32768u;
        const uint32_t bBase = sb + 65536u + (uint32_t)s * 65536u;
#pragma unroll
        for (int ks = 0; ks < 4; ks++) {
            uint32_t ah[2][4], al[2][4];
#pragma unroll
            for (int mt = 0; mt < 2; mt++) {
                uint32_t row = (uint32_t)(warpM * 32 + mt * 16 + (lane & 7) + ((lane >> 3) & 1) * 8);
                uint32_t kb  = (uint32_t)(ks * 32 + ((lane >> 4) & 1) * 16);
                uint32_t addr = aBase + swz(row, kb);
                ldm_x4(addr,         ah[mt]);
                ldm_x4(addr + 16384, al[mt]);
            }
#pragma unroll
            for (int p = 0; p < 4; p++) {
                uint32_t nrow = (uint32_t)(warpN * 64 + p * 16 + (lane & 7) + ((lane >> 4) & 1) * 8);
                uint32_t kb   = (uint32_t)(ks * 32 + ((lane >> 3) & 1) * 16);
                uint32_t addr = bBase + swz(nrow, kb);
                uint32_t bh[4], bl[4];
                ldm_x4(addr,         bh);
                ldm_x4(addr + 32768, bl);
#pragma unroll
                for (int t = 0; t < 2; t++) {
#pragma unroll
                    for (int mt = 0; mt < 2; mt++) {
                        float* cc = c[mt][p * 2 + t];
                        mma_bf16(cc, ah[mt], bh + t * 2);
                        mma_bf16(cc, ah[mt], bl + t * 2);
                        mma_bf16(cc, al[mt], bh + t * 2);
                    }
                }
            }
        }
        if (ch < 3) storeA(s ^ 1);
        __syncthreads();
    }

    const int gid = lane >> 2, tig = lane & 3;
    float2* rb = reinterpret_cast<float2*>(smem);

#pragma unroll
    for (int mt = 0; mt < 2; mt++)
#pragma unroll
        for (int nt = 0; nt < 8; nt++) {
            int col = warpN * 64 + nt * 8 + tig * 2;
            float2 bv = *reinterpret_cast<const float2*>(bias + col);
            c[mt][nt][0] = lrelu_f(c[mt][nt][0] + bv.x);
            c[mt][nt][1] = lrelu_f(c[mt][nt][1] + bv.y);
            c[mt][nt][2] = lrelu_f(c[mt][nt][2] + bv.x);
            c[mt][nt][3] = lrelu_f(c[mt][nt][3] + bv.y);
        }

#pragma unroll
    for (int mt = 0; mt < 2; mt++) {
        float s0 = 0.f, q0 = 0.f, s1 = 0.f, q1 = 0.f;
#pragma unroll
        for (int nt = 0; nt < 8; nt++) {
            float o0 = c[mt][nt][0], o1 = c[mt][nt][1];
            float o2 = c[mt][nt][2], o3 = c[mt][nt][3];
            s0 += o0 + o1; q0 += o0 * o0 + o1 * o1;
            s1 += o2 + o3; q1 += o2 * o2 + o3 * o3;
        }
#pragma unroll
        for (int o = 1; o < 4; o <<= 1) {
            s0 += __shfl_xor_sync(0xFFFFFFFFu, s0, o);
            q0 += __shfl_xor_sync(0xFFFFFFFFu, q0, o);
            s1 += __shfl_xor_sync(0xFFFFFFFFu, s1, o);
            q1 += __shfl_xor_sync(0xFFFFFFFFu, q1, o);
        }
        if (tig == 0) {
            int lr0 = warpM * 32 + mt * 16 + gid;
            rb[lr0 * 4 + warpN]       = make_float2(s0, q0);
            rb[(lr0 + 8) * 4 + warpN] = make_float2(s1, q1);
        }
    }
    __syncthreads();

    float sd[2][2] = {{0.f, 0.f}, {0.f, 0.f}};
#pragma unroll
    for (int mt = 0; mt < 2; mt++) {
        int lr0 = warpM * 32 + mt * 16 + gid;
        int lr1 = lr0 + 8;
        float2 p00 = rb[lr0*4+0], p01 = rb[lr0*4+1], p02 = rb[lr0*4+2], p03 = rb[lr0*4+3];
        float2 p10 = rb[lr1*4+0], p11 = rb[lr1*4+1], p12 = rb[lr1*4+2], p13 = rb[lr1*4+3];
        float sum0 = p00.x + p01.x + p02.x + p03.x;
        float sq0  = p00.y + p01.y + p02.y + p03.y;
        float sum1 = p10.x + p11.x + p12.x + p13.x;
        float sq1  = p10.y + p11.y + p12.y + p13.y;
        float mean0 = sum0 * (1.f / 256.f);
        float rstd0 = rsqrtf(sq0 * (1.f / 256.f) - mean0 * mean0 + 1e-5f);
        float mean1 = sum1 * (1.f / 256.f);
        float rstd1 = rsqrtf(sq1 * (1.f / 256.f) - mean1 * mean1 + 1e-5f);
        int r0 = rowBase + lr0, r1 = rowBase + lr1;
        bool v0 = r0 < Mrows, v1 = r1 < Mrows;
#pragma unroll
        for (int nt = 0; nt < 8; nt++) {
            int col = warpN * 64 + nt * 8 + tig * 2;
            float2 gv = *reinterpret_cast<const float2*>(lng + col);
            float2 bv = *reinterpret_cast<const float2*>(lnb + col);
            float o0 = (c[mt][nt][0] - mean0) * rstd0 * gv.x + bv.x;
            float o1 = (c[mt][nt][1] - mean0) * rstd0 * gv.y + bv.y;
            float o2 = (c[mt][nt][2] - mean1) * rstd1 * gv.x + bv.x;
            float o3 = (c[mt][nt][3] - mean1) * rstd1 * gv.y + bv.y;
            if (v0) *reinterpret_cast<float2*>(C + (size_t)r0 * DD + col) = make_float2(o0, o1);
            if (v1) *reinterpret_cast<float2*>(C + (size_t)r1 * DD + col) = make_float2(o2, o3);
            if (snode != nullptr) {
                float2 avv = *reinterpret_cast<const float2*>(av + col);
                sd[mt][0] += o0 * avv.x + o1 * avv.y;
                sd[mt][1] += o2 * avv.x + o3 * avv.y;
            }
        }
    }

    if (snode != nullptr) {
        __syncthreads();
#pragma unroll
        for (int mt = 0; mt < 2; mt++) {
            float s0 = sd[mt][0], s1 = sd[mt][1];
#pragma unroll
            for (int o = 1; o < 4; o <<= 1) {
                s0 += __shfl_xor_sync(0xFFFFFFFFu, s0, o);
                s1 += __shfl_xor_sync(0xFFFFFFFFu, s1, o);
            }
            if (tig == 0) {
                int lr0 = warpM * 32 + mt * 16 + gid;
                rb[lr0 * 4 + warpN]       = make_float2(s0, 0.f);
                rb[(lr0 + 8) * 4 + warpN] = make_float2(s1, 0.f);
            }
        }
        __syncthreads();
        if (warpN == 0 && tig == 0) {
#pragma unroll
            for (int mt = 0; mt < 2; mt++) {
                int lr0 = warpM * 32 + mt * 16 + gid;
#pragma unroll
                for (int h = 0; h < 2; h++) {
                    int lr = lr0 + h * 8;
                    int row = rowBase + lr;
                    if (row < Mrows) {
                        snode[row] = rb[lr * 4 + 0].x + rb[lr * 4 + 1].x
                                   + rb[lr * 4 + 2].x + rb[lr * 4 + 3].x;
                    }
                }
            }
        }
    }
}

// ======== hgnn edge GEMM ========
template <int FLAGS>
__global__ __launch_bounds__(512, 1)
void tgemm256(const float* __restrict__ A, const unsigned char* __restrict__ Wp,
              const float* __restrict__ av, float* __restrict__ C,
              float* __restrict__ snode, int Mrows)
{
    extern __shared__ __align__(128) unsigned char smem[];
    const uint32_t sb = smem_to_u32(smem);
    const int tid = threadIdx.x, lane = tid & 31, wid = tid >> 5;
    const int warpM = wid >> 2, warpN = wid & 3;
    const int rowBase = blockIdx.x * 128;

    int rA[2], cgA[2];
#pragma unroll
    for (int i = 0; i < 2; i++) {
        int g = tid + i * 512;
        rA[i] = g >> 3; cgA[i] = g & 7;
    }
    float4 pref[4];

    auto issueA = [&](int ch) {
#pragma unroll
        for (int i = 0; i < 2; i++) {
            int row = rowBase + rA[i];
            if (row < Mrows) {
                const float4* src = reinterpret_cast<const float4*>(
                    A + (size_t)row * DD + ch * 64 + cgA[i] * 8);
                pref[i * 2]     = src[0];
                pref[i * 2 + 1] = src[1];
            } else {
                pref[i * 2]     = make_float4(0.f, 0.f, 0.f, 0.f);
                pref[i * 2 + 1] = make_float4(0.f, 0.f, 0.f, 0.f);
            }
        }
    };
    auto storeA = [&](int s) {
#pragma unroll
        for (int i = 0; i < 2; i++) {
            float x[8];
            float4 v0 = pref[i * 2], v1 = pref[i * 2 + 1];
            x[0] = v0.x; x[1] = v0.y; x[2] = v0.z; x[3] = v0.w;
            x[4] = v1.x; x[5] = v1.y; x[6] = v1.z; x[7] = v1.w;
            unsigned short hi[8], lo[8];
#pragma unroll
            for (int j = 0; j < 8; j++) {
                __nv_bfloat16 h = __float2bfloat16(x[j]);
                __nv_bfloat16 l = __float2bfloat16(x[j] - __bfloat162float(h));
                hi[j] = *reinterpret_cast<unsigned short*>(&h);
                lo[j] = *reinterpret_cast<unsigned short*>(&l);
            }
            uint32_t off = s * 32768u + swz((uint32_t)rA[i], (uint32_t)cgA[i] * 16u);
            *reinterpret_cast<uint4*>(smem + off)         = *reinterpret_cast<uint4*>(hi);
            *reinterpret_cast<uint4*>(smem + 16384 + off) = *reinterpret_cast<uint4*>(lo);
        }
    };
    auto issueB = [&](int ch, int s) {
        const unsigned char* bh = Wp + (size_t)(ch * 2 + 0) * 32768;
        const unsigned char* bl = Wp + (size_t)(ch * 2 + 1) * 32768;
        uint32_t dh = sb + 65536u + (uint32_t)s * 65536u;
        uint32_t dl = dh + 32768u;
#pragma unroll
        for (int i = 0; i < 4; i++) {
            int idx = (tid + i * 512) * 16;
            CP_ASYNC16(dh + idx, bh + idx);
            CP_ASYNC16(dl + idx, bl + idx);
        }
        CP_COMMIT();
    };

    float c[2][8][4];
#pragma unroll
    for (int mt = 0; mt < 2; mt++)
#pragma unroll
        for (int nt = 0; nt < 8; nt++)
#pragma unroll
            for (int q = 0; q < 4; q++) c[mt][nt][q] = 0.f;

    issueA(0);
    issueB(0, 0);
    storeA(0);

    for (int ch = 0; ch < 4; ch++) {
        const int s = ch & 1;
        if (ch < 3) {
            issueA(ch + 1);
            issueB(ch + 1, s ^ 1);
            CP_WAIT(1);
        } else {
            CP_WAIT(0);
        }
        __syncthreads();

        const uint32_t aBase = sb + (uint32_t)s * 32768u;
        const uint32_t bBase = sb + 65536u + (uint32_t)s * 65536u;
#pragma unroll
        for (int ks = 0; ks < 4; ks++) {
            uint32_t ah[2][4], al[2][4];
#pragma unroll
            for (int mt = 0; mt < 2; mt++) {
                uint32_t row = (uint32_t)(warpM * 32 + mt * 16 + (lane & 7) + ((lane >> 3) & 1) * 8);
                uint32_t kb  = (uint32_t)(ks * 32 + ((lane >> 4) & 1) * 16);
                uint32_t addr = aBase + swz(row, kb);
                ldm_x4(addr,         ah[mt]);
                ldm_x4(addr + 16384, al[mt]);
            }
#pragma unroll
            for (int p = 0; p < 4; p++) {
                uint32_t nrow = (uint32_t)(warpN * 64 + p * 16 + (lane & 7) + ((lane >> 4) & 1) * 8);
                uint32_t kb   = (uint32_t)(ks * 32 + ((lane >> 3) & 1) * 16);
                uint32_t addr = bBase + swz(nrow, kb);
                uint32_t bh[4], bl[4];
                ldm_x4(addr,         bh);
                ldm_x4(addr + 32768, bl);
#pragma unroll
                for (int t = 0; t < 2; t++) {
#pragma unroll
                    for (int mt = 0; mt < 2; mt++) {
                        float* cc = c[mt][p * 2 + t];
                        mma_bf16(cc, ah[mt], bh + t * 2);
                        mma_bf16(cc, ah[mt], bl + t * 2);
                        mma_bf16(cc, al[mt], bh + t * 2);
                    }
                }
            }
        }
        if (ch < 3) storeA(s ^ 1);
        __syncthreads();
    }

    const int gid = lane >> 2, tig = lane & 3;
    float2* rb = reinterpret_cast<float2*>(smem);

#pragma unroll
    for (int mt = 0; mt < 2; mt++) {
        int r0 = rowBase + warpM * 32 + mt * 16 + gid;
        int r1 = r0 + 8;
        bool v0 = r0 < Mrows, v1 = r1 < Mrows;
#pragma unroll
        for (int nt = 0; nt < 8; nt++) {
            int col = warpN * 64 + nt * 8 + tig * 2;
            if (v0) *reinterpret_cast<float2*>(C + (size_t)r0 * DD + col)
                        = make_float2(c[mt][nt][0], c[mt][nt][1]);
            if (v1) *reinterpret_cast<float2*>(C + (size_t)r1 * DD + col)
                        = make_float2(c[mt][nt][2], c[mt][nt][3]);
        }
    }

    if (FLAGS & F_SNODE) {
#pragma unroll
        for (int mt = 0; mt < 2; mt++) {
            float s0 = 0.f, s1 = 0.f;
#pragma unroll
            for (int nt = 0; nt < 8; nt++) {
                int col = warpN * 64 + nt * 8 + tig * 2;
                float2 avv = *reinterpret_cast<const float2*>(av + col);
                s0 += c[mt][nt][0] * avv.x + c[mt][nt][1] * avv.y;
                s1 += c[mt][nt][2] * avv.x + c[mt][nt][3] * avv.y;
            }
#pragma unroll
            for (int o = 1; o < 4; o <<= 1) {
                s0 += __shfl_xor_sync(0xFFFFFFFFu, s0, o);
                s1 += __shfl_xor_sync(0xFFFFFFFFu, s1, o);
            }
            if (tig == 0) {
                int lr0 = warpM * 32 + mt * 16 + gid;
                rb[lr0 * 4 + warpN]       = make_float2(s0, 0.f);
                rb[(lr0 + 8) * 4 + warpN] = make_float2(s1, 0.f);
            }
        }
        __syncthreads();
        if (warpN == 0 && tig == 0) {
#pragma unroll
            for (int mt = 0; mt < 2; mt++) {
                int lr0 = warpM * 32 + mt * 16 + gid;
#pragma unroll
                for (int h = 0; h < 2; h++) {
                    int lr = lr0 + h * 8;
                    int row = rowBase + lr;
                    if (row < Mrows) {
                        snode[row] = rb[lr * 4 + 0].x + rb[lr * 4 + 1].x
                                   + rb[lr * 4 + 2].x + rb[lr * 4 + 3].x;
                    }
                }
            }
        }
    }
}

// ======== fused dual GEMM ========
__global__ __launch_bounds__(512, 1)
void tgemm_dual(const float* __restrict__ A, const unsigned char* __restrict__ Wp1,
                const float* __restrict__ bias1, const float* __restrict__ R1,
                const float* __restrict__ lng1, const float* __restrict__ lnb1,
                const unsigned char* __restrict__ Wp2, const float* __restrict__ bias2,
                const float* __restrict__ lng2, const float* __restrict__ lnb2,
                float* __restrict__ C2, const float* __restrict__ av,
                float* __restrict__ snode, int Mrows)
{
    extern __shared__ __align__(128) unsigned char smem[];
    const uint32_t sb = smem_to_u32(smem);
    const int tid = threadIdx.x, lane = tid & 31, wid = tid >> 5;
    const int warpM = wid >> 2, warpN = wid & 3;
    const int rowBase = blockIdx.x * 128;

    int rA[2], cgA[2];
#pragma unroll
    for (int i = 0; i < 2; i++) {
        int g = tid + i * 512;
        rA[i] = g >> 3; cgA[i] = g & 7;
    }
    float4 pref[4];

    auto issueA = [&](int ch) {
#pragma unroll
        for (int i = 0; i < 2; i++) {
            int row = rowBase + rA[i];
            if (row < Mrows) {
                const float4* src = reinterpret_cast<const float4*>(
                    A + (size_t)row * DD + ch * 64 + cgA[i] * 8);
                pref[i * 2]     = src[0];
                pref[i * 2 + 1] = src[1];
            } else {
                pref[i * 2]     = make_float4(0.f, 0.f, 0.f, 0.f);
                pref[i * 2 + 1] = make_float4(0.f, 0.f, 0.f, 0.f);
            }
        }
    };
    auto storeA = [&](int s) {
#pragma unroll
        for (int i = 0; i < 2; i++) {
            float x[8];
            float4 v0 = pref[i * 2], v1 = pref[i * 2 + 1];
            x[0] = v0.x; x[1] = v0.y; x[2] = v0.z; x[3] = v0.w;
            x[4] = v1.x; x[5] = v1.y; x[6] = v1.z; x[7] = v1.w;
            unsigned short hi[8], lo[8];
#pragma unroll
            for (int j = 0; j < 8; j++) {
                __nv_bfloat16 h = __float2bfloat16(x[j]);
                __nv_bfloat16 l = __float2bfloat16(x[j] - __bfloat162float(h));
                hi[j] = *reinterpret_cast<unsigned short*>(&h);
                lo[j] = *reinterpret_cast<unsigned short*>(&l);
            }
            uint32_t off = 131072u + s * 32768u + swz((uint32_t)rA[i], (uint32_t)cgA[i] * 16u);
            *reinterpret_cast<uint4*>(smem + off)         = *reinterpret_cast<uint4*>(hi);
            *reinterpret_cast<uint4*>(smem + 16384 + off) = *reinterpret_cast<uint4*>(lo);
        }
    };
    auto issueB1 = [&](int ch, int s) {
        const unsigned char* bh = Wp1 + (size_t)(ch * 2 + 0) * 32768;
        const unsigned char* bl = Wp1 + (size_t)(ch * 2 + 1) * 32768;
        uint32_t dh = sb + (uint32_t)s * 65536u;
        uint32_t dl = dh + 32768u;
#pragma unroll
        for (int i = 0; i < 4; i++) {
            int idx = (tid + i * 512) * 16;
            CP_ASYNC16(dh + idx, bh + idx);
            CP_ASYNC16(dl + idx, bl + idx);
        }
        CP_COMMIT();
    };
    auto issueB2 = [&](int ch) {
        const unsigned char* bh = Wp2 + (size_t)(ch * 2 + 0) * 32768;
        const unsigned char* bl = Wp2 + (size_t)(ch * 2 + 1) * 32768;
        uint32_t dh = sb + 131072u;
        uint32_t dl = dh + 32768u;
#pragma unroll
        for (int i = 0; i < 4; i++) {
            int idx = (tid + i * 512) * 16;
            CP_ASYNC16(dh + idx, bh + idx);
            CP_ASYNC16(dl + idx, bl + idx);
        }
        CP_COMMIT();
    };

    float c[2][8][4];
#pragma unroll
    for (int mt = 0; mt < 2; mt++)
#pragma unroll
        for (int nt = 0; nt < 8; nt++)
#pragma unroll
            for (int q = 0; q < 4; q++) c[mt][nt][q] = 0.f;

    // ---- phase 1 ----
    issueA(0);
    issueB1(0, 0);
    storeA(0);

    for (int ch = 0; ch < 4; ch++) {
        const int s = ch & 1;
        if (ch < 3) {
            issueA(ch + 1);
            issueB1(ch + 1, s ^ 1);
            CP_WAIT(1);
        } else {
            CP_WAIT(0);
        }
        __syncthreads();

        const uint32_t aBase = sb + 131072u + (uint32_t)s * 32768u;
        const uint32_t bBase = sb + (uint32_t)s * 65536u;
#pragma unroll
        for (int ks = 0; ks < 4; ks++) {
            uint32_t ah[2][4], al[2][4];
#pragma unroll
            for (int mt = 0; mt < 2; mt++) {
                uint32_t row = (uint32_t)(warpM * 32 + mt * 16 + (lane & 7) + ((lane >> 3) & 1) * 8);
                uint32_t kb  = (uint32_t)(ks * 32 + ((lane >> 4) & 1) * 16);
                uint32_t addr = aBase + swz(row, kb);
                ldm_x4(addr,         ah[mt]);
                ldm_x4(addr + 16384, al[mt]);
            }
#pragma unroll
            for (int p = 0; p < 4; p++) {
                uint32_t nrow = (uint32_t)(warpN * 64 + p * 16 + (lane & 7) + ((lane >> 4) & 1) * 8);
                uint32_t kb   = (uint32_t)(ks * 32 + ((lane >> 3) & 1) * 16);
                uint32_t addr = bBase + swz(nrow, kb);
                uint32_t bh[4], bl[4];
                ldm_x4(addr,         bh);
                ldm_x4(addr + 32768, bl);
#pragma unroll
                for (int t = 0; t < 2; t++) {
#pragma unroll
                    for (int mt = 0; mt < 2; mt++) {
                        float* cc = c[mt][p * 2 + t];
                        mma_bf16(cc, ah[mt], bh + t * 2);
                        mma_bf16(cc, ah[mt], bl + t * 2);
                        mma_bf16(cc, al[mt], bh + t * 2);
                    }
                }
            }
        }
        if (ch < 3) storeA(s ^ 1);
        __syncthreads();
    }

    // ---- epilogue 1 ----
    const int gid = lane >> 2, tig = lane & 3;
    float2* rb = reinterpret_cast<float2*>(smem + 131072);

#pragma unroll
    for (int mt = 0; mt < 2; mt++) {
        int r0 = rowBase + warpM * 32 + mt * 16 + gid;
        int r1 = r0 + 8;
        bool v0 = r0 < Mrows, v1 = r1 < Mrows;
#pragma unroll
        for (int nt = 0; nt < 8; nt++) {
            int col = warpN * 64 + nt * 8 + tig * 2;
            float2 bv = *reinterpret_cast<const float2*>(bias1 + col);
            float o0 = lrelu_f(c[mt][nt][0] + bv.x), o1 = lrelu_f(c[mt][nt][1] + bv.y);
            float o2 = lrelu_f(c[mt][nt][2] + bv.x), o3 = lrelu_f(c[mt][nt][3] + bv.y);
            if (v0) {
                float2 rv = *reinterpret_cast<const float2*>(R1 + (size_t)r0 * DD + col);
                o0 += rv.x; o1 += rv.y;
            }
            if (v1) {
                float2 rv = *reinterpret_cast<const float2*>(R1 + (size_t)r1 * DD + col);
                o2 += rv.x; o3 += rv.y;
            }
            c[mt][nt][0] = o0; c[mt][nt][1] = o1; c[mt][nt][2] = o2; c[mt][nt][3] = o3;
        }
    }
#pragma unroll
    for (int mt = 0; mt < 2; mt++) {
        float s0 = 0.f, q0 = 0.f, s1 = 0.f, q1 = 0.f;
#pragma unroll
        for (int nt = 0; nt < 8; nt++) {
            float o0 = c[mt][nt][0], o1 = c[mt][nt][1];
            float o2 = c[mt][nt][2], o3 = c[mt][nt][3];
            s0 += o0 + o1; q0 += o0 * o0 + o1 * o1;
            s1 += o2 + o3; q1 += o2 * o2 + o3 * o3;
        }
#pragma unroll
        for (int o = 1; o < 4; o <<= 1) {
            s0 += __shfl_xor_sync(0xFFFFFFFFu, s0, o);
            q0 += __shfl_xor_sync(0xFFFFFFFFu, q0, o);
            s1 += __shfl_xor_sync(0xFFFFFFFFu, s1, o);
            q1 += __shfl_xor_sync(0xFFFFFFFFu, q1, o);
        }
        if (tig == 0) {
            int lr0 = warpM * 32 + mt * 16 + gid;
            rb[lr0 * 4 + warpN]       = make_float2(s0, q0);
            rb[(lr0 + 8) * 4 + warpN] = make_float2(s1, q1);
        }
    }
    __syncthreads();
#pragma unroll
    for (int mt = 0; mt < 2; mt++) {
        int lr0 = warpM * 32 + mt * 16 + gid;
        int lr1 = lr0 + 8;
        float2 p00 = rb[lr0*4+0], p01 = rb[lr0*4+1], p02 = rb[lr0*4+2], p03 = rb[lr0*4+3];
        float2 p10 = rb[lr1*4+0], p11 = rb[lr1*4+1], p12 = rb[lr1*4+2], p13 = rb[lr1*4+3];
        float sum0 = p00.x + p01.x + p02.x + p03.x;
        float sq0  = p00.y + p01.y + p02.y + p03.y;
        float sum1 = p10.x + p11.x + p12.x + p13.x;
        float sq1  = p10.y + p11.y + p12.y + p13.y;
        float mean0 = sum0 * (1.f / 256.f);
        float rstd0 = rsqrtf(sq0 * (1.f / 256.f) - mean0 * mean0 + 1e-5f);
        float mean1 = sum1 * (1.f / 256.f);
        float rstd1 = rsqrtf(sq1 * (1.f / 256.f) - mean1 * mean1 + 1e-5f);
#pragma unroll
        for (int nt = 0; nt < 8; nt++) {
            int col = warpN * 64 + nt * 8 + tig * 2;
            float2 gv = *reinterpret_cast<const float2*>(lng1 + col);
            float2 bv = *reinterpret_cast<const float2*>(lnb1 + col);
            c[mt][nt][0] = (c[mt][nt][0] - mean0) * rstd0 * gv.x + bv.x;
            c[mt][nt][1] = (c[mt][nt][1] - mean0) * rstd0 * gv.y + bv.y;
            c[mt][nt][2] = (c[mt][nt][2] - mean1) * rstd1 * gv.x + bv.x;
            c[mt][nt][3] = (c[mt][nt][3] - mean1) * rstd1 * gv.y + bv.y;
        }
    }
    __syncthreads();

    // ---- store obj1 to A2 smem + issue B2 chunk 0 ----
    issueB2(0);
#pragma unroll
    for (int mt = 0; mt < 2; mt++) {
        uint32_t lr0 = (uint32_t)(warpM * 32 + mt * 16 + gid);
        uint32_t lr1 = lr0 + 8;
#pragma unroll
        for (int nt = 0; nt < 8; nt++) {
            uint32_t cb = (uint32_t)(warpN * 64 + nt * 8 + tig * 2) * 2u;
            float o0 = c[mt][nt][0], o1 = c[mt][nt][1];
            float o2 = c[mt][nt][2], o3 = c[mt][nt][3];
            __nv_bfloat16 h0 = __float2bfloat16(o0), h1 = __float2bfloat16(o1);
            __nv_bfloat16 h2 = __float2bfloat16(o2), h3 = __float2bfloat16(o3);
            __nv_bfloat16 l0 = __float2bfloat16(o0 - __bfloat162float(h0));
            __nv_bfloat16 l1 = __float2bfloat16(o1 - __bfloat162float(h1));
            __nv_bfloat16 l2 = __float2bfloat16(o2 - __bfloat162float(h2));
            __nv_bfloat16 l3 = __float2bfloat16(o3 - __bfloat162float(h3));
            uint32_t hp0 = ((uint32_t)*reinterpret_cast<unsigned short*>(&h1) << 16)
                         |  (uint32_t)*reinterpret_cast<unsigned short*>(&h0);
            uint32_t lp0 = ((uint32_t)*reinterpret_cast<unsigned short*>(&l1) << 16)
                         |  (uint32_t)*reinterpret_cast<unsigned short*>(&l0);
            uint32_t hp1 = ((uint32_t)*reinterpret_cast<unsigned short*>(&h3) << 16)
                         |  (uint32_t)*reinterpret_cast<unsigned short*>(&h2);
            uint32_t lp1 = ((uint32_t)*reinterpret_cast<unsigned short*>(&l3) << 16)
                         |  (uint32_t)*reinterpret_cast<unsigned short*>(&l2);
            *reinterpret_cast<uint32_t*>(smem + swz512(lr0, cb))           = hp0;
            *reinterpret_cast<uint32_t*>(smem + 65536u + swz512(lr0, cb))  = lp0;
            *reinterpret_cast<uint32_t*>(smem + swz512(lr1, cb))           = hp1;
            *reinterpret_cast<uint32_t*>(smem + 65536u + swz512(lr1, cb))  = lp1;
        }
    }
#pragma unroll
    for (int mt = 0; mt < 2; mt++)
#pragma unroll
        for (int nt = 0; nt < 8; nt++)
#pragma unroll
            for (int q = 0; q < 4; q++) c[mt][nt][q] = 0.f;
    __syncthreads();

    // ---- phase 2 ----
    for (int ch = 0; ch < 4; ch++) {
        CP_WAIT(0);
        __syncthreads();
        const uint32_t bBase = sb + 131072u;
#pragma unroll
        for (int ks = 0; ks < 4; ks++) {
            uint32_t ah[2][4], al[2][4];
#pragma unroll
            for (int mt = 0; mt < 2; mt++) {
                uint32_t row = (uint32_t)(warpM * 32 + mt * 16 + (lane & 7) + ((lane >> 3) & 1) * 8);
                uint32_t kb  = (uint32_t)(ch * 128 + ks * 32 + ((lane >> 4) & 1) * 16);
                uint32_t addr = sb + swz512(row, kb);
                ldm_x4(addr,          ah[mt]);
                ldm_x4(addr + 65536u, al[mt]);
            }
#pragma unroll
            for (int p = 0; p < 4; p++) {
                uint32_t nrow = (uint32_t)(warpN * 64 + p * 16 + (lane & 7) + ((lane >> 4) & 1) * 8);
                uint32_t kb   = (uint32_t)(ks * 32 + ((lane >> 3) & 1) * 16);
                uint32_t addr = bBase + swz(nrow, kb);
                uint32_t bh[4], bl[4];
                ldm_x4(addr,          bh);
                ldm_x4(addr + 32768u, bl);
#pragma unroll
                for (int t = 0; t < 2; t++) {
#pragma unroll
                    for (int mt = 0; mt < 2; mt++) {
                        float* cc = c[mt][p * 2 + t];
                        mma_bf16(cc, ah[mt], bh + t * 2);
                        mma_bf16(cc, ah[mt], bl + t * 2);
                        mma_bf16(cc, al[mt], bh + t * 2);
                    }
                }
            }
        }
        __syncthreads();
        if (ch < 3) issueB2(ch + 1);
    }

    // ---- epilogue 2 ----
#pragma unroll
    for (int mt = 0; mt < 2; mt++) {
        uint32_t lr0 = (uint32_t)(warpM * 32 + mt * 16 + gid);
        uint32_t lr1 = lr0 + 8;
#pragma unroll
        for (int nt = 0; nt < 8; nt++) {
            int col = warpN * 64 + nt * 8 + tig * 2;
            uint32_t cb = (uint32_t)col * 2u;
            float2 bv = *reinterpret_cast<const float2*>(bias2 + col);
            float o0 = lrelu_f(c[mt][nt][0] + bv.x), o1 = lrelu_f(c[mt][nt][1] + bv.y);
            float o2 = lrelu_f(c[mt][nt][2] + bv.x), o3 = lrelu_f(c[mt][nt][3] + bv.y);
            uint32_t hp0 = *reinterpret_cast<uint32_t*>(smem + swz512(lr0, cb));
            uint32_t lp0 = *reinterpret_cast<uint32_t*>(smem + 65536u + swz512(lr0, cb));
            uint32_t hp1 = *reinterpret_cast<uint32_t*>(smem + swz512(lr1, cb));
            uint32_t lp1 = *reinterpret_cast<uint32_t*>(smem + 65536u + swz512(lr1, cb));
            unsigned short u;
            u = (unsigned short)(hp0 & 0xFFFF);
            float r0a = __bfloat162float(*reinterpret_cast<__nv_bfloat16*>(&u));
            u = (unsigned short)(lp0 & 0xFFFF);
            r0a += __bfloat162float(*reinterpret_cast<__nv_bfloat16*>(&u));
            u = (unsigned short)(hp0 >> 16);
            float r0b = __bfloat162float(*reinterpret_cast<__nv_bfloat16*>(&u));
            u = (unsigned short)(lp0 >> 16);
            r0b += __bfloat162float(*reinterpret_cast<__nv_bfloat16*>(&u));
            u = (unsigned short)(hp1 & 0xFFFF);
            float r1a = __bfloat162float(*reinterpret_cast<__nv_bfloat16*>(&u));
            u = (unsigned short)(lp1 & 0xFFFF);
            r1a += __bfloat162float(*reinterpret_cast<__nv_bfloat16*>(&u));
            u = (unsigned short)(hp1 >> 16);
            float r1b = __bfloat162float(*reinterpret_cast<__nv_bfloat16*>(&u));
            u = (unsigned short)(lp1 >> 16);
            r1b += __bfloat162float(*reinterpret_cast<__nv_bfloat16*>(&u));
            c[mt][nt][0] = o0 + r0a; c[mt][nt][1] = o1 + r0b;
            c[mt][nt][2] = o2 + r1a; c[mt][nt][3] = o3 + r1b;
        }
    }
#pragma unroll
    for (int mt = 0; mt < 2; mt++) {
        float s0 = 0.f, q0 = 0.f, s1 = 0.f, q1 = 0.f;
#pragma unroll
        for (int nt = 0; nt < 8; nt++) {
            float o0 = c[mt][nt][0], o1 = c[mt][nt][1];
            float o2 = c[mt][nt][2], o3 = c[mt][nt][3];
            s0 += o0 + o1; q0 += o0 * o0 + o1 * o1;
            s1 += o2 + o3; q1 += o2 * o2 + o3 * o3;
        }
#pragma unroll
        for (int o = 1; o < 4; o <<= 1) {
            s0 += __shfl_xor_sync(0xFFFFFFFFu, s0, o);
            q0 += __shfl_xor_sync(0xFFFFFFFFu, q0, o);
            s1 += __shfl_xor_sync(0xFFFFFFFFu, s1, o);
            q1 += __shfl_xor_sync(0xFFFFFFFFu, q1, o);
        }
        if (tig == 0) {
            int lr0 = warpM * 32 + mt * 16 + gid;
            rb[lr0 * 4 + warpN]       = make_float2(s0, q0);
            rb[(lr0 + 8) * 4 + warpN] = make_float2(s1, q1);
        }
    }
    __syncthreads();
    float sd[2][2] = {{0.f, 0.f}, {0.f, 0.f}};
#pragma unroll
    for (int mt = 0; mt < 2; mt++) {
        int lr0 = warpM * 32 + mt * 16 + gid;
        int lr1 = lr0 + 8;
        float2 p00 = rb[lr0*4+0], p01 = rb[lr0*4+1], p02 = rb[lr0*4+2], p03 = rb[lr0*4+3];
        float2 p10 = rb[lr1*4+0], p11 = rb[lr1*4+1], p12 = rb[lr1*4+2], p13 = rb[lr1*4+3];
        float sum0 = p00.x + p01.x + p02.x + p03.x;
        float sq0  = p00.y + p01.y + p02.y + p03.y;
        float sum1 = p10.x + p11.x + p12.x + p13.x;
        float sq1  = p10.y + p11.y + p12.y + p13.y;
        float mean0 = sum0 * (1.f / 256.f);
        float rstd0 = rsqrtf(sq0 * (1.f / 256.f) - mean0 * mean0 + 1e-5f);
        float mean1 = sum1 * (1.f / 256.f);
        float rstd1 = rsqrtf(sq1 * (1.f / 256.f) - mean1 * mean1 + 1e-5f);
        int r0 = rowBase + lr0, r1 = rowBase + lr1;
        bool v0 = r0 < Mrows, v1 = r1 < Mrows;
#pragma unroll
        for (int nt = 0; nt < 8; nt++) {
            int col = warpN * 64 + nt * 8 + tig * 2;
            float2 gv = *reinterpret_cast<const float2*>(lng2 + col);
            float2 bv = *reinterpret_cast<const float2*>(lnb2 + col);
            float o0 = (c[mt][nt][0] - mean0) * rstd0 * gv.x + bv.x;
            float o1 = (c[mt][nt][1] - mean0) * rstd0 * gv.y + bv.y;
            float o2 = (c[mt][nt][2] - mean1) * rstd1 * gv.x + bv.x;
            float o3 = (c[mt][nt][3] - mean1) * rstd1 * gv.y + bv.y;
            if (v0) *reinterpret_cast<float2*>(C2 + (size_t)r0 * DD + col) = make_float2(o0, o1);
            if (v1) *reinterpret_cast<float2*>(C2 + (size_t)r1 * DD + col) = make_float2(o2, o3);
            float2 avv = *reinterpret_cast<const float2*>(av + col);
            sd[mt][0] += o0 * avv.x + o1 * avv.y;
            sd[mt][1] += o2 * avv.x + o3 * avv.y;
        }
    }
    __syncthreads();
#pragma unroll
    for (int mt = 0; mt < 2; mt++) {
        float s0 = sd[mt][0], s1 = sd[mt][1];
#pragma unroll
        for (int o = 1; o < 4; o <<= 1) {
            s0 += __shfl_xor_sync(0xFFFFFFFFu, s0, o);
            s1 += __shfl_xor_sync(0xFFFFFFFFu, s1, o);
        }
        if (tig == 0) {
            int lr0 = warpM * 32 + mt * 16 + gid;
            rb[lr0 * 4 + warpN]       = make_float2(s0, 0.f);
            rb[(lr0 + 8) * 4 + warpN] = make_float2(s1, 0.f);
        }
    }
    __syncthreads();
    if (warpN == 0 && tig == 0) {
#pragma unroll
        for (int mt = 0; mt < 2; mt++) {
            int lr0 = warpM * 32 + mt * 16 + gid;
#pragma unroll
            for (int h = 0; h < 2; h++) {
                int lr = lr0 + h * 8;
                int row = rowBase + lr;
                if (row < Mrows) {
                    snode[row] = rb[lr * 4 + 0].x + rb[lr * 4 + 1].x
                               + rb[lr * 4 + 2].x + rb[lr * 4 + 3].x;
                }
            }
        }
    }
}

// -------- edge gather (combined, layer-2 path) --------
__global__ void edge_gatherX(const float* __restrict__ X, const int* __restrict__ nodeE,
                             const int* __restrict__ offE, const int* __restrict__ cntE,
                             float* __restrict__ Xmean, int act, int nEdges)
{
    int ed = blockIdx.x * 8 + (threadIdx.x >> 5);
    if (ed >= nEdges) return;
    int lane = threadIdx.x & 31;
    int start = offE[ed], deg = cntE[ed];
    float4 a0 = make_float4(0.f,0.f,0.f,0.f), a1 = a0;
    for (int base = 0; base < deg; base += 32) {
        int m = min(32, deg - base);
        int src = 0;
        if (lane < m) src = nodeE[start + base + lane];
        for (int i = 0; i < m; i++) {
            int node = __shfl_sync(0xFFFFFFFFu, src, i);
            const float4* rp = reinterpret_cast<const float4*>(X + (size_t)node * DD + lane * 8);
            float4 v0 = rp[0], v1 = rp[1];
            if (act) {
                v0.x = lrelu_f(v0.x); v0.y = lrelu_f(v0.y); v0.z = lrelu_f(v0.z); v0.w = lrelu_f(v0.w);
                v1.x = lrelu_f(v1.x); v1.y = lrelu_f(v1.y); v1.z = lrelu_f(v1.z); v1.w = lrelu_f(v1.w);
            }
            a0.x += v0.x; a0.y += v0.y; a0.z += v0.z; a0.w += v0.w;
            a1.x += v1.x; a1.y += v1.y; a1.z += v1.z; a1.w += v1.w;
        }
    }
    float inv = 1.f / fmaxf((float)deg, 1.f);
    a0.x *= inv; a0.y *= inv; a0.z *= inv; a0.w *= inv;
    a1.x *= inv; a1.y *= inv; a1.z *= inv; a1.w *= inv;
    float4* op = reinterpret_cast<float4*>(Xmean + (size_t)ed * DD + lane * 8);
    op[0] = a0; op[1] = a1;
}

// -------- split edge gather (partitioned ranges; no wasted iterations) --------
// phase 0: entries [0, evCnt)  (ev nodes); phase 1: entries [evCnt, deg) + finalize.
__global__ void edge_gather_phase(const float* __restrict__ X, const int* __restrict__ nodeE,
                                  const int* __restrict__ offE, const int* __restrict__ cntE,
                                  const int* __restrict__ evCnt, float* __restrict__ Xm,
                                  int phase, int nEdges)
{
    int ed = blockIdx.x * 8 + (threadIdx.x >> 5);
    if (ed >= nEdges) return;
    int lane = threadIdx.x & 31;
    int deg = cntE[ed];
    int ec = evCnt[ed];
    int lo = (phase == 0) ? 0 : ec;
    int hi = (phase == 0) ? ec : deg;
    int start = offE[ed];
    float4 a0 = make_float4(0.f,0.f,0.f,0.f), a1 = a0;
    for (int base = lo; base < hi; base += 32) {
        int m = min(32, hi - base);
        int src = 0;
        if (lane < m) src = nodeE[start + base + lane];
        for (int i = 0; i < m; i++) {
            int node = __shfl_sync(0xFFFFFFFFu, src, i);
            const float4* rp = reinterpret_cast<const float4*>(X + (size_t)node * DD + lane * 8);
            float4 v0 = rp[0], v1 = rp[1];
            a0.x += v0.x; a0.y += v0.y; a0.z += v0.z; a0.w += v0.w;
            a1.x += v1.x; a1.y += v1.y; a1.z += v1.z; a1.w += v1.w;
        }
    }
    float4* op = reinterpret_cast<float4*>(Xm + (size_t)ed * DD + lane * 8);
    if (phase == 0) {
        op[0] = a0; op[1] = a1;
    } else {
        float4 p0 = op[0], p1 = op[1];
        float inv = 1.f / fmaxf((float)deg, 1.f);
        a0.x = (a0.x + p0.x) * inv; a0.y = (a0.y + p0.y) * inv;
        a0.z = (a0.z + p0.z) * inv; a0.w = (a0.w + p0.w) * inv;
        a1.x = (a1.x + p1.x) * inv; a1.y = (a1.y + p1.y) * inv;
        a1.z = (a1.z + p1.z) * inv; a1.w = (a1.w + p1.w) * inv;
        op[0] = a0; op[1] = a1;
    }
}

// -------- fused per-node softmax + aggregate --------
__global__ void node_attn_agg(const float* __restrict__ ef, const float* __restrict__ sn,
                              const float* __restrict__ se, const int* __restrict__ edN,
                              const int* __restrict__ permN, const int* __restrict__ offN,
                              const int* __restrict__ cntN, float* __restrict__ attn,
                              float* __restrict__ out, const float* __restrict__ av,
                              float* __restrict__ snodeOut, int doLrelu, int nNodes)
{
    int n = blockIdx.x * 8 + (threadIdx.x >> 5);
    if (n >= nNodes) return;
    int lane = threadIdx.x & 31;
    int st = offN[n], deg = cntN[n];
    float4 a0 = make_float4(0.f,0.f,0.f,0.f), a1 = a0;

    if (deg > 0) {
        float s0 = sn[n];
        if (deg <= 32) {
            int ed = 0;
            float sc = -3.4e38f;
            if (lane < deg) {
                ed = edN[st + lane];
                sc = lrelu_f(s0 + se[ed]);
            }
            float mx = sc;
#pragma unroll
            for (int o = 16; o; o >>= 1) mx = fmaxf(mx, __shfl_xor_sync(0xFFFFFFFFu, mx, o));
            float e = (lane < deg) ? expf(sc - mx) : 0.f;
            float z = e;
#pragma unroll
            for (int o = 16; o; o >>= 1) z += __shfl_xor_sync(0xFFFFFFFFu, z, o);
            float w = e / fmaxf(z, 1e-9f);
            if (lane < deg && attn != nullptr) attn[permN[st + lane]] = w;
            for (int i = 0; i < deg; i++) {
                int e_   = __shfl_sync(0xFFFFFFFFu, ed, i);
                float w_ = __shfl_sync(0xFFFFFFFFu, w, i);
                const float4* rp = reinterpret_cast<const float4*>(ef + (size_t)e_ * DD + lane * 8);
                float4 v0 = rp[0], v1 = rp[1];
                a0.x += w_*v0.x; a0.y += w_*v0.y; a0.z += w_*v0.z; a0.w += w_*v0.w;
                a1.x += w_*v1.x; a1.y += w_*v1.y; a1.z += w_*v1.z; a1.w += w_*v1.w;
            }
        } else {
            float mx = -3.4e38f;
            for (int base = 0; base < deg; base += 32) {
                float sc = -3.4e38f;
                if (base + lane < deg)
                    sc = lrelu_f(s0 + se[edN[st + base + lane]]);
                mx = fmaxf(mx, sc);
            }
#pragma unroll
            for (int o = 16; o; o >>= 1) mx = fmaxf(mx, __shfl_xor_sync(0xFFFFFFFFu, mx, o));
            float z = 0.f;
            for (int base = 0; base < deg; base += 32) {
                if (base + lane < deg)
                    z += expf(lrelu_f(s0 + se[edN[st + base + lane]]) - mx);
            }
#pragma unroll
            for (int o = 16; o; o >>= 1) z += __shfl_xor_sync(0xFFFFFFFFu, z, o);
            float invz = 1.f / fmaxf(z, 1e-9f);
            for (int base = 0; base < deg; base += 32) {
                int m = min(32, deg - base);
                int ed = 0; float w = 0.f;
                if (lane < m) {
                    ed = edN[st + base + lane];
                    w = expf(lrelu_f(s0 + se[ed]) - mx) * invz;
                    if (attn != nullptr) attn[permN[st + base + lane]] = w;
                }
                for (int i = 0; i < m; i++) {
                    int e_   = __shfl_sync(0xFFFFFFFFu, ed, i);
                    float w_ = __shfl_sync(0xFFFFFFFFu, w, i);
                    const float4* rp = reinterpret_cast<const float4*>(ef + (size_t)e_ * DD + lane * 8);
                    float4 v0 = rp[0], v1 = rp[1];
                    a0.x += w_*v0.x; a0.y += w_*v0.y; a0.z += w_*v0.z; a0.w += w_*v0.w;
                    a1.x += w_*v1.x; a1.y += w_*v1.y; a1.z += w_*v1.z; a1.w += w_*v1.w;
                }
            }
        }
    }
    if (snodeOut != nullptr) {
        const float4* ap = reinterpret_cast<const float4*>(av + lane * 8);
        float4 w0 = ap[0], w1 = ap[1];
        float d = lrelu_f(a0.x)*w0.x + lrelu_f(a0.y)*w0.y + lrelu_f(a0.z)*w0.z + lrelu_f(a0.w)*w0.w
                + lrelu_f(a1.x)*w1.x + lrelu_f(a1.y)*w1.y + lrelu_f(a1.z)*w1.z + lrelu_f(a1.w)*w1.w;
#pragma unroll
        for (int o = 16; o; o >>= 1) d += __shfl_xor_sync(0xFFFFFFFFu, d, o);
        if (lane == 0) snodeOut[n] = d;
    }
    if (doLrelu) {
        a0.x = lrelu_f(a0.x); a0.y = lrelu_f(a0.y); a0.z = lrelu_f(a0.z); a0.w = lrelu_f(a0.w);
        a1.x = lrelu_f(a1.x); a1.y = lrelu_f(a1.y); a1.z = lrelu_f(a1.z); a1.w = lrelu_f(a1.w);
    }
    float4* op = reinterpret_cast<float4*>(out + (size_t)n * DD + lane * 8);
    op[0] = a0; op[1] = a1;
}

// -------- object message gather --------
__global__ void obj_gather(const float* __restrict__ ev, const int* __restrict__ srcO,
                           const int* __restrict__ offO, const int* __restrict__ cntO,
                           float* __restrict__ msg, int nObj)
{
    int o = blockIdx.x * 8 + (threadIdx.x >> 5);
    if (o >= nObj) return;
    int lane = threadIdx.x & 31;
    int start = offO[o], deg = cntO[o];
    float4 a0 = make_float4(0.f,0.f,0.f,0.f), a1 = a0;
    for (int base = 0; base < deg; base += 32) {
        int m = min(32, deg - base);
        int src = 0;
        if (lane < m) src = srcO[start + base + lane];
        for (int i = 0; i < m; i++) {
            int row = __shfl_sync(0xFFFFFFFFu, src, i);
            const float4* rp = reinterpret_cast<const float4*>(ev + (size_t)row * DD + lane * 8);
            float4 v0 = rp[0], v1 = rp[1];
            a0.x += v0.x; a0.y += v0.y; a0.z += v0.z; a0.w += v0.w;
            a1.x += v1.x; a1.y += v1.y; a1.z += v1.z; a1.w += v1.w;
        }
    }
    float4* op = reinterpret_cast<float4*>(msg + (size_t)o * DD + lane * 8);
    op[0] = a0; op[1] = a1;
}

// ----------------- host orchestration -----------------
struct Ptrs {
    float *X, *obj, *msg, *Xm, *H, *ef, *snode, *sedge, *wav1, *wav2;
    unsigned char* wp;
    int *cntE, *offE, *nodeE, *cntN, *offN, *permN, *edN, *cntO, *offO, *srcO, *cur;
};

static void get_ptrs(Ptrs& p) {
    cudaGetSymbolAddress((void**)&p.X,     g_X);
    cudaGetSymbolAddress((void**)&p.obj,   g_obj);
    cudaGetSymbolAddress((void**)&p.msg,   g_msg);
    cudaGetSymbolAddress((void**)&p.Xm,    g_Xm);
    cudaGetSymbolAddress((void**)&p.H,     g_H);
    cudaGetSymbolAddress((void**)&p.ef,    g_ef);
    cudaGetSymbolAddress((void**)&p.snode, g_snode);
    cudaGetSymbolAddress((void**)&p.sedge, g_sedge);
    cudaGetSymbolAddress((void**)&p.wav1,  g_wav1);
    cudaGetSymbolAddress((void**)&p.wav2,  g_wav2);
    cudaGetSymbolAddress((void**)&p.wp,    g_Wprep);
    cudaGetSymbolAddress((void**)&p.cntE,  g_cntE);
    cudaGetSymbolAddress((void**)&p.offE,  g_offE);
    cudaGetSymbolAddress((void**)&p.nodeE, g_nodeE);
    cudaGetSymbolAddress((void**)&p.cntN,  g_cntN);
    cudaGetSymbolAddress((void**)&p.offN,  g_offN);
    cudaGetSymbolAddress((void**)&p.permN, g_permN);
    cudaGetSymbolAddress((void**)&p.edN,   g_edN);
    cudaGetSymbolAddress((void**)&p.cntO,  g_cntO);
    cudaGetSymbolAddress((void**)&p.offO,  g_offO);
    cudaGetSymbolAddress((void**)&p.srcO,  g_srcO);
    cudaGetSymbolAddress((void**)&p.cur,   g_cur);
}

extern "C" void kernel_launch(void* const* d_in, const int* in_sizes, int n_in,
                              void* d_out, int out_size)
{
    const float* object_X = (const float*)d_in[0];
    const float* event_X  = (const float*)d_in[1];
    const float* Wo = (const float*)d_in[2];  const float* bo  = (const float*)d_in[3];
    const float* go = (const float*)d_in[4];  const float* bon = (const float*)d_in[5];
    const float* We = (const float*)d_in[6];  const float* be  = (const float*)d_in[7];
    const float* ge = (const float*)d_in[8];  const float* ben = (const float*)d_in[9];
    const float* Wu = (const float*)d_in[10]; const float* bu  = (const float*)d_in[11];
    const float* Wl = (const float*)d_in[12]; const float* bl  = (const float*)d_in[13];
    const float* g1 = (const float*)d_in[14]; const float* b1  = (const float*)d_in[15];
    const float* g2 = (const float*)d_in[16]; const float* b2  = (const float*)d_in[17];
    const float* Wh1 = (const float*)d_in[18]; const float* ah1 = (const float*)d_in[19];
    const float* Wh2 = (const float*)d_in[20]; const float* ah2 = (const float*)d_in[21];
    const int* oe_ev   = (const int*)d_in[22];
    const int* oe_obj  = (const int*)d_in[23];
    const int* hg_node = (const int*)d_in[24];
    const int* hg_edge = (const int*)d_in[25];

    Ptrs p; get_ptrs(p);

    static cudaStream_t s2 = nullptr;
    static cudaEvent_t evFork = nullptr, evJoin = nullptr, evEv = nullptr,
                       evMsg = nullptr, evPass = nullptr;
    if (s2 == nullptr) {
        cudaStreamCreateWithFlags(&s2, cudaStreamNonBlocking);
        cudaEventCreateWithFlags(&evFork, cudaEventDisableTiming);
        cudaEventCreateWithFlags(&evJoin, cudaEventDisableTiming);
        cudaEventCreateWithFlags(&evEv,   cudaEventDisableTiming);
        cudaEventCreateWithFlags(&evMsg,  cudaEventDisableTiming);
        cudaEventCreateWithFlags(&evPass, cudaEventDisableTiming);
    }

    // ---- fork: CSR build on side stream ----
    cudaEventRecord(evFork, 0);
    cudaStreamWaitEvent(s2, evFork, 0);
    zero_misc<<<(2 * (NE + NN + NO) + NE + 255) / 256, 256, 0, s2>>>();
    count_all<<<(2 * E2N + E1N + 255) / 256, 256, 0, s2>>>(hg_edge, hg_node, oe_obj);
    scan_all<<<NBT, 1024, 0, s2>>>();
    scan_small3<<<1, 32, 0, s2>>>();
    add_off_all<<<(NE + NN + NO + 255) / 256, 256, 0, s2>>>();
    fill_all<<<(2 * E2N + E1N + 255) / 256, 256, 0, s2>>>(hg_edge, hg_node, oe_obj, oe_ev);
    cudaEventRecord(evJoin, s2);

    // ---- main stream: weight prep, then ev-projection ----
    prep_w<<<dim3(32, 6), 256>>>(We, Wo, Wu, Wl, Wh1, Wh2);
    prep_wav<<<(DD + 7) / 8, 256>>>(Wh1, ah1, p.wav1);
    prep_wav<<<(DD + 7) / 8, 256>>>(Wh2, ah2, p.wav2);

    const unsigned char *wpe = p.wp, *wpo = p.wp + 262144, *wpu = p.wp + 2 * 262144,
                        *wpl = p.wp + 3 * 262144, *wph1 = p.wp + 4 * 262144,
                        *wph2 = p.wp + 5 * 262144;

    cudaFuncSetAttribute(proj_gemm, cudaFuncAttributeMaxDynamicSharedMemorySize, SMEM_SZ);
    int nbEv = (NE + 127) / 128, nbObj = (NO + 127) / 128;
    // ev rows (-> X[0:NE), snode fused)
    proj_gemm<<<nbEv, 512, SMEM_SZ>>>(
        event_X, wpe, be, ge, ben, p.X, p.wav1, p.snode, NE, nbEv,
        event_X, wpe, be, ge, ben, p.X, NE);
    cudaEventRecord(evEv, 0);

    // obj rows (-> g_obj), runs while side stream gathers from ev rows
    proj_gemm<<<nbObj, 512, SMEM_SZ>>>(
        object_X, wpo, bo, go, bon, p.obj, nullptr, nullptr, NO, 0,
        object_X, wpo, bo, go, bon, p.obj, NO);

    // ---- side stream: after ev rows + CSR: obj message gather, then phase-0 edge gather ----
    cudaStreamWaitEvent(s2, evEv, 0);
    obj_gather<<<(NO + 7) / 8, 256, 0, s2>>>(p.X, p.srcO, p.offO, p.cntO, p.msg, NO);
    cudaEventRecord(evMsg, s2);
    edge_gather_phase<<<(NE + 7) / 8, 256, 0, s2>>>(p.X, p.nodeE, p.offE, p.cntE,
                                                    p.cur, p.Xm, 0, NE);
    cudaEventRecord(evPass, s2);

    // ---- main: dual GEMM (needs msg from side + obj from main) ----
    cudaStreamWaitEvent(0, evMsg, 0);
    cudaFuncSetAttribute(tgemm_dual, cudaFuncAttributeMaxDynamicSharedMemorySize, SMEM_SZ);
    tgemm_dual<<<(NO + 127) / 128, 512, SMEM_SZ>>>(p.msg, wpu, bu, p.obj, g1, b1,
                                                   wpl, bl, g2, b2,
                                                   p.X + (size_t)NE * DD,
                                                   p.wav1, p.snode + NE, NO);

    // ---- layer 1: phase-1 gather (obj contributions only) + edge GEMM + node agg ----
    cudaStreamWaitEvent(0, evPass, 0);
    edge_gather_phase<<<(NE + 7) / 8, 256>>>(p.X, p.nodeE, p.offE, p.cntE,
                                             p.cur, p.Xm, 1, NE);
    cudaFuncSetAttribute(tgemm256<F_SNODE>, cudaFuncAttributeMaxDynamicSharedMemorySize, SMEM_SZ);
    tgemm256<F_SNODE><<<(NE + 127) / 128, 512, SMEM_SZ>>>(p.Xm, wph1, ah1 + DD, p.ef, p.sedge, NE);
    node_attn_agg<<<(NN + 7) / 8, 256>>>(p.ef, p.snode, p.sedge, p.edN,
                                         p.permN, p.offN, p.cntN,
                                         nullptr, p.H, p.wav2, p.snode, 0, NN);

    // ---- layer 2 ----
    float* out = (float*)d_out;
    edge_gatherX<<<(NE + 7) / 8, 256>>>(p.H, p.nodeE, p.offE, p.cntE, p.Xm, 1, NE);
    tgemm256<F_SNODE><<<(NE + 127) / 128, 512, SMEM_SZ>>>(p.Xm, wph2, ah2 + DD, p.ef, p.sedge, NE);
    node_attn_agg<<<(NN + 7) / 8, 256>>>(p.ef, p.snode, p.sedge, p.edN,
                                         p.permN, p.offN, p.cntN,
                                         out + (size_t)NN * DD, out, nullptr, nullptr, 1, NN);
}

// round 15
// speedup vs baseline: 1.0189x; 1.0189x over previous
#include <cuda_runtime.h>
#include <cuda_bf16.h>
#include <cstdint>

#define DD 256
static const int NE  = 50000;
static const int NO  = 100000;
static const int NN  = 150000;
static const int E1N = 400000;
static const int E2N = 800000;

// -------- device scratch --------
__device__ float    g_X  [(size_t)NN * DD];
__device__ float    g_obj[(size_t)NO * DD];
__device__ float    g_msg[(size_t)NO * DD];   // also Xmean[NE*DD] in hgnn layers
__device__ float    g_H  [(size_t)NN * DD];
__device__ float    g_ef [(size_t)NE * DD];
__device__ float    g_snode[NN];
__device__ float    g_sedge[NE];
__device__ float    g_wav1[DD];
__device__ float    g_wav2[DD];
__device__ unsigned char g_Wprep[6 * 4 * 2 * 256 * 128];
// CSR structures (value-direct)
__device__ int g_cntE[NE],  g_offE[NE],  g_nodeE[E2N];
__device__ int g_cntN[NN],  g_offN[NN],  g_permN[E2N], g_edN[E2N];
__device__ int g_cntO[NO],  g_offO[NO],  g_srcO[E1N];
__device__ int g_cur[NE + NN + NO];
__device__ int g_bsum[512];

static const int NBE = (NE + 1023) / 1024;
static const int NBN = (NN + 1023) / 1024;
static const int NBO = (NO + 1023) / 1024;
static const int NBT = NBE + NBN + NBO;

// -------- helpers --------
__device__ __forceinline__ float lrelu_f(float x) { return x >= 0.f ? x : 0.2f * x; }

__device__ __forceinline__ uint32_t smem_to_u32(const void* p) {
    uint32_t a;
    asm("{ .reg .u64 t; cvta.to.shared.u64 t, %1; cvt.u32.u64 %0, t; }" : "=r"(a) : "l"(p));
    return a;
}
__device__ __forceinline__ void ldm_x4(uint32_t addr, uint32_t* r) {
    asm volatile("ldmatrix.sync.aligned.m8n8.x4.shared.b16 {%0,%1,%2,%3}, [%4];"
                 : "=r"(r[0]), "=r"(r[1]), "=r"(r[2]), "=r"(r[3]) : "r"(addr));
}
__device__ __forceinline__ void mma_bf16(float* c, const uint32_t* a, const uint32_t* b) {
    asm volatile("mma.sync.aligned.m16n8k16.row.col.f32.bf16.bf16.f32 "
                 "{%0,%1,%2,%3}, {%4,%5,%6,%7}, {%8,%9}, {%0,%1,%2,%3};"
                 : "+f"(c[0]), "+f"(c[1]), "+f"(c[2]), "+f"(c[3])
                 : "r"(a[0]), "r"(a[1]), "r"(a[2]), "r"(a[3]), "r"(b[0]), "r"(b[1]));
}
__device__ __forceinline__ uint32_t swz(uint32_t row, uint32_t cb) {
    return row * 128u + (cb ^ ((row & 7u) << 4));
}
__device__ __forceinline__ uint32_t swz512(uint32_t row, uint32_t cb) {
    return row * 512u + (cb ^ ((row & 7u) << 4));
}
#define CP_ASYNC16(dst, src) \
    asm volatile("cp.async.cg.shared.global [%0], [%1], 16;" :: "r"(dst), "l"(src) : "memory")
#define CP_COMMIT() asm volatile("cp.async.commit_group;" ::: "memory")
#define CP_WAIT(n)  asm volatile("cp.async.wait_group %0;" :: "n"(n) : "memory")

enum { F_SNODE = 16 };

// ======== condensed CSR build ========
__global__ void zero_misc()
{
    int g = blockIdx.x * blockDim.x + threadIdx.x;
    if (g < NE) g_cntE[g] = 0;
    else if (g < NE + NN) g_cntN[g - NE] = 0;
    else if (g < NE + NN + NO) g_cntO[g - NE - NN] = 0;
    int h = g - (NE + NN + NO);
    if (h >= 0 && h < NE + NN + NO) g_cur[h] = 0;
}
__global__ void count_all(const int* __restrict__ he, const int* __restrict__ hn,
                          const int* __restrict__ oo)
{
    int t = blockIdx.x * blockDim.x + threadIdx.x;
    if (t < E2N) atomicAdd(&g_cntE[he[t]], 1);
    else if (t < 2 * E2N) atomicAdd(&g_cntN[hn[t - E2N]], 1);
    else if (t < 2 * E2N + E1N) atomicAdd(&g_cntO[oo[t - 2 * E2N]], 1);
}
__global__ void scan_all()
{
    __shared__ int sh[1024];
    int b = blockIdx.x;
    const int* cnt; int* off; int nseg; int lb;
    if (b < NBE)            { cnt = g_cntE; off = g_offE; nseg = NE; lb = b; }
    else if (b < NBE + NBN) { cnt = g_cntN; off = g_offN; nseg = NN; lb = b - NBE; }
    else                    { cnt = g_cntO; off = g_offO; nseg = NO; lb = b - NBE - NBN; }
    int g = lb * 1024 + threadIdx.x;
    int v = (g < nseg) ? cnt[g] : 0;
    sh[threadIdx.x] = v;
    __syncthreads();
#pragma unroll
    for (int o = 1; o < 1024; o <<= 1) {
        int t = (threadIdx.x >= o) ? sh[threadIdx.x - o] : 0;
        __syncthreads();
        sh[threadIdx.x] += t;
        __syncthreads();
    }
    if (g < nseg) off[g] = sh[threadIdx.x] - v;
    if (threadIdx.x == 1023) g_bsum[b] = sh[1023];
}
__global__ void scan_small3()
{
    int t = threadIdx.x;
    int s, e;
    if (t == 0)      { s = 0;          e = NBE; }
    else if (t == 1) { s = NBE;        e = NBE + NBN; }
    else if (t == 2) { s = NBE + NBN;  e = NBT; }
    else return;
    int run = 0;
    for (int i = s; i < e; i++) { int v = g_bsum[i]; g_bsum[i] = run; run += v; }
}
__global__ void add_off_all()
{
    int g = blockIdx.x * blockDim.x + threadIdx.x;
    if (g < NE) g_offE[g] += g_bsum[g >> 10];
    else if (g < NE + NN) {
        int l = g - NE; g_offN[l] += g_bsum[NBE + (l >> 10)];
    } else if (g < NE + NN + NO) {
        int l = g - NE - NN; g_offO[l] += g_bsum[NBE + NBN + (l >> 10)];
    }
}
__global__ void fill_all(const int* __restrict__ he, const int* __restrict__ hn,
                         const int* __restrict__ oo, const int* __restrict__ oev)
{
    int t = blockIdx.x * blockDim.x + threadIdx.x;
    if (t < E2N) {
        int s = he[t];
        int pos = g_offE[s] + atomicAdd(&g_cur[s], 1);
        g_nodeE[pos] = hn[t];
    } else if (t < 2 * E2N) {
        int e = t - E2N;
        int s = hn[e];
        int pos = g_offN[s] + atomicAdd(&g_cur[NE + s], 1);
        g_permN[pos] = e;
        g_edN[pos]   = he[e];
    } else if (t < 2 * E2N + E1N) {
        int e = t - 2 * E2N;
        int s = oo[e];
        int pos = g_offO[s] + atomicAdd(&g_cur[NE + NN + s], 1);
        g_srcO[pos] = oev[e];
    }
}

// -------- weight prep --------
__global__ void prep_w(const float* W0, const float* W1, const float* W2,
                       const float* W3, const float* W4, const float* W5)
{
    const float* Ws[6] = {W0, W1, W2, W3, W4, W5};
    const float* W = Ws[blockIdx.y];
    unsigned char* base = g_Wprep + (size_t)blockIdx.y * 262144;
    int g = blockIdx.x * 256 + threadIdx.x;
    int n = g >> 5, kg = g & 31, k0 = kg * 8;
    unsigned short hi[8], lo[8];
#pragma unroll
    for (int i = 0; i < 8; i++) {
        float x = W[(size_t)(k0 + i) * DD + n];
        __nv_bfloat16 h = __float2bfloat16(x);
        __nv_bfloat16 l = __float2bfloat16(x - __bfloat162float(h));
        hi[i] = *reinterpret_cast<unsigned short*>(&h);
        lo[i] = *reinterpret_cast<unsigned short*>(&l);
    }
    int chunk = k0 >> 6, kc = k0 & 63;
    uint32_t off = (uint32_t)n * 128u + (((uint32_t)kc * 2u) ^ (((uint32_t)n & 7u) << 4));
    *reinterpret_cast<uint4*>(base + (size_t)(chunk * 2 + 0) * 32768 + off) =
        *reinterpret_cast<uint4*>(hi);
    *reinterpret_cast<uint4*>(base + (size_t)(chunk * 2 + 1) * 32768 + off) =
        *reinterpret_cast<uint4*>(lo);
}

// merged: gridDim.y = 2 -> (Wh1,ah1)->wav1 and (Wh2,ah2)->wav2 in one launch
__global__ void prep_wav2(const float* __restrict__ W1, const float* __restrict__ a1,
                          const float* __restrict__ W2, const float* __restrict__ a2,
                          float* __restrict__ w1, float* __restrict__ w2)
{
    const float* W = (blockIdx.y == 0) ? W1 : W2;
    const float* a = (blockIdx.y == 0) ? a1 : a2;
    float* w = (blockIdx.y == 0) ? w1 : w2;
    int k = blockIdx.x * 8 + (threadIdx.x >> 5);
    if (k >= DD) return;
    int lane = threadIdx.x & 31;
    const float4* rp = reinterpret_cast<const float4*>(W + (size_t)k * DD);
    const float4* ap = reinterpret_cast<const float4*>(a);
    float4 v0 = rp[lane], v1 = rp[lane + 32];
    float4 a0 = ap[lane], a1v = ap[lane + 32];
    float d = v0.x*a0.x + v0.y*a0.y + v0.z*a0.z + v0.w*a0.w
            + v1.x*a1v.x + v1.y*a1v.y + v1.z*a1v.z + v1.w*a1v.w;
#pragma unroll
    for (int o = 16; o; o >>= 1) d += __shfl_xor_sync(0xFFFFFFFFu, d, o);
    if (lane == 0) w[k] = d;
}

static const int SMEM_SZ = 196608;

// ======== combined projection GEMM ========
__global__ __launch_bounds__(512, 1)
void proj_gemm(const float* __restrict__ A0, const unsigned char* __restrict__ Wp0,
               const float* __restrict__ bias0, const float* __restrict__ lng0,
               const float* __restrict__ lnb0, float* __restrict__ C0,
               const float* __restrict__ av0, float* __restrict__ snode0, int M0, int nb0,
               const float* __restrict__ A1, const unsigned char* __restrict__ Wp1,
               const float* __restrict__ bias1, const float* __restrict__ lng1,
               const float* __restrict__ lnb1, float* __restrict__ C1, int M1)
{
    extern __shared__ __align__(128) unsigned char smem[];
    const uint32_t sb = smem_to_u32(smem);
    const int tid = threadIdx.x, lane = tid & 31, wid = tid >> 5;
    const int warpM = wid >> 2, warpN = wid & 3;

    const float* A; const unsigned char* Wp; const float* bias;
    const float* lng; const float* lnb; float* C;
    const float* av; float* snode; int Mrows, rowBase;
    if ((int)blockIdx.x < nb0) {
        A = A0; Wp = Wp0; bias = bias0; lng = lng0; lnb = lnb0; C = C0;
        av = av0; snode = snode0; Mrows = M0; rowBase = blockIdx.x * 128;
    } else {
        A = A1; Wp = Wp1; bias = bias1; lng = lng1; lnb = lnb1; C = C1;
        av = nullptr; snode = nullptr; Mrows = M1; rowBase = (blockIdx.x - nb0) * 128;
    }

    int rA[2], cgA[2];
#pragma unroll
    for (int i = 0; i < 2; i++) {
        int g = tid + i * 512;
        rA[i] = g >> 3; cgA[i] = g & 7;
    }
    float4 pref[4];

    auto issueA = [&](int ch) {
#pragma unroll
        for (int i = 0; i < 2; i++) {
            int row = rowBase + rA[i];
            if (row < Mrows) {
                const float4* src = reinterpret_cast<const float4*>(
                    A + (size_t)row * DD + ch * 64 + cgA[i] * 8);
                pref[i * 2]     = src[0];
                pref[i * 2 + 1] = src[1];
            } else {
                pref[i * 2]     = make_float4(0.f, 0.f, 0.f, 0.f);
                pref[i * 2 + 1] = make_float4(0.f, 0.f, 0.f, 0.f);
            }
        }
    };
    auto storeA = [&](int s) {
#pragma unroll
        for (int i = 0; i < 2; i++) {
            float x[8];
            float4 v0 = pref[i * 2], v1 = pref[i * 2 + 1];
            x[0] = v0.x; x[1] = v0.y; x[2] = v0.z; x[3] = v0.w;
            x[4] = v1.x; x[5] = v1.y; x[6] = v1.z; x[7] = v1.w;
            unsigned short hi[8], lo[8];
#pragma unroll
            for (int j = 0; j < 8; j++) {
                __nv_bfloat16 h = __float2bfloat16(x[j]);
                __nv_bfloat16 l = __float2bfloat16(x[j] - __bfloat162float(h));
                hi[j] = *reinterpret_cast<unsigned short*>(&h);
                lo[j] = *reinterpret_cast<unsigned short*>(&l);
            }
            uint32_t off = s * 32768u + swz((uint32_t)rA[i], (uint32_t)cgA[i] * 16u);
            *reinterpret_cast<uint4*>(smem + off)         = *reinterpret_cast<uint4*>(hi);
            *reinterpret_cast<uint4*>(smem + 16384 + off) = *reinterpret_cast<uint4*>(lo);
        }
    };
    auto issueB = [&](int ch, int s) {
        const unsigned char* bh = Wp + (size_t)(ch * 2 + 0) * 32768;
        const unsigned char* bl = Wp + (size_t)(ch * 2 + 1) * 32768;
        uint32_t dh = sb + 65536u + (uint32_t)s * 65536u;
        uint32_t dl = dh + 32768u;
#pragma unroll
        for (int i = 0; i < 4; i++) {
            int idx = (tid + i * 512) * 16;
            CP_ASYNC16(dh + idx, bh + idx);
            CP_ASYNC16(dl + idx, bl + idx);
        }
        CP_COMMIT();
    };

    float c[2][8][4];
#pragma unroll
    for (int mt = 0; mt < 2; mt++)
#pragma unroll
        for (int nt = 0; nt < 8; nt++)
#pragma unroll
            for (int q = 0; q < 4; q++) c[mt][nt][q] = 0.f;

    issueA(0);
    issueB(0, 0);
    storeA(0);

    for (int ch = 0; ch < 4; ch++) {
        const int s = ch & 1;
        if (ch < 3) {
            issueA(ch + 1);
            issueB(ch + 1, s ^ 1);
            CP_WAIT(1);
        } else {
            CP_WAIT(0);
        }
        __syncthreads();

        const uint32_t aBase = sb + (uint32_t)s * 32768u;
        const uint32_t bBase = sb + 65536u + (uint32_t)s * 65536u;
#pragma unroll
        for (int ks = 0; ks < 4; ks++) {
            uint32_t ah[2][4], al[2][4];
#pragma unroll
            for (int mt = 0; mt < 2; mt++) {
                uint32_t row = (uint32_t)(warpM * 32 + mt * 16 + (lane & 7) + ((lane >> 3) & 1) * 8);
                uint32_t kb  = (uint32_t)(ks * 32 + ((lane >> 4) & 1) * 16);
                uint32_t addr = aBase + swz(row, kb);
                ldm_x4(addr,         ah[mt]);
                ldm_x4(addr + 16384, al[mt]);
            }
#pragma unroll
            for (int p = 0; p < 4; p++) {
                uint32_t nrow = (uint32_t)(warpN * 64 + p * 16 + (lane & 7) + ((lane >> 4) & 1) * 8);
                uint32_t kb   = (uint32_t)(ks * 32 + ((lane >> 3) & 1) * 16);
                uint32_t addr = bBase + swz(nrow, kb);
                uint32_t bh[4], bl[4];
                ldm_x4(addr,         bh);
                ldm_x4(addr + 32768, bl);
#pragma unroll
                for (int t = 0; t < 2; t++) {
#pragma unroll
                    for (int mt = 0; mt < 2; mt++) {
                        float* cc = c[mt][p * 2 + t];
                        mma_bf16(cc, ah[mt], bh + t * 2);
                        mma_bf16(cc, ah[mt], bl + t * 2);
                        mma_bf16(cc, al[mt], bh + t * 2);
                    }
                }
            }
        }
        if (ch < 3) storeA(s ^ 1);
        __syncthreads();
    }

    const int gid = lane >> 2, tig = lane & 3;
    float2* rb = reinterpret_cast<float2*>(smem);

#pragma unroll
    for (int mt = 0; mt < 2; mt++)
#pragma unroll
        for (int nt = 0; nt < 8; nt++) {
            int col = warpN * 64 + nt * 8 + tig * 2;
            float2 bv = *reinterpret_cast<const float2*>(bias + col);
            c[mt][nt][0] = lrelu_f(c[mt][nt][0] + bv.x);
            c[mt][nt][1] = lrelu_f(c[mt][nt][1] + bv.y);
            c[mt][nt][2] = lrelu_f(c[mt][nt][2] + bv.x);
            c[mt][nt][3] = lrelu_f(c[mt][nt][3] + bv.y);
        }

#pragma unroll
    for (int mt = 0; mt < 2; mt++) {
        float s0 = 0.f, q0 = 0.f, s1 = 0.f, q1 = 0.f;
#pragma unroll
        for (int nt = 0; nt < 8; nt++) {
            float o0 = c[mt][nt][0], o1 = c[mt][nt][1];
            float o2 = c[mt][nt][2], o3 = c[mt][nt][3];
            s0 += o0 + o1; q0 += o0 * o0 + o1 * o1;
            s1 += o2 + o3; q1 += o2 * o2 + o3 * o3;
        }
#pragma unroll
        for (int o = 1; o < 4; o <<= 1) {
            s0 += __shfl_xor_sync(0xFFFFFFFFu, s0, o);
            q0 += __shfl_xor_sync(0xFFFFFFFFu, q0, o);
            s1 += __shfl_xor_sync(0xFFFFFFFFu, s1, o);
            q1 += __shfl_xor_sync(0xFFFFFFFFu, q1, o);
        }
        if (tig == 0) {
            int lr0 = warpM * 32 + mt * 16 + gid;
            rb[lr0 * 4 + warpN]       = make_float2(s0, q0);
            rb[(lr0 + 8) * 4 + warpN] = make_float2(s1, q1);
        }
    }
    __syncthreads();

    float sd[2][2] = {{0.f, 0.f}, {0.f, 0.f}};
#pragma unroll
    for (int mt = 0; mt < 2; mt++) {
        int lr0 = warpM * 32 + mt * 16 + gid;
        int lr1 = lr0 + 8;
        float2 p00 = rb[lr0*4+0], p01 = rb[lr0*4+1], p02 = rb[lr0*4+2], p03 = rb[lr0*4+3];
        float2 p10 = rb[lr1*4+0], p11 = rb[lr1*4+1], p12 = rb[lr1*4+2], p13 = rb[lr1*4+3];
        float sum0 = p00.x + p01.x + p02.x + p03.x;
        float sq0  = p00.y + p01.y + p02.y + p03.y;
        float sum1 = p10.x + p11.x + p12.x + p13.x;
        float sq1  = p10.y + p11.y + p12.y + p13.y;
        float mean0 = sum0 * (1.f / 256.f);
        float rstd0 = rsqrtf(sq0 * (1.f / 256.f) - mean0 * mean0 + 1e-5f);
        float mean1 = sum1 * (1.f / 256.f);
        float rstd1 = rsqrtf(sq1 * (1.f / 256.f) - mean1 * mean1 + 1e-5f);
        int r0 = rowBase + lr0, r1 = rowBase + lr1;
        bool v0 = r0 < Mrows, v1 = r1 < Mrows;
#pragma unroll
        for (int nt = 0; nt < 8; nt++) {
            int col = warpN * 64 + nt * 8 + tig * 2;
            float2 gv = *reinterpret_cast<const float2*>(lng + col);
            float2 bv = *reinterpret_cast<const float2*>(lnb + col);
            float o0 = (c[mt][nt][0] - mean0) * rstd0 * gv.x + bv.x;
            float o1 = (c[mt][nt][1] - mean0) * rstd0 * gv.y + bv.y;
            float o2 = (c[mt][nt][2] - mean1) * rstd1 * gv.x + bv.x;
            float o3 = (c[mt][nt][3] - mean1) * rstd1 * gv.y + bv.y;
            if (v0) *reinterpret_cast<float2*>(C + (size_t)r0 * DD + col) = make_float2(o0, o1);
            if (v1) *reinterpret_cast<float2*>(C + (size_t)r1 * DD + col) = make_float2(o2, o3);
            if (snode != nullptr) {
                float2 avv = *reinterpret_cast<const float2*>(av + col);
                sd[mt][0] += o0 * avv.x + o1 * avv.y;
                sd[mt][1] += o2 * avv.x + o3 * avv.y;
            }
        }
    }

    if (snode != nullptr) {
        __syncthreads();
#pragma unroll
        for (int mt = 0; mt < 2; mt++) {
            float s0 = sd[mt][0], s1 = sd[mt][1];
#pragma unroll
            for (int o = 1; o < 4; o <<= 1) {
                s0 += __shfl_xor_sync(0xFFFFFFFFu, s0, o);
                s1 += __shfl_xor_sync(0xFFFFFFFFu, s1, o);
            }
            if (tig == 0) {
                int lr0 = warpM * 32 + mt * 16 + gid;
                rb[lr0 * 4 + warpN]       = make_float2(s0, 0.f);
                rb[(lr0 + 8) * 4 + warpN] = make_float2(s1, 0.f);
            }
        }
        __syncthreads();
        if (warpN == 0 && tig == 0) {
#pragma unroll
            for (int mt = 0; mt < 2; mt++) {
                int lr0 = warpM * 32 + mt * 16 + gid;
#pragma unroll
                for (int h = 0; h < 2; h++) {
                    int lr = lr0 + h * 8;
                    int row = rowBase + lr;
                    if (row < Mrows) {
                        snode[row] = rb[lr * 4 + 0].x + rb[lr * 4 + 1].x
                                   + rb[lr * 4 + 2].x + rb[lr * 4 + 3].x;
                    }
                }
            }
        }
    }
}

// ======== hgnn edge GEMM ========
template <int FLAGS>
__global__ __launch_bounds__(512, 1)
void tgemm256(const float* __restrict__ A, const unsigned char* __restrict__ Wp,
              const float* __restrict__ av, float* __restrict__ C,
              float* __restrict__ snode, int Mrows)
{
    extern __shared__ __align__(128) unsigned char smem[];
    const uint32_t sb = smem_to_u32(smem);
    const int tid = threadIdx.x, lane = tid & 31, wid = tid >> 5;
    const int warpM = wid >> 2, warpN = wid & 3;
    const int rowBase = blockIdx.x * 128;

    int rA[2], cgA[2];
#pragma unroll
    for (int i = 0; i < 2; i++) {
        int g = tid + i * 512;
        rA[i] = g >> 3; cgA[i] = g & 7;
    }
    float4 pref[4];

    auto issueA = [&](int ch) {
#pragma unroll
        for (int i = 0; i < 2; i++) {
            int row = rowBase + rA[i];
            if (row < Mrows) {
                const float4* src = reinterpret_cast<const float4*>(
                    A + (size_t)row * DD + ch * 64 + cgA[i] * 8);
                pref[i * 2]     = src[0];
                pref[i * 2 + 1] = src[1];
            } else {
                pref[i * 2]     = make_float4(0.f, 0.f, 0.f, 0.f);
                pref[i * 2 + 1] = make_float4(0.f, 0.f, 0.f, 0.f);
            }
        }
    };
    auto storeA = [&](int s) {
#pragma unroll
        for (int i = 0; i < 2; i++) {
            float x[8];
            float4 v0 = pref[i * 2], v1 = pref[i * 2 + 1];
            x[0] = v0.x; x[1] = v0.y; x[2] = v0.z; x[3] = v0.w;
            x[4] = v1.x; x[5] = v1.y; x[6] = v1.z; x[7] = v1.w;
            unsigned short hi[8], lo[8];
#pragma unroll
            for (int j = 0; j < 8; j++) {
                __nv_bfloat16 h = __float2bfloat16(x[j]);
                __nv_bfloat16 l = __float2bfloat16(x[j] - __bfloat162float(h));
                hi[j] = *reinterpret_cast<unsigned short*>(&h);
                lo[j] = *reinterpret_cast<unsigned short*>(&l);
            }
            uint32_t off = s * 32768u + swz((uint32_t)rA[i], (uint32_t)cgA[i] * 16u);
            *reinterpret_cast<uint4*>(smem + off)         = *reinterpret_cast<uint4*>(hi);
            *reinterpret_cast<uint4*>(smem + 16384 + off) = *reinterpret_cast<uint4*>(lo);
        }
    };
    auto issueB = [&](int ch, int s) {
        const unsigned char* bh = Wp + (size_t)(ch * 2 + 0) * 32768;
        const unsigned char* bl = Wp + (size_t)(ch * 2 + 1) * 32768;
        uint32_t dh = sb + 65536u + (uint32_t)s * 65536u;
        uint32_t dl = dh + 32768u;
#pragma unroll
        for (int i = 0; i < 4; i++) {
            int idx = (tid + i * 512) * 16;
            CP_ASYNC16(dh + idx, bh + idx);
            CP_ASYNC16(dl + idx, bl + idx);
        }
        CP_COMMIT();
    };

    float c[2][8][4];
#pragma unroll
    for (int mt = 0; mt < 2; mt++)
#pragma unroll
        for (int nt = 0; nt < 8; nt++)
#pragma unroll
            for (int q = 0; q < 4; q++) c[mt][nt][q] = 0.f;

    issueA(0);
    issueB(0, 0);
    storeA(0);

    for (int ch = 0; ch < 4; ch++) {
        const int s = ch & 1;
        if (ch < 3) {
            issueA(ch + 1);
            issueB(ch + 1, s ^ 1);
            CP_WAIT(1);
        } else {
            CP_WAIT(0);
        }
        __syncthreads();

        const uint32_t aBase = sb + (uint32_t)s * 32768u;
        const uint32_t bBase = sb + 65536u + (uint32_t)s * 65536u;
#pragma unroll
        for (int ks = 0; ks < 4; ks++) {
            uint32_t ah[2][4], al[2][4];
#pragma unroll
            for (int mt = 0; mt < 2; mt++) {
                uint32_t row = (uint32_t)(warpM * 32 + mt * 16 + (lane & 7) + ((lane >> 3) & 1) * 8);
                uint32_t kb  = (uint32_t)(ks * 32 + ((lane >> 4) & 1) * 16);
                uint32_t addr = aBase + swz(row, kb);
                ldm_x4(addr,         ah[mt]);
                ldm_x4(addr + 16384, al[mt]);
            }
#pragma unroll
            for (int p = 0; p < 4; p++) {
                uint32_t nrow = (uint32_t)(warpN * 64 + p * 16 + (lane & 7) + ((lane >> 4) & 1) * 8);
                uint32_t kb   = (uint32_t)(ks * 32 + ((lane >> 3) & 1) * 16);
                uint32_t addr = bBase + swz(nrow, kb);
                uint32_t bh[4], bl[4];
                ldm_x4(addr,         bh);
                ldm_x4(addr + 32768, bl);
#pragma unroll
                for (int t = 0; t < 2; t++) {
#pragma unroll
                    for (int mt = 0; mt < 2; mt++) {
                        float* cc = c[mt][p * 2 + t];
                        mma_bf16(cc, ah[mt], bh + t * 2);
                        mma_bf16(cc, ah[mt], bl + t * 2);
                        mma_bf16(cc, al[mt], bh + t * 2);
                    }
                }
            }
        }
        if (ch < 3) storeA(s ^ 1);
        __syncthreads();
    }

    const int gid = lane >> 2, tig = lane & 3;
    float2* rb = reinterpret_cast<float2*>(smem);

#pragma unroll
    for (int mt = 0; mt < 2; mt++) {
        int r0 = rowBase + warpM * 32 + mt * 16 + gid;
        int r1 = r0 + 8;
        bool v0 = r0 < Mrows, v1 = r1 < Mrows;
#pragma unroll
        for (int nt = 0; nt < 8; nt++) {
            int col = warpN * 64 + nt * 8 + tig * 2;
            if (v0) *reinterpret_cast<float2*>(C + (size_t)r0 * DD + col)
                        = make_float2(c[mt][nt][0], c[mt][nt][1]);
            if (v1) *reinterpret_cast<float2*>(C + (size_t)r1 * DD + col)
                        = make_float2(c[mt][nt][2], c[mt][nt][3]);
        }
    }

    if (FLAGS & F_SNODE) {
#pragma unroll
        for (int mt = 0; mt < 2; mt++) {
            float s0 = 0.f, s1 = 0.f;
#pragma unroll
            for (int nt = 0; nt < 8; nt++) {
                int col = warpN * 64 + nt * 8 + tig * 2;
                float2 avv = *reinterpret_cast<const float2*>(av + col);
                s0 += c[mt][nt][0] * avv.x + c[mt][nt][1] * avv.y;
                s1 += c[mt][nt][2] * avv.x + c[mt][nt][3] * avv.y;
            }
#pragma unroll
            for (int o = 1; o < 4; o <<= 1) {
                s0 += __shfl_xor_sync(0xFFFFFFFFu, s0, o);
                s1 += __shfl_xor_sync(0xFFFFFFFFu, s1, o);
            }
            if (tig == 0) {
                int lr0 = warpM * 32 + mt * 16 + gid;
                rb[lr0 * 4 + warpN]       = make_float2(s0, 0.f);
                rb[(lr0 + 8) * 4 + warpN] = make_float2(s1, 0.f);
            }
        }
        __syncthreads();
        if (warpN == 0 && tig == 0) {
#pragma unroll
            for (int mt = 0; mt < 2; mt++) {
                int lr0 = warpM * 32 + mt * 16 + gid;
#pragma unroll
                for (int h = 0; h < 2; h++) {
                    int lr = lr0 + h * 8;
                    int row = rowBase + lr;
                    if (row < Mrows) {
                        snode[row] = rb[lr * 4 + 0].x + rb[lr * 4 + 1].x
                                   + rb[lr * 4 + 2].x + rb[lr * 4 + 3].x;
                    }
                }
            }
        }
    }
}

// ======== fused dual GEMM ========
__global__ __launch_bounds__(512, 1)
void tgemm_dual(const float* __restrict__ A, const unsigned char* __restrict__ Wp1,
                const float* __restrict__ bias1, const float* __restrict__ R1,
                const float* __restrict__ lng1, const float* __restrict__ lnb1,
                const unsigned char* __restrict__ Wp2, const float* __restrict__ bias2,
                const float* __restrict__ lng2, const float* __restrict__ lnb2,
                float* __restrict__ C2, const float* __restrict__ av,
                float* __restrict__ snode, int Mrows)
{
    extern __shared__ __align__(128) unsigned char smem[];
    const uint32_t sb = smem_to_u32(smem);
    const int tid = threadIdx.x, lane = tid & 31, wid = tid >> 5;
    const int warpM = wid >> 2, warpN = wid & 3;
    const int rowBase = blockIdx.x * 128;

    int rA[2], cgA[2];
#pragma unroll
    for (int i = 0; i < 2; i++) {
        int g = tid + i * 512;
        rA[i] = g >> 3; cgA[i] = g & 7;
    }
    float4 pref[4];

    auto issueA = [&](int ch) {
#pragma unroll
        for (int i = 0; i < 2; i++) {
            int row = rowBase + rA[i];
            if (row < Mrows) {
                const float4* src = reinterpret_cast<const float4*>(
                    A + (size_t)row * DD + ch * 64 + cgA[i] * 8);
                pref[i * 2]     = src[0];
                pref[i * 2 + 1] = src[1];
            } else {
                pref[i * 2]     = make_float4(0.f, 0.f, 0.f, 0.f);
                pref[i * 2 + 1] = make_float4(0.f, 0.f, 0.f, 0.f);
            }
        }
    };
    auto storeA = [&](int s) {
#pragma unroll
        for (int i = 0; i < 2; i++) {
            float x[8];
            float4 v0 = pref[i * 2], v1 = pref[i * 2 + 1];
            x[0] = v0.x; x[1] = v0.y; x[2] = v0.z; x[3] = v0.w;
            x[4] = v1.x; x[5] = v1.y; x[6] = v1.z; x[7] = v1.w;
            unsigned short hi[8], lo[8];
#pragma unroll
            for (int j = 0; j < 8; j++) {
                __nv_bfloat16 h = __float2bfloat16(x[j]);
                __nv_bfloat16 l = __float2bfloat16(x[j] - __bfloat162float(h));
                hi[j] = *reinterpret_cast<unsigned short*>(&h);
                lo[j] = *reinterpret_cast<unsigned short*>(&l);
            }
            uint32_t off = 131072u + s * 32768u + swz((uint32_t)rA[i], (uint32_t)cgA[i] * 16u);
            *reinterpret_cast<uint4*>(smem + off)         = *reinterpret_cast<uint4*>(hi);
            *reinterpret_cast<uint4*>(smem + 16384 + off) = *reinterpret_cast<uint4*>(lo);
        }
    };
    auto issueB1 = [&](int ch, int s) {
        const unsigned char* bh = Wp1 + (size_t)(ch * 2 + 0) * 32768;
        const unsigned char* bl = Wp1 + (size_t)(ch * 2 + 1) * 32768;
        uint32_t dh = sb + (uint32_t)s * 65536u;
        uint32_t dl = dh + 32768u;
#pragma unroll
        for (int i = 0; i < 4; i++) {
            int idx = (tid + i * 512) * 16;
            CP_ASYNC16(dh + idx, bh + idx);
            CP_ASYNC16(dl + idx, bl + idx);
        }
        CP_COMMIT();
    };
    auto issueB2 = [&](int ch) {
        const unsigned char* bh = Wp2 + (size_t)(ch * 2 + 0) * 32768;
        const unsigned char* bl = Wp2 + (size_t)(ch * 2 + 1) * 32768;
        uint32_t dh = sb + 131072u;
        uint32_t dl = dh + 32768u;
#pragma unroll
        for (int i = 0; i < 4; i++) {
            int idx = (tid + i * 512) * 16;
            CP_ASYNC16(dh + idx, bh + idx);
            CP_ASYNC16(dl + idx, bl + idx);
        }
        CP_COMMIT();
    };

    float c[2][8][4];
#pragma unroll
    for (int mt = 0; mt < 2; mt++)
#pragma unroll
        for (int nt = 0; nt < 8; nt++)
#pragma unroll
            for (int q = 0; q < 4; q++) c[mt][nt][q] = 0.f;

    // ---- phase 1 ----
    issueA(0);
    issueB1(0, 0);
    storeA(0);

    for (int ch = 0; ch < 4; ch++) {
        const int s = ch & 1;
        if (ch < 3) {
            issueA(ch + 1);
            issueB1(ch + 1, s ^ 1);
            CP_WAIT(1);
        } else {
            CP_WAIT(0);
        }
        __syncthreads();

        const uint32_t aBase = sb + 131072u + (uint32_t)s * 32768u;
        const uint32_t bBase = sb + (uint32_t)s * 65536u;
#pragma unroll
        for (int ks = 0; ks < 4; ks++) {
            uint32_t ah[2][4], al[2][4];
#pragma unroll
            for (int mt = 0; mt < 2; mt++) {
                uint32_t row = (uint32_t)(warpM * 32 + mt * 16 + (lane & 7) + ((lane >> 3) & 1) * 8);
                uint32_t kb  = (uint32_t)(ks * 32 + ((lane >> 4) & 1) * 16);
                uint32_t addr = aBase + swz(row, kb);
                ldm_x4(addr,         ah[mt]);
                ldm_x4(addr + 16384, al[mt]);
            }
#pragma unroll
            for (int p = 0; p < 4; p++) {
                uint32_t nrow = (uint32_t)(warpN * 64 + p * 16 + (lane & 7) + ((lane >> 4) & 1) * 8);
                uint32_t kb   = (uint32_t)(ks * 32 + ((lane >> 3) & 1) * 16);
                uint32_t addr = bBase + swz(nrow, kb);
                uint32_t bh[4], bl[4];
                ldm_x4(addr,         bh);
                ldm_x4(addr + 32768, bl);
#pragma unroll
                for (int t = 0; t < 2; t++) {
#pragma unroll
                    for (int mt = 0; mt < 2; mt++) {
                        float* cc = c[mt][p * 2 + t];
                        mma_bf16(cc, ah[mt], bh + t * 2);
                        mma_bf16(cc, ah[mt], bl + t * 2);
                        mma_bf16(cc, al[mt], bh + t * 2);
                    }
                }
            }
        }
        if (ch < 3) storeA(s ^ 1);
        __syncthreads();
    }

    // ---- epilogue 1 ----
    const int gid = lane >> 2, tig = lane & 3;
    float2* rb = reinterpret_cast<float2*>(smem + 131072);

#pragma unroll
    for (int mt = 0; mt < 2; mt++) {
        int r0 = rowBase + warpM * 32 + mt * 16 + gid;
        int r1 = r0 + 8;
        bool v0 = r0 < Mrows, v1 = r1 < Mrows;
#pragma unroll
        for (int nt = 0; nt < 8; nt++) {
            int col = warpN * 64 + nt * 8 + tig * 2;
            float2 bv = *reinterpret_cast<const float2*>(bias1 + col);
            float o0 = lrelu_f(c[mt][nt][0] + bv.x), o1 = lrelu_f(c[mt][nt][1] + bv.y);
            float o2 = lrelu_f(c[mt][nt][2] + bv.x), o3 = lrelu_f(c[mt][nt][3] + bv.y);
            if (v0) {
                float2 rv = *reinterpret_cast<const float2*>(R1 + (size_t)r0 * DD + col);
                o0 += rv.x; o1 += rv.y;
            }
            if (v1) {
                float2 rv = *reinterpret_cast<const float2*>(R1 + (size_t)r1 * DD + col);
                o2 += rv.x; o3 += rv.y;
            }
            c[mt][nt][0] = o0; c[mt][nt][1] = o1; c[mt][nt][2] = o2; c[mt][nt][3] = o3;
        }
    }
#pragma unroll
    for (int mt = 0; mt < 2; mt++) {
        float s0 = 0.f, q0 = 0.f, s1 = 0.f, q1 = 0.f;
#pragma unroll
        for (int nt = 0; nt < 8; nt++) {
            float o0 = c[mt][nt][0], o1 = c[mt][nt][1];
            float o2 = c[mt][nt][2], o3 = c[mt][nt][3];
            s0 += o0 + o1; q0 += o0 * o0 + o1 * o1;
            s1 += o2 + o3; q1 += o2 * o2 + o3 * o3;
        }
#pragma unroll
        for (int o = 1; o < 4; o <<= 1) {
            s0 += __shfl_xor_sync(0xFFFFFFFFu, s0, o);
            q0 += __shfl_xor_sync(0xFFFFFFFFu, q0, o);
            s1 += __shfl_xor_sync(0xFFFFFFFFu, s1, o);
            q1 += __shfl_xor_sync(0xFFFFFFFFu, q1, o);
        }
        if (tig == 0) {
            int lr0 = warpM * 32 + mt * 16 + gid;
            rb[lr0 * 4 + warpN]       = make_float2(s0, q0);
            rb[(lr0 + 8) * 4 + warpN] = make_float2(s1, q1);
        }
    }
    __syncthreads();
#pragma unroll
    for (int mt = 0; mt < 2; mt++) {
        int lr0 = warpM * 32 + mt * 16 + gid;
        int lr1 = lr0 + 8;
        float2 p00 = rb[lr0*4+0], p01 = rb[lr0*4+1], p02 = rb[lr0*4+2], p03 = rb[lr0*4+3];
        float2 p10 = rb[lr1*4+0], p11 = rb[lr1*4+1], p12 = rb[lr1*4+2], p13 = rb[lr1*4+3];
        float sum0 = p00.x + p01.x + p02.x + p03.x;
        float sq0  = p00.y + p01.y + p02.y + p03.y;
        float sum1 = p10.x + p11.x + p12.x + p13.x;
        float sq1  = p10.y + p11.y + p12.y + p13.y;
        float mean0 = sum0 * (1.f / 256.f);
        float rstd0 = rsqrtf(sq0 * (1.f / 256.f) - mean0 * mean0 + 1e-5f);
        float mean1 = sum1 * (1.f / 256.f);
        float rstd1 = rsqrtf(sq1 * (1.f / 256.f) - mean1 * mean1 + 1e-5f);
#pragma unroll
        for (int nt = 0; nt < 8; nt++) {
            int col = warpN * 64 + nt * 8 + tig * 2;
            float2 gv = *reinterpret_cast<const float2*>(lng1 + col);
            float2 bv = *reinterpret_cast<const float2*>(lnb1 + col);
            c[mt][nt][0] = (c[mt][nt][0] - mean0) * rstd0 * gv.x + bv.x;
            c[mt][nt][1] = (c[mt][nt][1] - mean0) * rstd0 * gv.y + bv.y;
            c[mt][nt][2] = (c[mt][nt][2] - mean1) * rstd1 * gv.x + bv.x;
            c[mt][nt][3] = (c[mt][nt][3] - mean1) * rstd1 * gv.y + bv.y;
        }
    }
    __syncthreads();

    // ---- store obj1 to A2 smem + issue B2 chunk 0 ----
    issueB2(0);
#pragma unroll
    for (int mt = 0; mt < 2; mt++) {
        uint32_t lr0 = (uint32_t)(warpM * 32 + mt * 16 + gid);
        uint32_t lr1 = lr0 + 8;
#pragma unroll
        for (int nt = 0; nt < 8; nt++) {
            uint32_t cb = (uint32_t)(warpN * 64 + nt * 8 + tig * 2) * 2u;
            float o0 = c[mt][nt][0], o1 = c[mt][nt][1];
            float o2 = c[mt][nt][2], o3 = c[mt][nt][3];
            __nv_bfloat16 h0 = __float2bfloat16(o0), h1 = __float2bfloat16(o1);
            __nv_bfloat16 h2 = __float2bfloat16(o2), h3 = __float2bfloat16(o3);
            __nv_bfloat16 l0 = __float2bfloat16(o0 - __bfloat162float(h0));
            __nv_bfloat16 l1 = __float2bfloat16(o1 - __bfloat162float(h1));
            __nv_bfloat16 l2 = __float2bfloat16(o2 - __bfloat162float(h2));
            __nv_bfloat16 l3 = __float2bfloat16(o3 - __bfloat162float(h3));
            uint32_t hp0 = ((uint32_t)*reinterpret_cast<unsigned short*>(&h1) << 16)
                         |  (uint32_t)*reinterpret_cast<unsigned short*>(&h0);
            uint32_t lp0 = ((uint32_t)*reinterpret_cast<unsigned short*>(&l1) << 16)
                         |  (uint32_t)*reinterpret_cast<unsigned short*>(&l0);
            uint32_t hp1 = ((uint32_t)*reinterpret_cast<unsigned short*>(&h3) << 16)
                         |  (uint32_t)*reinterpret_cast<unsigned short*>(&h2);
            uint32_t lp1 = ((uint32_t)*reinterpret_cast<unsigned short*>(&l3) << 16)
                         |  (uint32_t)*reinterpret_cast<unsigned short*>(&l2);
            *reinterpret_cast<uint32_t*>(smem + swz512(lr0, cb))           = hp0;
            *reinterpret_cast<uint32_t*>(smem + 65536u + swz512(lr0, cb))  = lp0;
            *reinterpret_cast<uint32_t*>(smem + swz512(lr1, cb))           = hp1;
            *reinterpret_cast<uint32_t*>(smem + 65536u + swz512(lr1, cb))  = lp1;
        }
    }
#pragma unroll
    for (int mt = 0; mt < 2; mt++)
#pragma unroll
        for (int nt = 0; nt < 8; nt++)
#pragma unroll
            for (int q = 0; q < 4; q++) c[mt][nt][q] = 0.f;
    __syncthreads();

    // ---- phase 2 ----
    for (int ch = 0; ch < 4; ch++) {
        CP_WAIT(0);
        __syncthreads();
        const uint32_t bBase = sb + 131072u;
#pragma unroll
        for (int ks = 0; ks < 4; ks++) {
            uint32_t ah[2][4], al[2][4];
#pragma unroll
            for (int mt = 0; mt < 2; mt++) {
                uint32_t row = (uint32_t)(warpM * 32 + mt * 16 + (lane & 7) + ((lane >> 3) & 1) * 8);
                uint32_t kb  = (uint32_t)(ch * 128 + ks * 32 + ((lane >> 4) & 1) * 16);
                uint32_t addr = sb + swz512(row, kb);
                ldm_x4(addr,          ah[mt]);
                ldm_x4(addr + 65536u, al[mt]);
            }
#pragma unroll
            for (int p = 0; p < 4; p++) {
                uint32_t nrow = (uint32_t)(warpN * 64 + p * 16 + (lane & 7) + ((lane >> 4) & 1) * 8);
                uint32_t kb   = (uint32_t)(ks * 32 + ((lane >> 3) & 1) * 16);
                uint32_t addr = bBase + swz(nrow, kb);
                uint32_t bh[4], bl[4];
                ldm_x4(addr,          bh);
                ldm_x4(addr + 32768u, bl);
#pragma unroll
                for (int t = 0; t < 2; t++) {
#pragma unroll
                    for (int mt = 0; mt < 2; mt++) {
                        float* cc = c[mt][p * 2 + t];
                        mma_bf16(cc, ah[mt], bh + t * 2);
                        mma_bf16(cc, ah[mt], bl + t * 2);
                        mma_bf16(cc, al[mt], bh + t * 2);
                    }
                }
            }
        }
        __syncthreads();
        if (ch < 3) issueB2(ch + 1);
    }

    // ---- epilogue 2 ----
#pragma unroll
    for (int mt = 0; mt < 2; mt++) {
        uint32_t lr0 = (uint32_t)(warpM * 32 + mt * 16 + gid);
        uint32_t lr1 = lr0 + 8;
#pragma unroll
        for (int nt = 0; nt < 8; nt++) {
            int col = warpN * 64 + nt * 8 + tig * 2;
            uint32_t cb = (uint32_t)col * 2u;
            float2 bv = *reinterpret_cast<const float2*>(bias2 + col);
            float o0 = lrelu_f(c[mt][nt][0] + bv.x), o1 = lrelu_f(c[mt][nt][1] + bv.y);
            float o2 = lrelu_f(c[mt][nt][2] + bv.x), o3 = lrelu_f(c[mt][nt][3] + bv.y);
            uint32_t hp0 = *reinterpret_cast<uint32_t*>(smem + swz512(lr0, cb));
            uint32_t lp0 = *reinterpret_cast<uint32_t*>(smem + 65536u + swz512(lr0, cb));
            uint32_t hp1 = *reinterpret_cast<uint32_t*>(smem + swz512(lr1, cb));
            uint32_t lp1 = *reinterpret_cast<uint32_t*>(smem + 65536u + swz512(lr1, cb));
            unsigned short u;
            u = (unsigned short)(hp0 & 0xFFFF);
            float r0a = __bfloat162float(*reinterpret_cast<__nv_bfloat16*>(&u));
            u = (unsigned short)(lp0 & 0xFFFF);
            r0a += __bfloat162float(*reinterpret_cast<__nv_bfloat16*>(&u));
            u = (unsigned short)(hp0 >> 16);
            float r0b = __bfloat162float(*reinterpret_cast<__nv_bfloat16*>(&u));
            u = (unsigned short)(lp0 >> 16);
            r0b += __bfloat162float(*reinterpret_cast<__nv_bfloat16*>(&u));
            u = (unsigned short)(hp1 & 0xFFFF);
            float r1a = __bfloat162float(*reinterpret_cast<__nv_bfloat16*>(&u));
            u = (unsigned short)(lp1 & 0xFFFF);
            r1a += __bfloat162float(*reinterpret_cast<__nv_bfloat16*>(&u));
            u = (unsigned short)(hp1 >> 16);
            float r1b = __bfloat162float(*reinterpret_cast<__nv_bfloat16*>(&u));
            u = (unsigned short)(lp1 >> 16);
            r1b += __bfloat162float(*reinterpret_cast<__nv_bfloat16*>(&u));
            c[mt][nt][0] = o0 + r0a; c[mt][nt][1] = o1 + r0b;
            c[mt][nt][2] = o2 + r1a; c[mt][nt][3] = o3 + r1b;
        }
    }
#pragma unroll
    for (int mt = 0; mt < 2; mt++) {
        float s0 = 0.f, q0 = 0.f, s1 = 0.f, q1 = 0.f;
#pragma unroll
        for (int nt = 0; nt < 8; nt++) {
            float o0 = c[mt][nt][0], o1 = c[mt][nt][1];
            float o2 = c[mt][nt][2], o3 = c[mt][nt][3];
            s0 += o0 + o1; q0 += o0 * o0 + o1 * o1;
            s1 += o2 + o3; q1 += o2 * o2 + o3 * o3;
        }
#pragma unroll
        for (int o = 1; o < 4; o <<= 1) {
            s0 += __shfl_xor_sync(0xFFFFFFFFu, s0, o);
            q0 += __shfl_xor_sync(0xFFFFFFFFu, q0, o);
            s1 += __shfl_xor_sync(0xFFFFFFFFu, s1, o);
            q1 += __shfl_xor_sync(0xFFFFFFFFu, q1, o);
        }
        if (tig == 0) {
            int lr0 = warpM * 32 + mt * 16 + gid;
            rb[lr0 * 4 + warpN]       = make_float2(s0, q0);
            rb[(lr0 + 8) * 4 + warpN] = make_float2(s1, q1);
        }
    }
    __syncthreads();
    float sd[2][2] = {{0.f, 0.f}, {0.f, 0.f}};
#pragma unroll
    for (int mt = 0; mt < 2; mt++) {
        int lr0 = warpM * 32 + mt * 16 + gid;
        int lr1 = lr0 + 8;
        float2 p00 = rb[lr0*4+0], p01 = rb[lr0*4+1], p02 = rb[lr0*4+2], p03 = rb[lr0*4+3];
        float2 p10 = rb[lr1*4+0], p11 = rb[lr1*4+1], p12 = rb[lr1*4+2], p13 = rb[lr1*4+3];
        float sum0 = p00.x + p01.x + p02.x + p03.x;
        float sq0  = p00.y + p01.y + p02.y + p03.y;
        float sum1 = p10.x + p11.x + p12.x + p13.x;
        float sq1  = p10.y + p11.y + p12.y + p13.y;
        float mean0 = sum0 * (1.f / 256.f);
        float rstd0 = rsqrtf(sq0 * (1.f / 256.f) - mean0 * mean0 + 1e-5f);
        float mean1 = sum1 * (1.f / 256.f);
        float rstd1 = rsqrtf(sq1 * (1.f / 256.f) - mean1 * mean1 + 1e-5f);
        int r0 = rowBase + lr0, r1 = rowBase + lr1;
        bool v0 = r0 < Mrows, v1 = r1 < Mrows;
#pragma unroll
        for (int nt = 0; nt < 8; nt++) {
            int col = warpN * 64 + nt * 8 + tig * 2;
            float2 gv = *reinterpret_cast<const float2*>(lng2 + col);
            float2 bv = *reinterpret_cast<const float2*>(lnb2 + col);
            float o0 = (c[mt][nt][0] - mean0) * rstd0 * gv.x + bv.x;
            float o1 = (c[mt][nt][1] - mean0) * rstd0 * gv.y + bv.y;
            float o2 = (c[mt][nt][2] - mean1) * rstd1 * gv.x + bv.x;
            float o3 = (c[mt][nt][3] - mean1) * rstd1 * gv.y + bv.y;
            if (v0) *reinterpret_cast<float2*>(C2 + (size_t)r0 * DD + col) = make_float2(o0, o1);
            if (v1) *reinterpret_cast<float2*>(C2 + (size_t)r1 * DD + col) = make_float2(o2, o3);
            float2 avv = *reinterpret_cast<const float2*>(av + col);
            sd[mt][0] += o0 * avv.x + o1 * avv.y;
            sd[mt][1] += o2 * avv.x + o3 * avv.y;
        }
    }
    __syncthreads();
#pragma unroll
    for (int mt = 0; mt < 2; mt++) {
        float s0 = sd[mt][0], s1 = sd[mt][1];
#pragma unroll
        for (int o = 1; o < 4; o <<= 1) {
            s0 += __shfl_xor_sync(0xFFFFFFFFu, s0, o);
            s1 += __shfl_xor_sync(0xFFFFFFFFu, s1, o);
        }
        if (tig == 0) {
            int lr0 = warpM * 32 + mt * 16 + gid;
            rb[lr0 * 4 + warpN]       = make_float2(s0, 0.f);
            rb[(lr0 + 8) * 4 + warpN] = make_float2(s1, 0.f);
        }
    }
    __syncthreads();
    if (warpN == 0 && tig == 0) {
#pragma unroll
        for (int mt = 0; mt < 2; mt++) {
            int lr0 = warpM * 32 + mt * 16 + gid;
#pragma unroll
            for (int h = 0; h < 2; h++) {
                int lr = lr0 + h * 8;
                int row = rowBase + lr;
                if (row < Mrows) {
                    snode[row] = rb[lr * 4 + 0].x + rb[lr * 4 + 1].x
                               + rb[lr * 4 + 2].x + rb[lr * 4 + 3].x;
                }
            }
        }
    }
}

// -------- edge gather (value-direct node ids) --------
__global__ void edge_gatherX(const float* __restrict__ X, const int* __restrict__ nodeE,
                             const int* __restrict__ offE, const int* __restrict__ cntE,
                             float* __restrict__ Xmean, int act, int nEdges)
{
    int ed = blockIdx.x * 8 + (threadIdx.x >> 5);
    if (ed >= nEdges) return;
    int lane = threadIdx.x & 31;
    int start = offE[ed], deg = cntE[ed];
    float4 a0 = make_float4(0.f,0.f,0.f,0.f), a1 = a0;
    for (int base = 0; base < deg; base += 32) {
        int m = min(32, deg - base);
        int src = 0;
        if (lane < m) src = nodeE[start + base + lane];
        for (int i = 0; i < m; i++) {
            int node = __shfl_sync(0xFFFFFFFFu, src, i);
            const float4* rp = reinterpret_cast<const float4*>(X + (size_t)node * DD + lane * 8);
            float4 v0 = rp[0], v1 = rp[1];
            if (act) {
                v0.x = lrelu_f(v0.x); v0.y = lrelu_f(v0.y); v0.z = lrelu_f(v0.z); v0.w = lrelu_f(v0.w);
                v1.x = lrelu_f(v1.x); v1.y = lrelu_f(v1.y); v1.z = lrelu_f(v1.z); v1.w = lrelu_f(v1.w);
            }
            a0.x += v0.x; a0.y += v0.y; a0.z += v0.z; a0.w += v0.w;
            a1.x += v1.x; a1.y += v1.y; a1.z += v1.z; a1.w += v1.w;
        }
    }
    float inv = 1.f / fmaxf((float)deg, 1.f);
    a0.x *= inv; a0.y *= inv; a0.z *= inv; a0.w *= inv;
    a1.x *= inv; a1.y *= inv; a1.z *= inv; a1.w *= inv;
    float4* op = reinterpret_cast<float4*>(Xmean + (size_t)ed * DD + lane * 8);
    op[0] = a0; op[1] = a1;
}

// -------- fused per-node softmax + aggregate --------
__global__ void node_attn_agg(const float* __restrict__ ef, const float* __restrict__ sn,
                              const float* __restrict__ se, const int* __restrict__ edN,
                              const int* __restrict__ permN, const int* __restrict__ offN,
                              const int* __restrict__ cntN, float* __restrict__ attn,
                              float* __restrict__ out, const float* __restrict__ av,
                              float* __restrict__ snodeOut, int doLrelu, int nNodes)
{
    int n = blockIdx.x * 8 + (threadIdx.x >> 5);
    if (n >= nNodes) return;
    int lane = threadIdx.x & 31;
    int st = offN[n], deg = cntN[n];
    float4 a0 = make_float4(0.f,0.f,0.f,0.f), a1 = a0;

    if (deg > 0) {
        float s0 = sn[n];
        if (deg <= 32) {
            int ed = 0;
            float sc = -3.4e38f;
            if (lane < deg) {
                ed = edN[st + lane];
                sc = lrelu_f(s0 + se[ed]);
            }
            float mx = sc;
#pragma unroll
            for (int o = 16; o; o >>= 1) mx = fmaxf(mx, __shfl_xor_sync(0xFFFFFFFFu, mx, o));
            float e = (lane < deg) ? expf(sc - mx) : 0.f;
            float z = e;
#pragma unroll
            for (int o = 16; o; o >>= 1) z += __shfl_xor_sync(0xFFFFFFFFu, z, o);
            float w = e / fmaxf(z, 1e-9f);
            if (lane < deg && attn != nullptr) attn[permN[st + lane]] = w;
            for (int i = 0; i < deg; i++) {
                int e_   = __shfl_sync(0xFFFFFFFFu, ed, i);
                float w_ = __shfl_sync(0xFFFFFFFFu, w, i);
                const float4* rp = reinterpret_cast<const float4*>(ef + (size_t)e_ * DD + lane * 8);
                float4 v0 = rp[0], v1 = rp[1];
                a0.x += w_*v0.x; a0.y += w_*v0.y; a0.z += w_*v0.z; a0.w += w_*v0.w;
                a1.x += w_*v1.x; a1.y += w_*v1.y; a1.z += w_*v1.z; a1.w += w_*v1.w;
            }
        } else {
            float mx = -3.4e38f;
            for (int base = 0; base < deg; base += 32) {
                float sc = -3.4e38f;
                if (base + lane < deg)
                    sc = lrelu_f(s0 + se[edN[st + base + lane]]);
                mx = fmaxf(mx, sc);
            }
#pragma unroll
            for (int o = 16; o; o >>= 1) mx = fmaxf(mx, __shfl_xor_sync(0xFFFFFFFFu, mx, o));
            float z = 0.f;
            for (int base = 0; base < deg; base += 32) {
                if (base + lane < deg)
                    z += expf(lrelu_f(s0 + se[edN[st + base + lane]]) - mx);
            }
#pragma unroll
            for (int o = 16; o; o >>= 1) z += __shfl_xor_sync(0xFFFFFFFFu, z, o);
            float invz = 1.f / fmaxf(z, 1e-9f);
            for (int base = 0; base < deg; base += 32) {
                int m = min(32, deg - base);
                int ed = 0; float w = 0.f;
                if (lane < m) {
                    ed = edN[st + base + lane];
                    w = expf(lrelu_f(s0 + se[ed]) - mx) * invz;
                    if (attn != nullptr) attn[permN[st + base + lane]] = w;
                }
                for (int i = 0; i < m; i++) {
                    int e_   = __shfl_sync(0xFFFFFFFFu, ed, i);
                    float w_ = __shfl_sync(0xFFFFFFFFu, w, i);
                    const float4* rp = reinterpret_cast<const float4*>(ef + (size_t)e_ * DD + lane * 8);
                    float4 v0 = rp[0], v1 = rp[1];
                    a0.x += w_*v0.x; a0.y += w_*v0.y; a0.z += w_*v0.z; a0.w += w_*v0.w;
                    a1.x += w_*v1.x; a1.y += w_*v1.y; a1.z += w_*v1.z; a1.w += w_*v1.w;
                }
            }
        }
    }
    if (snodeOut != nullptr) {
        const float4* ap = reinterpret_cast<const float4*>(av + lane * 8);
        float4 w0 = ap[0], w1 = ap[1];
        float d = lrelu_f(a0.x)*w0.x + lrelu_f(a0.y)*w0.y + lrelu_f(a0.z)*w0.z + lrelu_f(a0.w)*w0.w
                + lrelu_f(a1.x)*w1.x + lrelu_f(a1.y)*w1.y + lrelu_f(a1.z)*w1.z + lrelu_f(a1.w)*w1.w;
#pragma unroll
        for (int o = 16; o; o >>= 1) d += __shfl_xor_sync(0xFFFFFFFFu, d, o);
        if (lane == 0) snodeOut[n] = d;
    }
    if (doLrelu) {
        a0.x = lrelu_f(a0.x); a0.y = lrelu_f(a0.y); a0.z = lrelu_f(a0.z); a0.w = lrelu_f(a0.w);
        a1.x = lrelu_f(a1.x); a1.y = lrelu_f(a1.y); a1.z = lrelu_f(a1.z); a1.w = lrelu_f(a1.w);
    }
    float4* op = reinterpret_cast<float4*>(out + (size_t)n * DD + lane * 8);
    op[0] = a0; op[1] = a1;
}

// -------- object message gather --------
__global__ void obj_gather(const float* __restrict__ ev, const int* __restrict__ srcO,
                           const int* __restrict__ offO, const int* __restrict__ cntO,
                           float* __restrict__ msg, int nObj)
{
    int o = blockIdx.x * 8 + (threadIdx.x >> 5);
    if (o >= nObj) return;
    int lane = threadIdx.x & 31;
    int start = offO[o], deg = cntO[o];
    float4 a0 = make_float4(0.f,0.f,0.f,0.f), a1 = a0;
    for (int base = 0; base < deg; base += 32) {
        int m = min(32, deg - base);
        int src = 0;
        if (lane < m) src = srcO[start + base + lane];
        for (int i = 0; i < m; i++) {
            int row = __shfl_sync(0xFFFFFFFFu, src, i);
            const float4* rp = reinterpret_cast<const float4*>(ev + (size_t)row * DD + lane * 8);
            float4 v0 = rp[0], v1 = rp[1];
            a0.x += v0.x; a0.y += v0.y; a0.z += v0.z; a0.w += v0.w;
            a1.x += v1.x; a1.y += v1.y; a1.z += v1.z; a1.w += v1.w;
        }
    }
    float4* op = reinterpret_cast<float4*>(msg + (size_t)o * DD + lane * 8);
    op[0] = a0; op[1] = a1;
}

// ----------------- host orchestration -----------------
struct Ptrs {
    float *X, *obj, *msg, *H, *ef, *snode, *sedge, *wav1, *wav2;
    unsigned char* wp;
    int *cntE, *offE, *nodeE, *cntN, *offN, *permN, *edN, *cntO, *offO, *srcO;
};

static void get_ptrs(Ptrs& p) {
    cudaGetSymbolAddress((void**)&p.X,     g_X);
    cudaGetSymbolAddress((void**)&p.obj,   g_obj);
    cudaGetSymbolAddress((void**)&p.msg,   g_msg);
    cudaGetSymbolAddress((void**)&p.H,     g_H);
    cudaGetSymbolAddress((void**)&p.ef,    g_ef);
    cudaGetSymbolAddress((void**)&p.snode, g_snode);
    cudaGetSymbolAddress((void**)&p.sedge, g_sedge);
    cudaGetSymbolAddress((void**)&p.wav1,  g_wav1);
    cudaGetSymbolAddress((void**)&p.wav2,  g_wav2);
    cudaGetSymbolAddress((void**)&p.wp,    g_Wprep);
    cudaGetSymbolAddress((void**)&p.cntE,  g_cntE);
    cudaGetSymbolAddress((void**)&p.offE,  g_offE);
    cudaGetSymbolAddress((void**)&p.nodeE, g_nodeE);
    cudaGetSymbolAddress((void**)&p.cntN,  g_cntN);
    cudaGetSymbolAddress((void**)&p.offN,  g_offN);
    cudaGetSymbolAddress((void**)&p.permN, g_permN);
    cudaGetSymbolAddress((void**)&p.edN,   g_edN);
    cudaGetSymbolAddress((void**)&p.cntO,  g_cntO);
    cudaGetSymbolAddress((void**)&p.offO,  g_offO);
    cudaGetSymbolAddress((void**)&p.srcO,  g_srcO);
}

extern "C" void kernel_launch(void* const* d_in, const int* in_sizes, int n_in,
                              void* d_out, int out_size)
{
    const float* object_X = (const float*)d_in[0];
    const float* event_X  = (const float*)d_in[1];
    const float* Wo = (const float*)d_in[2];  const float* bo  = (const float*)d_in[3];
    const float* go = (const float*)d_in[4];  const float* bon = (const float*)d_in[5];
    const float* We = (const float*)d_in[6];  const float* be  = (const float*)d_in[7];
    const float* ge = (const float*)d_in[8];  const float* ben = (const float*)d_in[9];
    const float* Wu = (const float*)d_in[10]; const float* bu  = (const float*)d_in[11];
    const float* Wl = (const float*)d_in[12]; const float* bl  = (const float*)d_in[13];
    const float* g1 = (const float*)d_in[14]; const float* b1  = (const float*)d_in[15];
    const float* g2 = (const float*)d_in[16]; const float* b2  = (const float*)d_in[17];
    const float* Wh1 = (const float*)d_in[18]; const float* ah1 = (const float*)d_in[19];
    const float* Wh2 = (const float*)d_in[20]; const float* ah2 = (const float*)d_in[21];
    const int* oe_ev   = (const int*)d_in[22];
    const int* oe_obj  = (const int*)d_in[23];
    const int* hg_node = (const int*)d_in[24];
    const int* hg_edge = (const int*)d_in[25];

    Ptrs p; get_ptrs(p);

    static cudaStream_t s2 = nullptr;
    static cudaEvent_t evFork = nullptr, evJoin = nullptr;
    if (s2 == nullptr) {
        cudaStreamCreateWithFlags(&s2, cudaStreamNonBlocking);
        cudaEventCreateWithFlags(&evFork, cudaEventDisableTiming);
        cudaEventCreateWithFlags(&evJoin, cudaEventDisableTiming);
    }

    // ---- fork: CSR build on side stream, overlapped with weight prep + proj GEMM ----
    cudaEventRecord(evFork, 0);
    cudaStreamWaitEvent(s2, evFork, 0);
    zero_misc<<<(2 * (NE + NN + NO) + 255) / 256, 256, 0, s2>>>();
    count_all<<<(2 * E2N + E1N + 255) / 256, 256, 0, s2>>>(hg_edge, hg_node, oe_obj);
    scan_all<<<NBT, 1024, 0, s2>>>();
    scan_small3<<<1, 32, 0, s2>>>();
    add_off_all<<<(NE + NN + NO + 255) / 256, 256, 0, s2>>>();
    fill_all<<<(2 * E2N + E1N + 255) / 256, 256, 0, s2>>>(hg_edge, hg_node, oe_obj, oe_ev);
    cudaEventRecord(evJoin, s2);

    // ---- main stream: weight prep + projections ----
    prep_w<<<dim3(32, 6), 256>>>(We, Wo, Wu, Wl, Wh1, Wh2);
    prep_wav2<<<dim3((DD + 7) / 8, 2), 256>>>(Wh1, ah1, Wh2, ah2, p.wav1, p.wav2);

    const unsigned char *wpe = p.wp, *wpo = p.wp + 262144, *wpu = p.wp + 2 * 262144,
                        *wpl = p.wp + 3 * 262144, *wph1 = p.wp + 4 * 262144,
                        *wph2 = p.wp + 5 * 262144;

    cudaFuncSetAttribute(proj_gemm, cudaFuncAttributeMaxDynamicSharedMemorySize, SMEM_SZ);
    int nb0 = (NE + 127) / 128, nb1 = (NO + 127) / 128;
    proj_gemm<<<nb0 + nb1, 512, SMEM_SZ>>>(
        event_X, wpe, be, ge, ben, p.X, p.wav1, p.snode, NE, nb0,
        object_X, wpo, bo, go, bon, p.obj, NO);

    // ---- join: CSR must be ready before gathers ----
    cudaStreamWaitEvent(0, evJoin, 0);

    // 3) msg = segment_sum(ev[oe_ev], oe_obj)
    obj_gather<<<(NO + 7) / 8, 256>>>(p.X, p.srcO, p.offO, p.cntO, p.msg, NO);

    // 4+5) fused dual GEMM -> X[NE:NN) + snode for obj rows
    cudaFuncSetAttribute(tgemm_dual, cudaFuncAttributeMaxDynamicSharedMemorySize, SMEM_SZ);
    tgemm_dual<<<(NO + 127) / 128, 512, SMEM_SZ>>>(p.msg, wpu, bu, p.obj, g1, b1,
                                                   wpl, bl, g2, b2,
                                                   p.X + (size_t)NE * DD,
                                                   p.wav1, p.snode + NE, NO);

    // 6) HGNN layer 1 -> H; snode2 fused into node_attn_agg
    cudaFuncSetAttribute(tgemm256<F_SNODE>, cudaFuncAttributeMaxDynamicSharedMemorySize, SMEM_SZ);
    edge_gatherX<<<(NE + 7) / 8, 256>>>(p.X, p.nodeE, p.offE, p.cntE, p.msg, 0, NE);
    tgemm256<F_SNODE><<<(NE + 127) / 128, 512, SMEM_SZ>>>(p.msg, wph1, ah1 + DD, p.ef, p.sedge, NE);
    node_attn_agg<<<(NN + 7) / 8, 256>>>(p.ef, p.snode, p.sedge, p.edN,
                                         p.permN, p.offN, p.cntN,
                                         nullptr, p.H, p.wav2, p.snode, 0, NN);

    // 7) HGNN layer 2 -> d_out
    float* out = (float*)d_out;
    edge_gatherX<<<(NE + 7) / 8, 256>>>(p.H, p.nodeE, p.offE, p.cntE, p.msg, 1, NE);
    tgemm256<F_SNODE><<<(NE + 127) / 128, 512, SMEM_SZ>>>(p.msg, wph2, ah2 + DD, p.ef, p.sedge, NE);
    node_attn_agg<<<(NN + 7) / 8, 256>>>(p.ef, p.snode, p.sedge, p.edN,
                                         p.permN, p.offN, p.cntN,
                                         out + (size_t)NN * DD, out, nullptr, nullptr, 1, NN);
}

// round 16
// speedup vs baseline: 1.0566x; 1.0370x over previous
#include <cuda_runtime.h>
#include <cuda_bf16.h>
#include <cuda_fp16.h>
#include <cstdint>

#define DD 256
static const int NE  = 50000;
static const int NO  = 100000;
static const int NN  = 150000;
static const int E1N = 400000;
static const int E2N = 800000;

// -------- device scratch --------
__device__ float    g_X  [(size_t)NN * DD];
__device__ __half   g_Xh [(size_t)NN * DD];   // fp16 mirror of X (gather source)
__device__ float    g_obj[(size_t)NO * DD];
__device__ float    g_msg[(size_t)NO * DD];   // also Xmean[NE*DD] in hgnn layers
__device__ float    g_H  [(size_t)NN * DD];
__device__ __half   g_Hh [(size_t)NN * DD];   // fp16 mirror of H
__device__ float    g_ef [(size_t)NE * DD];
__device__ float    g_snode[NN];
__device__ float    g_sedge[NE];
__device__ float    g_wav1[DD];
__device__ float    g_wav2[DD];
__device__ unsigned char g_Wprep[6 * 4 * 2 * 256 * 128];
// CSR structures (value-direct)
__device__ int g_cntE[NE],  g_offE[NE],  g_nodeE[E2N];
__device__ int g_cntN[NN],  g_offN[NN],  g_permN[E2N], g_edN[E2N];
__device__ int g_cntO[NO],  g_offO[NO],  g_srcO[E1N];
__device__ int g_cur[NE + NN + NO];
__device__ int g_bsum[512];

static const int NBE = (NE + 1023) / 1024;
static const int NBN = (NN + 1023) / 1024;
static const int NBO = (NO + 1023) / 1024;
static const int NBT = NBE + NBN + NBO;

// -------- helpers --------
__device__ __forceinline__ float lrelu_f(float x) { return x >= 0.f ? x : 0.2f * x; }

__device__ __forceinline__ uint32_t smem_to_u32(const void* p) {
    uint32_t a;
    asm("{ .reg .u64 t; cvta.to.shared.u64 t, %1; cvt.u32.u64 %0, t; }" : "=r"(a) : "l"(p));
    return a;
}
__device__ __forceinline__ void ldm_x4(uint32_t addr, uint32_t* r) {
    asm volatile("ldmatrix.sync.aligned.m8n8.x4.shared.b16 {%0,%1,%2,%3}, [%4];"
                 : "=r"(r[0]), "=r"(r[1]), "=r"(r[2]), "=r"(r[3]) : "r"(addr));
}
__device__ __forceinline__ void mma_bf16(float* c, const uint32_t* a, const uint32_t* b) {
    asm volatile("mma.sync.aligned.m16n8k16.row.col.f32.bf16.bf16.f32 "
                 "{%0,%1,%2,%3}, {%4,%5,%6,%7}, {%8,%9}, {%0,%1,%2,%3};"
                 : "+f"(c[0]), "+f"(c[1]), "+f"(c[2]), "+f"(c[3])
                 : "r"(a[0]), "r"(a[1]), "r"(a[2]), "r"(a[3]), "r"(b[0]), "r"(b[1]));
}
__device__ __forceinline__ uint32_t swz(uint32_t row, uint32_t cb) {
    return row * 128u + (cb ^ ((row & 7u) << 4));
}
__device__ __forceinline__ uint32_t swz512(uint32_t row, uint32_t cb) {
    return row * 512u + (cb ^ ((row & 7u) << 4));
}
#define CP_ASYNC16(dst, src) \
    asm volatile("cp.async.cg.shared.global [%0], [%1], 16;" :: "r"(dst), "l"(src) : "memory")
#define CP_COMMIT() asm volatile("cp.async.commit_group;" ::: "memory")
#define CP_WAIT(n)  asm volatile("cp.async.wait_group %0;" :: "n"(n) : "memory")

enum { F_SNODE = 16 };

// unpack 8 halves (uint4) to 8 floats with optional lrelu
__device__ __forceinline__ void half8_to_f(uint4 v, float* f, int act) {
    const __half2* hp = reinterpret_cast<const __half2*>(&v);
#pragma unroll
    for (int i = 0; i < 4; i++) {
        float2 t = __half22float2(hp[i]);
        f[i * 2]     = act ? lrelu_f(t.x) : t.x;
        f[i * 2 + 1] = act ? lrelu_f(t.y) : t.y;
    }
}

// ======== condensed CSR build ========
__global__ void zero_misc()
{
    int g = blockIdx.x * blockDim.x + threadIdx.x;
    if (g < NE) g_cntE[g] = 0;
    else if (g < NE + NN) g_cntN[g - NE] = 0;
    else if (g < NE + NN + NO) g_cntO[g - NE - NN] = 0;
    int h = g - (NE + NN + NO);
    if (h >= 0 && h < NE + NN + NO) g_cur[h] = 0;
}
__global__ void count_all(const int* __restrict__ he, const int* __restrict__ hn,
                          const int* __restrict__ oo)
{
    int t = blockIdx.x * blockDim.x + threadIdx.x;
    if (t < E2N) atomicAdd(&g_cntE[he[t]], 1);
    else if (t < 2 * E2N) atomicAdd(&g_cntN[hn[t - E2N]], 1);
    else if (t < 2 * E2N + E1N) atomicAdd(&g_cntO[oo[t - 2 * E2N]], 1);
}
__global__ void scan_all()
{
    __shared__ int sh[1024];
    int b = blockIdx.x;
    const int* cnt; int* off; int nseg; int lb;
    if (b < NBE)            { cnt = g_cntE; off = g_offE; nseg = NE; lb = b; }
    else if (b < NBE + NBN) { cnt = g_cntN; off = g_offN; nseg = NN; lb = b - NBE; }
    else                    { cnt = g_cntO; off = g_offO; nseg = NO; lb = b - NBE - NBN; }
    int g = lb * 1024 + threadIdx.x;
    int v = (g < nseg) ? cnt[g] : 0;
    sh[threadIdx.x] = v;
    __syncthreads();
#pragma unroll
    for (int o = 1; o < 1024; o <<= 1) {
        int t = (threadIdx.x >= o) ? sh[threadIdx.x - o] : 0;
        __syncthreads();
        sh[threadIdx.x] += t;
        __syncthreads();
    }
    if (g < nseg) off[g] = sh[threadIdx.x] - v;
    if (threadIdx.x == 1023) g_bsum[b] = sh[1023];
}
__global__ void scan_small3()
{
    int t = threadIdx.x;
    int s, e;
    if (t == 0)      { s = 0;          e = NBE; }
    else if (t == 1) { s = NBE;        e = NBE + NBN; }
    else if (t == 2) { s = NBE + NBN;  e = NBT; }
    else return;
    int run = 0;
    for (int i = s; i < e; i++) { int v = g_bsum[i]; g_bsum[i] = run; run += v; }
}
__global__ void add_off_all()
{
    int g = blockIdx.x * blockDim.x + threadIdx.x;
    if (g < NE) g_offE[g] += g_bsum[g >> 10];
    else if (g < NE + NN) {
        int l = g - NE; g_offN[l] += g_bsum[NBE + (l >> 10)];
    } else if (g < NE + NN + NO) {
        int l = g - NE - NN; g_offO[l] += g_bsum[NBE + NBN + (l >> 10)];
    }
}
__global__ void fill_all(const int* __restrict__ he, const int* __restrict__ hn,
                         const int* __restrict__ oo, const int* __restrict__ oev)
{
    int t = blockIdx.x * blockDim.x + threadIdx.x;
    if (t < E2N) {
        int s = he[t];
        int pos = g_offE[s] + atomicAdd(&g_cur[s], 1);
        g_nodeE[pos] = hn[t];
    } else if (t < 2 * E2N) {
        int e = t - E2N;
        int s = hn[e];
        int pos = g_offN[s] + atomicAdd(&g_cur[NE + s], 1);
        g_permN[pos] = e;
        g_edN[pos]   = he[e];
    } else if (t < 2 * E2N + E1N) {
        int e = t - 2 * E2N;
        int s = oo[e];
        int pos = g_offO[s] + atomicAdd(&g_cur[NE + NN + s], 1);
        g_srcO[pos] = oev[e];
    }
}

// -------- weight prep --------
__global__ void prep_w(const float* W0, const float* W1, const float* W2,
                       const float* W3, const float* W4, const float* W5)
{
    const float* Ws[6] = {W0, W1, W2, W3, W4, W5};
    const float* W = Ws[blockIdx.y];
    unsigned char* base = g_Wprep + (size_t)blockIdx.y * 262144;
    int g = blockIdx.x * 256 + threadIdx.x;
    int n = g >> 5, kg = g & 31, k0 = kg * 8;
    unsigned short hi[8], lo[8];
#pragma unroll
    for (int i = 0; i < 8; i++) {
        float x = W[(size_t)(k0 + i) * DD + n];
        __nv_bfloat16 h = __float2bfloat16(x);
        __nv_bfloat16 l = __float2bfloat16(x - __bfloat162float(h));
        hi[i] = *reinterpret_cast<unsigned short*>(&h);
        lo[i] = *reinterpret_cast<unsigned short*>(&l);
    }
    int chunk = k0 >> 6, kc = k0 & 63;
    uint32_t off = (uint32_t)n * 128u + (((uint32_t)kc * 2u) ^ (((uint32_t)n & 7u) << 4));
    *reinterpret_cast<uint4*>(base + (size_t)(chunk * 2 + 0) * 32768 + off) =
        *reinterpret_cast<uint4*>(hi);
    *reinterpret_cast<uint4*>(base + (size_t)(chunk * 2 + 1) * 32768 + off) =
        *reinterpret_cast<uint4*>(lo);
}

__global__ void prep_wav2(const float* __restrict__ W1, const float* __restrict__ a1,
                          const float* __restrict__ W2, const float* __restrict__ a2,
                          float* __restrict__ w1, float* __restrict__ w2)
{
    const float* W = (blockIdx.y == 0) ? W1 : W2;
    const float* a = (blockIdx.y == 0) ? a1 : a2;
    float* w = (blockIdx.y == 0) ? w1 : w2;
    int k = blockIdx.x * 8 + (threadIdx.x >> 5);
    if (k >= DD) return;
    int lane = threadIdx.x & 31;
    const float4* rp = reinterpret_cast<const float4*>(W + (size_t)k * DD);
    const float4* ap = reinterpret_cast<const float4*>(a);
    float4 v0 = rp[lane], v1 = rp[lane + 32];
    float4 a0 = ap[lane], a1v = ap[lane + 32];
    float d = v0.x*a0.x + v0.y*a0.y + v0.z*a0.z + v0.w*a0.w
            + v1.x*a1v.x + v1.y*a1v.y + v1.z*a1v.z + v1.w*a1v.w;
#pragma unroll
    for (int o = 16; o; o >>= 1) d += __shfl_xor_sync(0xFFFFFFFFu, d, o);
    if (lane == 0) w[k] = d;
}

static const int SMEM_SZ = 196608;

// ======== combined projection GEMM (+ fp16 mirror write for job0) ========
__global__ __launch_bounds__(512, 1)
void proj_gemm(const float* __restrict__ A0, const unsigned char* __restrict__ Wp0,
               const float* __restrict__ bias0, const float* __restrict__ lng0,
               const float* __restrict__ lnb0, float* __restrict__ C0,
               __half* __restrict__ C0h,
               const float* __restrict__ av0, float* __restrict__ snode0, int M0, int nb0,
               const float* __restrict__ A1, const unsigned char* __restrict__ Wp1,
               const float* __restrict__ bias1, const float* __restrict__ lng1,
               const float* __restrict__ lnb1, float* __restrict__ C1, int M1)
{
    extern __shared__ __align__(128) unsigned char smem[];
    const uint32_t sb = smem_to_u32(smem);
    const int tid = threadIdx.x, lane = tid & 31, wid = tid >> 5;
    const int warpM = wid >> 2, warpN = wid & 3;

    const float* A; const unsigned char* Wp; const float* bias;
    const float* lng; const float* lnb; float* C; __half* Ch;
    const float* av; float* snode; int Mrows, rowBase;
    if ((int)blockIdx.x < nb0) {
        A = A0; Wp = Wp0; bias = bias0; lng = lng0; lnb = lnb0; C = C0; Ch = C0h;
        av = av0; snode = snode0; Mrows = M0; rowBase = blockIdx.x * 128;
    } else {
        A = A1; Wp = Wp1; bias = bias1; lng = lng1; lnb = lnb1; C = C1; Ch = nullptr;
        av = nullptr; snode = nullptr; Mrows = M1; rowBase = (blockIdx.x - nb0) * 128;
    }

    int rA[2], cgA[2];
#pragma unroll
    for (int i = 0; i < 2; i++) {
        int g = tid + i * 512;
        rA[i] = g >> 3; cgA[i] = g & 7;
    }
    float4 pref[4];

    auto issueA = [&](int ch) {
#pragma unroll
        for (int i = 0; i < 2; i++) {
            int row = rowBase + rA[i];
            if (row < Mrows) {
                const float4* src = reinterpret_cast<const float4*>(
                    A + (size_t)row * DD + ch * 64 + cgA[i] * 8);
                pref[i * 2]     = src[0];
                pref[i * 2 + 1] = src[1];
            } else {
                pref[i * 2]     = make_float4(0.f, 0.f, 0.f, 0.f);
                pref[i * 2 + 1] = make_float4(0.f, 0.f, 0.f, 0.f);
            }
        }
    };
    auto storeA = [&](int s) {
#pragma unroll
        for (int i = 0; i < 2; i++) {
            float x[8];
            float4 v0 = pref[i * 2], v1 = pref[i * 2 + 1];
            x[0] = v0.x; x[1] = v0.y; x[2] = v0.z; x[3] = v0.w;
            x[4] = v1.x; x[5] = v1.y; x[6] = v1.z; x[7] = v1.w;
            unsigned short hi[8], lo[8];
#pragma unroll
            for (int j = 0; j < 8; j++) {
                __nv_bfloat16 h = __float2bfloat16(x[j]);
                __nv_bfloat16 l = __float2bfloat16(x[j] - __bfloat162float(h));
                hi[j] = *reinterpret_cast<unsigned short*>(&h);
                lo[j] = *reinterpret_cast<unsigned short*>(&l);
            }
            uint32_t off = s * 32768u + swz((uint32_t)rA[i], (uint32_t)cgA[i] * 16u);
            *reinterpret_cast<uint4*>(smem + off)         = *reinterpret_cast<uint4*>(hi);
            *reinterpret_cast<uint4*>(smem + 16384 + off) = *reinterpret_cast<uint4*>(lo);
        }
    };
    auto issueB = [&](int ch, int s) {
        const unsigned char* bh = Wp + (size_t)(ch * 2 + 0) * 32768;
        const unsigned char* bl = Wp + (size_t)(ch * 2 + 1) * 32768;
        uint32_t dh = sb + 65536u + (uint32_t)s * 65536u;
        uint32_t dl = dh + 32768u;
#pragma unroll
        for (int i = 0; i < 4; i++) {
            int idx = (tid + i * 512) * 16;
            CP_ASYNC16(dh + idx, bh + idx);
            CP_ASYNC16(dl + idx, bl + idx);
        }
        CP_COMMIT();
    };

    float c[2][8][4];
#pragma unroll
    for (int mt = 0; mt < 2; mt++)
#pragma unroll
        for (int nt = 0; nt < 8; nt++)
#pragma unroll
            for (int q = 0; q < 4; q++) c[mt][nt][q] = 0.f;

    issueA(0);
    issueB(0, 0);
    storeA(0);

    for (int ch = 0; ch < 4; ch++) {
        const int s = ch & 1;
        if (ch < 3) {
            issueA(ch + 1);
            issueB(ch + 1, s ^ 1);
            CP_WAIT(1);
        } else {
            CP_WAIT(0);
        }
        __syncthreads();

        const uint32_t aBase = sb + (uint32_t)s * 32768u;
        const uint32_t bBase = sb + 65536u + (uint32_t)s * 65536u;
#pragma unroll
        for (int ks = 0; ks < 4; ks++) {
            uint32_t ah[2][4], al[2][4];
#pragma unroll
            for (int mt = 0; mt < 2; mt++) {
                uint32_t row = (uint32_t)(warpM * 32 + mt * 16 + (lane & 7) + ((lane >> 3) & 1) * 8);
                uint32_t kb  = (uint32_t)(ks * 32 + ((lane >> 4) & 1) * 16);
                uint32_t addr = aBase + swz(row, kb);
                ldm_x4(addr,         ah[mt]);
                ldm_x4(addr + 16384, al[mt]);
            }
#pragma unroll
            for (int p = 0; p < 4; p++) {
                uint32_t nrow = (uint32_t)(warpN * 64 + p * 16 + (lane & 7) + ((lane >> 4) & 1) * 8);
                uint32_t kb   = (uint32_t)(ks * 32 + ((lane >> 3) & 1) * 16);
                uint32_t addr = bBase + swz(nrow, kb);
                uint32_t bh[4], bl[4];
                ldm_x4(addr,         bh);
                ldm_x4(addr + 32768, bl);
#pragma unroll
                for (int t = 0; t < 2; t++) {
#pragma unroll
                    for (int mt = 0; mt < 2; mt++) {
                        float* cc = c[mt][p * 2 + t];
                        mma_bf16(cc, ah[mt], bh + t * 2);
                        mma_bf16(cc, ah[mt], bl + t * 2);
                        mma_bf16(cc, al[mt], bh + t * 2);
                    }
                }
            }
        }
        if (ch < 3) storeA(s ^ 1);
        __syncthreads();
    }

    const int gid = lane >> 2, tig = lane & 3;
    float2* rb = reinterpret_cast<float2*>(smem);

#pragma unroll
    for (int mt = 0; mt < 2; mt++)
#pragma unroll
        for (int nt = 0; nt < 8; nt++) {
            int col = warpN * 64 + nt * 8 + tig * 2;
            float2 bv = *reinterpret_cast<const float2*>(bias + col);
            c[mt][nt][0] = lrelu_f(c[mt][nt][0] + bv.x);
            c[mt][nt][1] = lrelu_f(c[mt][nt][1] + bv.y);
            c[mt][nt][2] = lrelu_f(c[mt][nt][2] + bv.x);
            c[mt][nt][3] = lrelu_f(c[mt][nt][3] + bv.y);
        }

#pragma unroll
    for (int mt = 0; mt < 2; mt++) {
        float s0 = 0.f, q0 = 0.f, s1 = 0.f, q1 = 0.f;
#pragma unroll
        for (int nt = 0; nt < 8; nt++) {
            float o0 = c[mt][nt][0], o1 = c[mt][nt][1];
            float o2 = c[mt][nt][2], o3 = c[mt][nt][3];
            s0 += o0 + o1; q0 += o0 * o0 + o1 * o1;
            s1 += o2 + o3; q1 += o2 * o2 + o3 * o3;
        }
#pragma unroll
        for (int o = 1; o < 4; o <<= 1) {
            s0 += __shfl_xor_sync(0xFFFFFFFFu, s0, o);
            q0 += __shfl_xor_sync(0xFFFFFFFFu, q0, o);
            s1 += __shfl_xor_sync(0xFFFFFFFFu, s1, o);
            q1 += __shfl_xor_sync(0xFFFFFFFFu, q1, o);
        }
        if (tig == 0) {
            int lr0 = warpM * 32 + mt * 16 + gid;
            rb[lr0 * 4 + warpN]       = make_float2(s0, q0);
            rb[(lr0 + 8) * 4 + warpN] = make_float2(s1, q1);
        }
    }
    __syncthreads();

    float sd[2][2] = {{0.f, 0.f}, {0.f, 0.f}};
#pragma unroll
    for (int mt = 0; mt < 2; mt++) {
        int lr0 = warpM * 32 + mt * 16 + gid;
        int lr1 = lr0 + 8;
        float2 p00 = rb[lr0*4+0], p01 = rb[lr0*4+1], p02 = rb[lr0*4+2], p03 = rb[lr0*4+3];
        float2 p10 = rb[lr1*4+0], p11 = rb[lr1*4+1], p12 = rb[lr1*4+2], p13 = rb[lr1*4+3];
        float sum0 = p00.x + p01.x + p02.x + p03.x;
        float sq0  = p00.y + p01.y + p02.y + p03.y;
        float sum1 = p10.x + p11.x + p12.x + p13.x;
        float sq1  = p10.y + p11.y + p12.y + p13.y;
        float mean0 = sum0 * (1.f / 256.f);
        float rstd0 = rsqrtf(sq0 * (1.f / 256.f) - mean0 * mean0 + 1e-5f);
        float mean1 = sum1 * (1.f / 256.f);
        float rstd1 = rsqrtf(sq1 * (1.f / 256.f) - mean1 * mean1 + 1e-5f);
        int r0 = rowBase + lr0, r1 = rowBase + lr1;
        bool v0 = r0 < Mrows, v1 = r1 < Mrows;
#pragma unroll
        for (int nt = 0; nt < 8; nt++) {
            int col = warpN * 64 + nt * 8 + tig * 2;
            float2 gv = *reinterpret_cast<const float2*>(lng + col);
            float2 bv = *reinterpret_cast<const float2*>(lnb + col);
            float o0 = (c[mt][nt][0] - mean0) * rstd0 * gv.x + bv.x;
            float o1 = (c[mt][nt][1] - mean0) * rstd0 * gv.y + bv.y;
            float o2 = (c[mt][nt][2] - mean1) * rstd1 * gv.x + bv.x;
            float o3 = (c[mt][nt][3] - mean1) * rstd1 * gv.y + bv.y;
            if (v0) {
                *reinterpret_cast<float2*>(C + (size_t)r0 * DD + col) = make_float2(o0, o1);
                if (Ch) *reinterpret_cast<__half2*>(Ch + (size_t)r0 * DD + col) = __floats2half2_rn(o0, o1);
            }
            if (v1) {
                *reinterpret_cast<float2*>(C + (size_t)r1 * DD + col) = make_float2(o2, o3);
                if (Ch) *reinterpret_cast<__half2*>(Ch + (size_t)r1 * DD + col) = __floats2half2_rn(o2, o3);
            }
            if (snode != nullptr) {
                float2 avv = *reinterpret_cast<const float2*>(av + col);
                sd[mt][0] += o0 * avv.x + o1 * avv.y;
                sd[mt][1] += o2 * avv.x + o3 * avv.y;
            }
        }
    }

    if (snode != nullptr) {
        __syncthreads();
#pragma unroll
        for (int mt = 0; mt < 2; mt++) {
            float s0 = sd[mt][0], s1 = sd[mt][1];
#pragma unroll
            for (int o = 1; o < 4; o <<= 1) {
                s0 += __shfl_xor_sync(0xFFFFFFFFu, s0, o);
                s1 += __shfl_xor_sync(0xFFFFFFFFu, s1, o);
            }
            if (tig == 0) {
                int lr0 = warpM * 32 + mt * 16 + gid;
                rb[lr0 * 4 + warpN]       = make_float2(s0, 0.f);
                rb[(lr0 + 8) * 4 + warpN] = make_float2(s1, 0.f);
            }
        }
        __syncthreads();
        if (warpN == 0 && tig == 0) {
#pragma unroll
            for (int mt = 0; mt < 2; mt++) {
                int lr0 = warpM * 32 + mt * 16 + gid;
#pragma unroll
                for (int h = 0; h < 2; h++) {
                    int lr = lr0 + h * 8;
                    int row = rowBase + lr;
                    if (row < Mrows) {
                        snode[row] = rb[lr * 4 + 0].x + rb[lr * 4 + 1].x
                                   + rb[lr * 4 + 2].x + rb[lr * 4 + 3].x;
                    }
                }
            }
        }
    }
}

// ======== hgnn edge GEMM ========
template <int FLAGS>
__global__ __launch_bounds__(512, 1)
void tgemm256(const float* __restrict__ A, const unsigned char* __restrict__ Wp,
              const float* __restrict__ av, float* __restrict__ C,
              float* __restrict__ snode, int Mrows)
{
    extern __shared__ __align__(128) unsigned char smem[];
    const uint32_t sb = smem_to_u32(smem);
    const int tid = threadIdx.x, lane = tid & 31, wid = tid >> 5;
    const int warpM = wid >> 2, warpN = wid & 3;
    const int rowBase = blockIdx.x * 128;

    int rA[2], cgA[2];
#pragma unroll
    for (int i = 0; i < 2; i++) {
        int g = tid + i * 512;
        rA[i] = g >> 3; cgA[i] = g & 7;
    }
    float4 pref[4];

    auto issueA = [&](int ch) {
#pragma unroll
        for (int i = 0; i < 2; i++) {
            int row = rowBase + rA[i];
            if (row < Mrows) {
                const float4* src = reinterpret_cast<const float4*>(
                    A + (size_t)row * DD + ch * 64 + cgA[i] * 8);
                pref[i * 2]     = src[0];
                pref[i * 2 + 1] = src[1];
            } else {
                pref[i * 2]     = make_float4(0.f, 0.f, 0.f, 0.f);
                pref[i * 2 + 1] = make_float4(0.f, 0.f, 0.f, 0.f);
            }
        }
    };
    auto storeA = [&](int s) {
#pragma unroll
        for (int i = 0; i < 2; i++) {
            float x[8];
            float4 v0 = pref[i * 2], v1 = pref[i * 2 + 1];
            x[0] = v0.x; x[1] = v0.y; x[2] = v0.z; x[3] = v0.w;
            x[4] = v1.x; x[5] = v1.y; x[6] = v1.z; x[7] = v1.w;
            unsigned short hi[8], lo[8];
#pragma unroll
            for (int j = 0; j < 8; j++) {
                __nv_bfloat16 h = __float2bfloat16(x[j]);
                __nv_bfloat16 l = __float2bfloat16(x[j] - __bfloat162float(h));
                hi[j] = *reinterpret_cast<unsigned short*>(&h);
                lo[j] = *reinterpret_cast<unsigned short*>(&l);
            }
            uint32_t off = s * 32768u + swz((uint32_t)rA[i], (uint32_t)cgA[i] * 16u);
            *reinterpret_cast<uint4*>(smem + off)         = *reinterpret_cast<uint4*>(hi);
            *reinterpret_cast<uint4*>(smem + 16384 + off) = *reinterpret_cast<uint4*>(lo);
        }
    };
    auto issueB = [&](int ch, int s) {
        const unsigned char* bh = Wp + (size_t)(ch * 2 + 0) * 32768;
        const unsigned char* bl = Wp + (size_t)(ch * 2 + 1) * 32768;
        uint32_t dh = sb + 65536u + (uint32_t)s * 65536u;
        uint32_t dl = dh + 32768u;
#pragma unroll
        for (int i = 0; i < 4; i++) {
            int idx = (tid + i * 512) * 16;
            CP_ASYNC16(dh + idx, bh + idx);
            CP_ASYNC16(dl + idx, bl + idx);
        }
        CP_COMMIT();
    };

    float c[2][8][4];
#pragma unroll
    for (int mt = 0; mt < 2; mt++)
#pragma unroll
        for (int nt = 0; nt < 8; nt++)
#pragma unroll
            for (int q = 0; q < 4; q++) c[mt][nt][q] = 0.f;

    issueA(0);
    issueB(0, 0);
    storeA(0);

    for (int ch = 0; ch < 4; ch++) {
        const int s = ch & 1;
        if (ch < 3) {
            issueA(ch + 1);
            issueB(ch + 1, s ^ 1);
            CP_WAIT(1);
        } else {
            CP_WAIT(0);
        }
        __syncthreads();

        const uint32_t aBase = sb + (uint32_t)s * 32768u;
        const uint32_t bBase = sb + 65536u + (uint32_t)s * 65536u;
#pragma unroll
        for (int ks = 0; ks < 4; ks++) {
            uint32_t ah[2][4], al[2][4];
#pragma unroll
            for (int mt = 0; mt < 2; mt++) {
                uint32_t row = (uint32_t)(warpM * 32 + mt * 16 + (lane & 7) + ((lane >> 3) & 1) * 8);
                uint32_t kb  = (uint32_t)(ks * 32 + ((lane >> 4) & 1) * 16);
                uint32_t addr = aBase + swz(row, kb);
                ldm_x4(addr,         ah[mt]);
                ldm_x4(addr + 16384, al[mt]);
            }
#pragma unroll
            for (int p = 0; p < 4; p++) {
                uint32_t nrow = (uint32_t)(warpN * 64 + p * 16 + (lane & 7) + ((lane >> 4) & 1) * 8);
                uint32_t kb   = (uint32_t)(ks * 32 + ((lane >> 3) & 1) * 16);
                uint32_t addr = bBase + swz(nrow, kb);
                uint32_t bh[4], bl[4];
                ldm_x4(addr,         bh);
                ldm_x4(addr + 32768, bl);
#pragma unroll
                for (int t = 0; t < 2; t++) {
#pragma unroll
                    for (int mt = 0; mt < 2; mt++) {
                        float* cc = c[mt][p * 2 + t];
                        mma_bf16(cc, ah[mt], bh + t * 2);
                        mma_bf16(cc, ah[mt], bl + t * 2);
                        mma_bf16(cc, al[mt], bh + t * 2);
                    }
                }
            }
        }
        if (ch < 3) storeA(s ^ 1);
        __syncthreads();
    }

    const int gid = lane >> 2, tig = lane & 3;
    float2* rb = reinterpret_cast<float2*>(smem);

#pragma unroll
    for (int mt = 0; mt < 2; mt++) {
        int r0 = rowBase + warpM * 32 + mt * 16 + gid;
        int r1 = r0 + 8;
        bool v0 = r0 < Mrows, v1 = r1 < Mrows;
#pragma unroll
        for (int nt = 0; nt < 8; nt++) {
            int col = warpN * 64 + nt * 8 + tig * 2;
            if (v0) *reinterpret_cast<float2*>(C + (size_t)r0 * DD + col)
                        = make_float2(c[mt][nt][0], c[mt][nt][1]);
            if (v1) *reinterpret_cast<float2*>(C + (size_t)r1 * DD + col)
                        = make_float2(c[mt][nt][2], c[mt][nt][3]);
        }
    }

    if (FLAGS & F_SNODE) {
#pragma unroll
        for (int mt = 0; mt < 2; mt++) {
            float s0 = 0.f, s1 = 0.f;
#pragma unroll
            for (int nt = 0; nt < 8; nt++) {
                int col = warpN * 64 + nt * 8 + tig * 2;
                float2 avv = *reinterpret_cast<const float2*>(av + col);
                s0 += c[mt][nt][0] * avv.x + c[mt][nt][1] * avv.y;
                s1 += c[mt][nt][2] * avv.x + c[mt][nt][3] * avv.y;
            }
#pragma unroll
            for (int o = 1; o < 4; o <<= 1) {
                s0 += __shfl_xor_sync(0xFFFFFFFFu, s0, o);
                s1 += __shfl_xor_sync(0xFFFFFFFFu, s1, o);
            }
            if (tig == 0) {
                int lr0 = warpM * 32 + mt * 16 + gid;
                rb[lr0 * 4 + warpN]       = make_float2(s0, 0.f);
                rb[(lr0 + 8) * 4 + warpN] = make_float2(s1, 0.f);
            }
        }
        __syncthreads();
        if (warpN == 0 && tig == 0) {
#pragma unroll
            for (int mt = 0; mt < 2; mt++) {
                int lr0 = warpM * 32 + mt * 16 + gid;
#pragma unroll
                for (int h = 0; h < 2; h++) {
                    int lr = lr0 + h * 8;
                    int row = rowBase + lr;
                    if (row < Mrows) {
                        snode[row] = rb[lr * 4 + 0].x + rb[lr * 4 + 1].x
                                   + rb[lr * 4 + 2].x + rb[lr * 4 + 3].x;
                    }
                }
            }
        }
    }
}

// ======== fused dual GEMM (+ fp16 mirror of obj2) ========
__global__ __launch_bounds__(512, 1)
void tgemm_dual(const float* __restrict__ A, const unsigned char* __restrict__ Wp1,
                const float* __restrict__ bias1, const float* __restrict__ R1,
                const float* __restrict__ lng1, const float* __restrict__ lnb1,
                const unsigned char* __restrict__ Wp2, const float* __restrict__ bias2,
                const float* __restrict__ lng2, const float* __restrict__ lnb2,
                float* __restrict__ C2, __half* __restrict__ C2h,
                const float* __restrict__ av,
                float* __restrict__ snode, int Mrows)
{
    extern __shared__ __align__(128) unsigned char smem[];
    const uint32_t sb = smem_to_u32(smem);
    const int tid = threadIdx.x, lane = tid & 31, wid = tid >> 5;
    const int warpM = wid >> 2, warpN = wid & 3;
    const int rowBase = blockIdx.x * 128;

    int rA[2], cgA[2];
#pragma unroll
    for (int i = 0; i < 2; i++) {
        int g = tid + i * 512;
        rA[i] = g >> 3; cgA[i] = g & 7;
    }
    float4 pref[4];

    auto issueA = [&](int ch) {
#pragma unroll
        for (int i = 0; i < 2; i++) {
            int row = rowBase + rA[i];
            if (row < Mrows) {
                const float4* src = reinterpret_cast<const float4*>(
                    A + (size_t)row * DD + ch * 64 + cgA[i] * 8);
                pref[i * 2]     = src[0];
                pref[i * 2 + 1] = src[1];
            } else {
                pref[i * 2]     = make_float4(0.f, 0.f, 0.f, 0.f);
                pref[i * 2 + 1] = make_float4(0.f, 0.f, 0.f, 0.f);
            }
        }
    };
    auto storeA = [&](int s) {
#pragma unroll
        for (int i = 0; i < 2; i++) {
            float x[8];
            float4 v0 = pref[i * 2], v1 = pref[i * 2 + 1];
            x[0] = v0.x; x[1] = v0.y; x[2] = v0.z; x[3] = v0.w;
            x[4] = v1.x; x[5] = v1.y; x[6] = v1.z; x[7] = v1.w;
            unsigned short hi[8], lo[8];
#pragma unroll
            for (int j = 0; j < 8; j++) {
                __nv_bfloat16 h = __float2bfloat16(x[j]);
                __nv_bfloat16 l = __float2bfloat16(x[j] - __bfloat162float(h));
                hi[j] = *reinterpret_cast<unsigned short*>(&h);
                lo[j] = *reinterpret_cast<unsigned short*>(&l);
            }
            uint32_t off = 131072u + s * 32768u + swz((uint32_t)rA[i], (uint32_t)cgA[i] * 16u);
            *reinterpret_cast<uint4*>(smem + off)         = *reinterpret_cast<uint4*>(hi);
            *reinterpret_cast<uint4*>(smem + 16384 + off) = *reinterpret_cast<uint4*>(lo);
        }
    };
    auto issueB1 = [&](int ch, int s) {
        const unsigned char* bh = Wp1 + (size_t)(ch * 2 + 0) * 32768;
        const unsigned char* bl = Wp1 + (size_t)(ch * 2 + 1) * 32768;
        uint32_t dh = sb + (uint32_t)s * 65536u;
        uint32_t dl = dh + 32768u;
#pragma unroll
        for (int i = 0; i < 4; i++) {
            int idx = (tid + i * 512) * 16;
            CP_ASYNC16(dh + idx, bh + idx);
            CP_ASYNC16(dl + idx, bl + idx);
        }
        CP_COMMIT();
    };
    auto issueB2 = [&](int ch) {
        const unsigned char* bh = Wp2 + (size_t)(ch * 2 + 0) * 32768;
        const unsigned char* bl = Wp2 + (size_t)(ch * 2 + 1) * 32768;
        uint32_t dh = sb + 131072u;
        uint32_t dl = dh + 32768u;
#pragma unroll
        for (int i = 0; i < 4; i++) {
            int idx = (tid + i * 512) * 16;
            CP_ASYNC16(dh + idx, bh + idx);
            CP_ASYNC16(dl + idx, bl + idx);
        }
        CP_COMMIT();
    };

    float c[2][8][4];
#pragma unroll
    for (int mt = 0; mt < 2; mt++)
#pragma unroll
        for (int nt = 0; nt < 8; nt++)
#pragma unroll
            for (int q = 0; q < 4; q++) c[mt][nt][q] = 0.f;

    // ---- phase 1 ----
    issueA(0);
    issueB1(0, 0);
    storeA(0);

    for (int ch = 0; ch < 4; ch++) {
        const int s = ch & 1;
        if (ch < 3) {
            issueA(ch + 1);
            issueB1(ch + 1, s ^ 1);
            CP_WAIT(1);
        } else {
            CP_WAIT(0);
        }
        __syncthreads();

        const uint32_t aBase = sb + 131072u + (uint32_t)s * 32768u;
        const uint32_t bBase = sb + (uint32_t)s * 65536u;
#pragma unroll
        for (int ks = 0; ks < 4; ks++) {
            uint32_t ah[2][4], al[2][4];
#pragma unroll
            for (int mt = 0; mt < 2; mt++) {
                uint32_t row = (uint32_t)(warpM * 32 + mt * 16 + (lane & 7) + ((lane >> 3) & 1) * 8);
                uint32_t kb  = (uint32_t)(ks * 32 + ((lane >> 4) & 1) * 16);
                uint32_t addr = aBase + swz(row, kb);
                ldm_x4(addr,         ah[mt]);
                ldm_x4(addr + 16384, al[mt]);
            }
#pragma unroll
            for (int p = 0; p < 4; p++) {
                uint32_t nrow = (uint32_t)(warpN * 64 + p * 16 + (lane & 7) + ((lane >> 4) & 1) * 8);
                uint32_t kb   = (uint32_t)(ks * 32 + ((lane >> 3) & 1) * 16);
                uint32_t addr = bBase + swz(nrow, kb);
                uint32_t bh[4], bl[4];
                ldm_x4(addr,         bh);
                ldm_x4(addr + 32768, bl);
#pragma unroll
                for (int t = 0; t < 2; t++) {
#pragma unroll
                    for (int mt = 0; mt < 2; mt++) {
                        float* cc = c[mt][p * 2 + t];
                        mma_bf16(cc, ah[mt], bh + t * 2);
                        mma_bf16(cc, ah[mt], bl + t * 2);
                        mma_bf16(cc, al[mt], bh + t * 2);
                    }
                }
            }
        }
        if (ch < 3) storeA(s ^ 1);
        __syncthreads();
    }

    // ---- epilogue 1 ----
    const int gid = lane >> 2, tig = lane & 3;
    float2* rb = reinterpret_cast<float2*>(smem + 131072);

#pragma unroll
    for (int mt = 0; mt < 2; mt++) {
        int r0 = rowBase + warpM * 32 + mt * 16 + gid;
        int r1 = r0 + 8;
        bool v0 = r0 < Mrows, v1 = r1 < Mrows;
#pragma unroll
        for (int nt = 0; nt < 8; nt++) {
            int col = warpN * 64 + nt * 8 + tig * 2;
            float2 bv = *reinterpret_cast<const float2*>(bias1 + col);
            float o0 = lrelu_f(c[mt][nt][0] + bv.x), o1 = lrelu_f(c[mt][nt][1] + bv.y);
            float o2 = lrelu_f(c[mt][nt][2] + bv.x), o3 = lrelu_f(c[mt][nt][3] + bv.y);
            if (v0) {
                float2 rv = *reinterpret_cast<const float2*>(R1 + (size_t)r0 * DD + col);
                o0 += rv.x; o1 += rv.y;
            }
            if (v1) {
                float2 rv = *reinterpret_cast<const float2*>(R1 + (size_t)r1 * DD + col);
                o2 += rv.x; o3 += rv.y;
            }
            c[mt][nt][0] = o0; c[mt][nt][1] = o1; c[mt][nt][2] = o2; c[mt][nt][3] = o3;
        }
    }
#pragma unroll
    for (int mt = 0; mt < 2; mt++) {
        float s0 = 0.f, q0 = 0.f, s1 = 0.f, q1 = 0.f;
#pragma unroll
        for (int nt = 0; nt < 8; nt++) {
            float o0 = c[mt][nt][0], o1 = c[mt][nt][1];
            float o2 = c[mt][nt][2], o3 = c[mt][nt][3];
            s0 += o0 + o1; q0 += o0 * o0 + o1 * o1;
            s1 += o2 + o3; q1 += o2 * o2 + o3 * o3;
        }
#pragma unroll
        for (int o = 1; o < 4; o <<= 1) {
            s0 += __shfl_xor_sync(0xFFFFFFFFu, s0, o);
            q0 += __shfl_xor_sync(0xFFFFFFFFu, q0, o);
            s1 += __shfl_xor_sync(0xFFFFFFFFu, s1, o);
            q1 += __shfl_xor_sync(0xFFFFFFFFu, q1, o);
        }
        if (tig == 0) {
            int lr0 = warpM * 32 + mt * 16 + gid;
            rb[lr0 * 4 + warpN]       = make_float2(s0, q0);
            rb[(lr0 + 8) * 4 + warpN] = make_float2(s1, q1);
        }
    }
    __syncthreads();
#pragma unroll
    for (int mt = 0; mt < 2; mt++) {
        int lr0 = warpM * 32 + mt * 16 + gid;
        int lr1 = lr0 + 8;
        float2 p00 = rb[lr0*4+0], p01 = rb[lr0*4+1], p02 = rb[lr0*4+2], p03 = rb[lr0*4+3];
        float2 p10 = rb[lr1*4+0], p11 = rb[lr1*4+1], p12 = rb[lr1*4+2], p13 = rb[lr1*4+3];
        float sum0 = p00.x + p01.x + p02.x + p03.x;
        float sq0  = p00.y + p01.y + p02.y + p03.y;
        float sum1 = p10.x + p11.x + p12.x + p13.x;
        float sq1  = p10.y + p11.y + p12.y + p13.y;
        float mean0 = sum0 * (1.f / 256.f);
        float rstd0 = rsqrtf(sq0 * (1.f / 256.f) - mean0 * mean0 + 1e-5f);
        float mean1 = sum1 * (1.f / 256.f);
        float rstd1 = rsqrtf(sq1 * (1.f / 256.f) - mean1 * mean1 + 1e-5f);
#pragma unroll
        for (int nt = 0; nt < 8; nt++) {
            int col = warpN * 64 + nt * 8 + tig * 2;
            float2 gv = *reinterpret_cast<const float2*>(lng1 + col);
            float2 bv = *reinterpret_cast<const float2*>(lnb1 + col);
            c[mt][nt][0] = (c[mt][nt][0] - mean0) * rstd0 * gv.x + bv.x;
            c[mt][nt][1] = (c[mt][nt][1] - mean0) * rstd0 * gv.y + bv.y;
            c[mt][nt][2] = (c[mt][nt][2] - mean1) * rstd1 * gv.x + bv.x;
            c[mt][nt][3] = (c[mt][nt][3] - mean1) * rstd1 * gv.y + bv.y;
        }
    }
    __syncthreads();

    // ---- store obj1 to A2 smem + issue B2 chunk 0 ----
    issueB2(0);
#pragma unroll
    for (int mt = 0; mt < 2; mt++) {
        uint32_t lr0 = (uint32_t)(warpM * 32 + mt * 16 + gid);
        uint32_t lr1 = lr0 + 8;
#pragma unroll
        for (int nt = 0; nt < 8; nt++) {
            uint32_t cb = (uint32_t)(warpN * 64 + nt * 8 + tig * 2) * 2u;
            float o0 = c[mt][nt][0], o1 = c[mt][nt][1];
            float o2 = c[mt][nt][2], o3 = c[mt][nt][3];
            __nv_bfloat16 h0 = __float2bfloat16(o0), h1 = __float2bfloat16(o1);
            __nv_bfloat16 h2 = __float2bfloat16(o2), h3 = __float2bfloat16(o3);
            __nv_bfloat16 l0 = __float2bfloat16(o0 - __bfloat162float(h0));
            __nv_bfloat16 l1 = __float2bfloat16(o1 - __bfloat162float(h1));
            __nv_bfloat16 l2 = __float2bfloat16(o2 - __bfloat162float(h2));
            __nv_bfloat16 l3 = __float2bfloat16(o3 - __bfloat162float(h3));
            uint32_t hp0 = ((uint32_t)*reinterpret_cast<unsigned short*>(&h1) << 16)
                         |  (uint32_t)*reinterpret_cast<unsigned short*>(&h0);
            uint32_t lp0 = ((uint32_t)*reinterpret_cast<unsigned short*>(&l1) << 16)
                         |  (uint32_t)*reinterpret_cast<unsigned short*>(&l0);
            uint32_t hp1 = ((uint32_t)*reinterpret_cast<unsigned short*>(&h3) << 16)
                         |  (uint32_t)*reinterpret_cast<unsigned short*>(&h2);
            uint32_t lp1 = ((uint32_t)*reinterpret_cast<unsigned short*>(&l3) << 16)
                         |  (uint32_t)*reinterpret_cast<unsigned short*>(&l2);
            *reinterpret_cast<uint32_t*>(smem + swz512(lr0, cb))           = hp0;
            *reinterpret_cast<uint32_t*>(smem + 65536u + swz512(lr0, cb))  = lp0;
            *reinterpret_cast<uint32_t*>(smem + swz512(lr1, cb))           = hp1;
            *reinterpret_cast<uint32_t*>(smem + 65536u + swz512(lr1, cb))  = lp1;
        }
    }
#pragma unroll
    for (int mt = 0; mt < 2; mt++)
#pragma unroll
        for (int nt = 0; nt < 8; nt++)
#pragma unroll
            for (int q = 0; q < 4; q++) c[mt][nt][q] = 0.f;
    __syncthreads();

    // ---- phase 2 ----
    for (int ch = 0; ch < 4; ch++) {
        CP_WAIT(0);
        __syncthreads();
        const uint32_t bBase = sb + 131072u;
#pragma unroll
        for (int ks = 0; ks < 4; ks++) {
            uint32_t ah[2][4], al[2][4];
#pragma unroll
            for (int mt = 0; mt < 2; mt++) {
                uint32_t row = (uint32_t)(warpM * 32 + mt * 16 + (lane & 7) + ((lane >> 3) & 1) * 8);
                uint32_t kb  = (uint32_t)(ch * 128 + ks * 32 + ((lane >> 4) & 1) * 16);
                uint32_t addr = sb + swz512(row, kb);
                ldm_x4(addr,          ah[mt]);
                ldm_x4(addr + 65536u, al[mt]);
            }
#pragma unroll
            for (int p = 0; p < 4; p++) {
                uint32_t nrow = (uint32_t)(warpN * 64 + p * 16 + (lane & 7) + ((lane >> 4) & 1) * 8);
                uint32_t kb   = (uint32_t)(ks * 32 + ((lane >> 3) & 1) * 16);
                uint32_t addr = bBase + swz(nrow, kb);
                uint32_t bh[4], bl[4];
                ldm_x4(addr,          bh);
                ldm_x4(addr + 32768u, bl);
#pragma unroll
                for (int t = 0; t < 2; t++) {
#pragma unroll
                    for (int mt = 0; mt < 2; mt++) {
                        float* cc = c[mt][p * 2 + t];
                        mma_bf16(cc, ah[mt], bh + t * 2);
                        mma_bf16(cc, ah[mt], bl + t * 2);
                        mma_bf16(cc, al[mt], bh + t * 2);
                    }
                }
            }
        }
        __syncthreads();
        if (ch < 3) issueB2(ch + 1);
    }

    // ---- epilogue 2 ----
#pragma unroll
    for (int mt = 0; mt < 2; mt++) {
        uint32_t lr0 = (uint32_t)(warpM * 32 + mt * 16 + gid);
        uint32_t lr1 = lr0 + 8;
#pragma unroll
        for (int nt = 0; nt < 8; nt++) {
            int col = warpN * 64 + nt * 8 + tig * 2;
            uint32_t cb = (uint32_t)col * 2u;
            float2 bv = *reinterpret_cast<const float2*>(bias2 + col);
            float o0 = lrelu_f(c[mt][nt][0] + bv.x), o1 = lrelu_f(c[mt][nt][1] + bv.y);
            float o2 = lrelu_f(c[mt][nt][2] + bv.x), o3 = lrelu_f(c[mt][nt][3] + bv.y);
            uint32_t hp0 = *reinterpret_cast<uint32_t*>(smem + swz512(lr0, cb));
            uint32_t lp0 = *reinterpret_cast<uint32_t*>(smem + 65536u + swz512(lr0, cb));
            uint32_t hp1 = *reinterpret_cast<uint32_t*>(smem + swz512(lr1, cb));
            uint32_t lp1 = *reinterpret_cast<uint32_t*>(smem + 65536u + swz512(lr1, cb));
            unsigned short u;
            u = (unsigned short)(hp0 & 0xFFFF);
            float r0a = __bfloat162float(*reinterpret_cast<__nv_bfloat16*>(&u));
            u = (unsigned short)(lp0 & 0xFFFF);
            r0a += __bfloat162float(*reinterpret_cast<__nv_bfloat16*>(&u));
            u = (unsigned short)(hp0 >> 16);
            float r0b = __bfloat162float(*reinterpret_cast<__nv_bfloat16*>(&u));
            u = (unsigned short)(lp0 >> 16);
            r0b += __bfloat162float(*reinterpret_cast<__nv_bfloat16*>(&u));
            u = (unsigned short)(hp1 & 0xFFFF);
            float r1a = __bfloat162float(*reinterpret_cast<__nv_bfloat16*>(&u));
            u = (unsigned short)(lp1 & 0xFFFF);
            r1a += __bfloat162float(*reinterpret_cast<__nv_bfloat16*>(&u));
            u = (unsigned short)(hp1 >> 16);
            float r1b = __bfloat162float(*reinterpret_cast<__nv_bfloat16*>(&u));
            u = (unsigned short)(lp1 >> 16);
            r1b += __bfloat162float(*reinterpret_cast<__nv_bfloat16*>(&u));
            c[mt][nt][0] = o0 + r0a; c[mt][nt][1] = o1 + r0b;
            c[mt][nt][2] = o2 + r1a; c[mt][nt][3] = o3 + r1b;
        }
    }
#pragma unroll
    for (int mt = 0; mt < 2; mt++) {
        float s0 = 0.f, q0 = 0.f, s1 = 0.f, q1 = 0.f;
#pragma unroll
        for (int nt = 0; nt < 8; nt++) {
            float o0 = c[mt][nt][0], o1 = c[mt][nt][1];
            float o2 = c[mt][nt][2], o3 = c[mt][nt][3];
            s0 += o0 + o1; q0 += o0 * o0 + o1 * o1;
            s1 += o2 + o3; q1 += o2 * o2 + o3 * o3;
        }
#pragma unroll
        for (int o = 1; o < 4; o <<= 1) {
            s0 += __shfl_xor_sync(0xFFFFFFFFu, s0, o);
            q0 += __shfl_xor_sync(0xFFFFFFFFu, q0, o);
            s1 += __shfl_xor_sync(0xFFFFFFFFu, s1, o);
            q1 += __shfl_xor_sync(0xFFFFFFFFu, q1, o);
        }
        if (tig == 0) {
            int lr0 = warpM * 32 + mt * 16 + gid;
            rb[lr0 * 4 + warpN]       = make_float2(s0, q0);
            rb[(lr0 + 8) * 4 + warpN] = make_float2(s1, q1);
        }
    }
    __syncthreads();
    float sd[2][2] = {{0.f, 0.f}, {0.f, 0.f}};
#pragma unroll
    for (int mt = 0; mt < 2; mt++) {
        int lr0 = warpM * 32 + mt * 16 + gid;
        int lr1 = lr0 + 8;
        float2 p00 = rb[lr0*4+0], p01 = rb[lr0*4+1], p02 = rb[lr0*4+2], p03 = rb[lr0*4+3];
        float2 p10 = rb[lr1*4+0], p11 = rb[lr1*4+1], p12 = rb[lr1*4+2], p13 = rb[lr1*4+3];
        float sum0 = p00.x + p01.x + p02.x + p03.x;
        float sq0  = p00.y + p01.y + p02.y + p03.y;
        float sum1 = p10.x + p11.x + p12.x + p13.x;
        float sq1  = p10.y + p11.y + p12.y + p13.y;
        float mean0 = sum0 * (1.f / 256.f);
        float rstd0 = rsqrtf(sq0 * (1.f / 256.f) - mean0 * mean0 + 1e-5f);
        float mean1 = sum1 * (1.f / 256.f);
        float rstd1 = rsqrtf(sq1 * (1.f / 256.f) - mean1 * mean1 + 1e-5f);
        int r0 = rowBase + lr0, r1 = rowBase + lr1;
        bool v0 = r0 < Mrows, v1 = r1 < Mrows;
#pragma unroll
        for (int nt = 0; nt < 8; nt++) {
            int col = warpN * 64 + nt * 8 + tig * 2;
            float2 gv = *reinterpret_cast<const float2*>(lng2 + col);
            float2 bv = *reinterpret_cast<const float2*>(lnb2 + col);
            float o0 = (c[mt][nt][0] - mean0) * rstd0 * gv.x + bv.x;
            float o1 = (c[mt][nt][1] - mean0) * rstd0 * gv.y + bv.y;
            float o2 = (c[mt][nt][2] - mean1) * rstd1 * gv.x + bv.x;
            float o3 = (c[mt][nt][3] - mean1) * rstd1 * gv.y + bv.y;
            if (v0) {
                *reinterpret_cast<float2*>(C2 + (size_t)r0 * DD + col) = make_float2(o0, o1);
                *reinterpret_cast<__half2*>(C2h + (size_t)r0 * DD + col) = __floats2half2_rn(o0, o1);
            }
            if (v1) {
                *reinterpret_cast<float2*>(C2 + (size_t)r1 * DD + col) = make_float2(o2, o3);
                *reinterpret_cast<__half2*>(C2h + (size_t)r1 * DD + col) = __floats2half2_rn(o2, o3);
            }
            float2 avv = *reinterpret_cast<const float2*>(av + col);
            sd[mt][0] += o0 * avv.x + o1 * avv.y;
            sd[mt][1] += o2 * avv.x + o3 * avv.y;
        }
    }
    __syncthreads();
#pragma unroll
    for (int mt = 0; mt < 2; mt++) {
        float s0 = sd[mt][0], s1 = sd[mt][1];
#pragma unroll
        for (int o = 1; o < 4; o <<= 1) {
            s0 += __shfl_xor_sync(0xFFFFFFFFu, s0, o);
            s1 += __shfl_xor_sync(0xFFFFFFFFu, s1, o);
        }
        if (tig == 0) {
            int lr0 = warpM * 32 + mt * 16 + gid;
            rb[lr0 * 4 + warpN]       = make_float2(s0, 0.f);
            rb[(lr0 + 8) * 4 + warpN] = make_float2(s1, 0.f);
        }
    }
    __syncthreads();
    if (warpN == 0 && tig == 0) {
#pragma unroll
        for (int mt = 0; mt < 2; mt++) {
            int lr0 = warpM * 32 + mt * 16 + gid;
#pragma unroll
            for (int h = 0; h < 2; h++) {
                int lr = lr0 + h * 8;
                int row = rowBase + lr;
                if (row < Mrows) {
                    snode[row] = rb[lr * 4 + 0].x + rb[lr * 4 + 1].x
                               + rb[lr * 4 + 2].x + rb[lr * 4 + 3].x;
                }
            }
        }
    }
}

// -------- edge gather from fp16 mirror --------
__global__ void edge_gatherX(const __half* __restrict__ Xh, const int* __restrict__ nodeE,
                             const int* __restrict__ offE, const int* __restrict__ cntE,
                             float* __restrict__ Xmean, int act, int nEdges)
{
    int ed = blockIdx.x * 8 + (threadIdx.x >> 5);
    if (ed >= nEdges) return;
    int lane = threadIdx.x & 31;
    int start = offE[ed], deg = cntE[ed];
    float acc[8] = {0.f, 0.f, 0.f, 0.f, 0.f, 0.f, 0.f, 0.f};
    for (int base = 0; base < deg; base += 32) {
        int m = min(32, deg - base);
        int src = 0;
        if (lane < m) src = nodeE[start + base + lane];
        for (int i = 0; i < m; i++) {
            int node = __shfl_sync(0xFFFFFFFFu, src, i);
            uint4 v = *reinterpret_cast<const uint4*>(Xh + (size_t)node * DD + lane * 8);
            float f[8];
            half8_to_f(v, f, act);
#pragma unroll
            for (int j = 0; j < 8; j++) acc[j] += f[j];
        }
    }
    float inv = 1.f / fmaxf((float)deg, 1.f);
    float4* op = reinterpret_cast<float4*>(Xmean + (size_t)ed * DD + lane * 8);
    op[0] = make_float4(acc[0] * inv, acc[1] * inv, acc[2] * inv, acc[3] * inv);
    op[1] = make_float4(acc[4] * inv, acc[5] * inv, acc[6] * inv, acc[7] * inv);
}

// -------- fused per-node softmax + aggregate (+ optional fp16 mirror out) --------
__global__ void node_attn_agg(const float* __restrict__ ef, const float* __restrict__ sn,
                              const float* __restrict__ se, const int* __restrict__ edN,
                              const int* __restrict__ permN, const int* __restrict__ offN,
                              const int* __restrict__ cntN, float* __restrict__ attn,
                              float* __restrict__ out, __half* __restrict__ outHalf,
                              const float* __restrict__ av,
                              float* __restrict__ snodeOut, int doLrelu, int nNodes)
{
    int n = blockIdx.x * 8 + (threadIdx.x >> 5);
    if (n >= nNodes) return;
    int lane = threadIdx.x & 31;
    int st = offN[n], deg = cntN[n];
    float4 a0 = make_float4(0.f,0.f,0.f,0.f), a1 = a0;

    if (deg > 0) {
        float s0 = sn[n];
        if (deg <= 32) {
            int ed = 0;
            float sc = -3.4e38f;
            if (lane < deg) {
                ed = edN[st + lane];
                sc = lrelu_f(s0 + se[ed]);
            }
            float mx = sc;
#pragma unroll
            for (int o = 16; o; o >>= 1) mx = fmaxf(mx, __shfl_xor_sync(0xFFFFFFFFu, mx, o));
            float e = (lane < deg) ? expf(sc - mx) : 0.f;
            float z = e;
#pragma unroll
            for (int o = 16; o; o >>= 1) z += __shfl_xor_sync(0xFFFFFFFFu, z, o);
            float w = e / fmaxf(z, 1e-9f);
            if (lane < deg && attn != nullptr) attn[permN[st + lane]] = w;
            for (int i = 0; i < deg; i++) {
                int e_   = __shfl_sync(0xFFFFFFFFu, ed, i);
                float w_ = __shfl_sync(0xFFFFFFFFu, w, i);
                const float4* rp = reinterpret_cast<const float4*>(ef + (size_t)e_ * DD + lane * 8);
                float4 v0 = rp[0], v1 = rp[1];
                a0.x += w_*v0.x; a0.y += w_*v0.y; a0.z += w_*v0.z; a0.w += w_*v0.w;
                a1.x += w_*v1.x; a1.y += w_*v1.y; a1.z += w_*v1.z; a1.w += w_*v1.w;
            }
        } else {
            float mx = -3.4e38f;
            for (int base = 0; base < deg; base += 32) {
                float sc = -3.4e38f;
                if (base + lane < deg)
                    sc = lrelu_f(s0 + se[edN[st + base + lane]]);
                mx = fmaxf(mx, sc);
            }
#pragma unroll
            for (int o = 16; o; o >>= 1) mx = fmaxf(mx, __shfl_xor_sync(0xFFFFFFFFu, mx, o));
            float z = 0.f;
            for (int base = 0; base < deg; base += 32) {
                if (base + lane < deg)
                    z += expf(lrelu_f(s0 + se[edN[st + base + lane]]) - mx);
            }
#pragma unroll
            for (int o = 16; o; o >>= 1) z += __shfl_xor_sync(0xFFFFFFFFu, z, o);
            float invz = 1.f / fmaxf(z, 1e-9f);
            for (int base = 0; base < deg; base += 32) {
                int m = min(32, deg - base);
                int ed = 0; float w = 0.f;
                if (lane < m) {
                    ed = edN[st + base + lane];
                    w = expf(lrelu_f(s0 + se[ed]) - mx) * invz;
                    if (attn != nullptr) attn[permN[st + base + lane]] = w;
                }
                for (int i = 0; i < m; i++) {
                    int e_   = __shfl_sync(0xFFFFFFFFu, ed, i);
                    float w_ = __shfl_sync(0xFFFFFFFFu, w, i);
                    const float4* rp = reinterpret_cast<const float4*>(ef + (size_t)e_ * DD + lane * 8);
                    float4 v0 = rp[0], v1 = rp[1];
                    a0.x += w_*v0.x; a0.y += w_*v0.y; a0.z += w_*v0.z; a0.w += w_*v0.w;
                    a1.x += w_*v1.x; a1.y += w_*v1.y; a1.z += w_*v1.z; a1.w += w_*v1.w;
                }
            }
        }
    }
    if (snodeOut != nullptr) {
        const float4* ap = reinterpret_cast<const float4*>(av + lane * 8);
        float4 w0 = ap[0], w1 = ap[1];
        float d = lrelu_f(a0.x)*w0.x + lrelu_f(a0.y)*w0.y + lrelu_f(a0.z)*w0.z + lrelu_f(a0.w)*w0.w
                + lrelu_f(a1.x)*w1.x + lrelu_f(a1.y)*w1.y + lrelu_f(a1.z)*w1.z + lrelu_f(a1.w)*w1.w;
#pragma unroll
        for (int o = 16; o; o >>= 1) d += __shfl_xor_sync(0xFFFFFFFFu, d, o);
        if (lane == 0) snodeOut[n] = d;
    }
    if (doLrelu) {
        a0.x = lrelu_f(a0.x); a0.y = lrelu_f(a0.y); a0.z = lrelu_f(a0.z); a0.w = lrelu_f(a0.w);
        a1.x = lrelu_f(a1.x); a1.y = lrelu_f(a1.y); a1.z = lrelu_f(a1.z); a1.w = lrelu_f(a1.w);
    }
    float4* op = reinterpret_cast<float4*>(out + (size_t)n * DD + lane * 8);
    op[0] = a0; op[1] = a1;
    if (outHalf != nullptr) {
        uint4 hv;
        __half2* hp = reinterpret_cast<__half2*>(&hv);
        hp[0] = __floats2half2_rn(a0.x, a0.y);
        hp[1] = __floats2half2_rn(a0.z, a0.w);
        hp[2] = __floats2half2_rn(a1.x, a1.y);
        hp[3] = __floats2half2_rn(a1.z, a1.w);
        *reinterpret_cast<uint4*>(outHalf + (size_t)n * DD + lane * 8) = hv;
    }
}

// -------- object message gather (fp16 mirror source) --------
__global__ void obj_gather(const __half* __restrict__ evh, const int* __restrict__ srcO,
                           const int* __restrict__ offO, const int* __restrict__ cntO,
                           float* __restrict__ msg, int nObj)
{
    int o = blockIdx.x * 8 + (threadIdx.x >> 5);
    if (o >= nObj) return;
    int lane = threadIdx.x & 31;
    int start = offO[o], deg = cntO[o];
    float acc[8] = {0.f, 0.f, 0.f, 0.f, 0.f, 0.f, 0.f, 0.f};
    for (int base = 0; base < deg; base += 32) {
        int m = min(32, deg - base);
        int src = 0;
        if (lane < m) src = srcO[start + base + lane];
        for (int i = 0; i < m; i++) {
            int row = __shfl_sync(0xFFFFFFFFu, src, i);
            uint4 v = *reinterpret_cast<const uint4*>(evh + (size_t)row * DD + lane * 8);
            float f[8];
            half8_to_f(v, f, 0);
#pragma unroll
            for (int j = 0; j < 8; j++) acc[j] += f[j];
        }
    }
    float4* op = reinterpret_cast<float4*>(msg + (size_t)o * DD + lane * 8);
    op[0] = make_float4(acc[0], acc[1], acc[2], acc[3]);
    op[1] = make_float4(acc[4], acc[5], acc[6], acc[7]);
}

// ----------------- host orchestration -----------------
struct Ptrs {
    float *X, *obj, *msg, *H, *ef, *snode, *sedge, *wav1, *wav2;
    __half *Xh, *Hh;
    unsigned char* wp;
    int *cntE, *offE, *nodeE, *cntN, *offN, *permN, *edN, *cntO, *offO, *srcO;
};

static void get_ptrs(Ptrs& p) {
    cudaGetSymbolAddress((void**)&p.X,     g_X);
    cudaGetSymbolAddress((void**)&p.Xh,    g_Xh);
    cudaGetSymbolAddress((void**)&p.obj,   g_obj);
    cudaGetSymbolAddress((void**)&p.msg,   g_msg);
    cudaGetSymbolAddress((void**)&p.H,     g_H);
    cudaGetSymbolAddress((void**)&p.Hh,    g_Hh);
    cudaGetSymbolAddress((void**)&p.ef,    g_ef);
    cudaGetSymbolAddress((void**)&p.snode, g_snode);
    cudaGetSymbolAddress((void**)&p.sedge, g_sedge);
    cudaGetSymbolAddress((void**)&p.wav1,  g_wav1);
    cudaGetSymbolAddress((void**)&p.wav2,  g_wav2);
    cudaGetSymbolAddress((void**)&p.wp,    g_Wprep);
    cudaGetSymbolAddress((void**)&p.cntE,  g_cntE);
    cudaGetSymbolAddress((void**)&p.offE,  g_offE);
    cudaGetSymbolAddress((void**)&p.nodeE, g_nodeE);
    cudaGetSymbolAddress((void**)&p.cntN,  g_cntN);
    cudaGetSymbolAddress((void**)&p.offN,  g_offN);
    cudaGetSymbolAddress((void**)&p.permN, g_permN);
    cudaGetSymbolAddress((void**)&p.edN,   g_edN);
    cudaGetSymbolAddress((void**)&p.cntO,  g_cntO);
    cudaGetSymbolAddress((void**)&p.offO,  g_offO);
    cudaGetSymbolAddress((void**)&p.srcO,  g_srcO);
}

extern "C" void kernel_launch(void* const* d_in, const int* in_sizes, int n_in,
                              void* d_out, int out_size)
{
    const float* object_X = (const float*)d_in[0];
    const float* event_X  = (const float*)d_in[1];
    const float* Wo = (const float*)d_in[2];  const float* bo  = (const float*)d_in[3];
    const float* go = (const float*)d_in[4];  const float* bon = (const float*)d_in[5];
    const float* We = (const float*)d_in[6];  const float* be  = (const float*)d_in[7];
    const float* ge = (const float*)d_in[8];  const float* ben = (const float*)d_in[9];
    const float* Wu = (const float*)d_in[10]; const float* bu  = (const float*)d_in[11];
    const float* Wl = (const float*)d_in[12]; const float* bl  = (const float*)d_in[13];
    const float* g1 = (const float*)d_in[14]; const float* b1  = (const float*)d_in[15];
    const float* g2 = (const float*)d_in[16]; const float* b2  = (const float*)d_in[17];
    const float* Wh1 = (const float*)d_in[18]; const float* ah1 = (const float*)d_in[19];
    const float* Wh2 = (const float*)d_in[20]; const float* ah2 = (const float*)d_in[21];
    const int* oe_ev   = (const int*)d_in[22];
    const int* oe_obj  = (const int*)d_in[23];
    const int* hg_node = (const int*)d_in[24];
    const int* hg_edge = (const int*)d_in[25];

    Ptrs p; get_ptrs(p);

    static cudaStream_t s2 = nullptr;
    static cudaEvent_t evFork = nullptr, evJoin = nullptr;
    if (s2 == nullptr) {
        cudaStreamCreateWithFlags(&s2, cudaStreamNonBlocking);
        cudaEventCreateWithFlags(&evFork, cudaEventDisableTiming);
        cudaEventCreateWithFlags(&evJoin, cudaEventDisableTiming);
    }

    // ---- fork: CSR build on side stream, overlapped with weight prep + proj GEMM ----
    cudaEventRecord(evFork, 0);
    cudaStreamWaitEvent(s2, evFork, 0);
    zero_misc<<<(2 * (NE + NN + NO) + 255) / 256, 256, 0, s2>>>();
    count_all<<<(2 * E2N + E1N + 255) / 256, 256, 0, s2>>>(hg_edge, hg_node, oe_obj);
    scan_all<<<NBT, 1024, 0, s2>>>();
    scan_small3<<<1, 32, 0, s2>>>();
    add_off_all<<<(NE + NN + NO + 255) / 256, 256, 0, s2>>>();
    fill_all<<<(2 * E2N + E1N + 255) / 256, 256, 0, s2>>>(hg_edge, hg_node, oe_obj, oe_ev);
    cudaEventRecord(evJoin, s2);

    // ---- main stream: weight prep + projections ----
    prep_w<<<dim3(32, 6), 256>>>(We, Wo, Wu, Wl, Wh1, Wh2);
    prep_wav2<<<dim3((DD + 7) / 8, 2), 256>>>(Wh1, ah1, Wh2, ah2, p.wav1, p.wav2);

    const unsigned char *wpe = p.wp, *wpo = p.wp + 262144, *wpu = p.wp + 2 * 262144,
                        *wpl = p.wp + 3 * 262144, *wph1 = p.wp + 4 * 262144,
                        *wph2 = p.wp + 5 * 262144;

    cudaFuncSetAttribute(proj_gemm, cudaFuncAttributeMaxDynamicSharedMemorySize, SMEM_SZ);
    int nb0 = (NE + 127) / 128, nb1 = (NO + 127) / 128;
    proj_gemm<<<nb0 + nb1, 512, SMEM_SZ>>>(
        event_X, wpe, be, ge, ben, p.X, p.Xh, p.wav1, p.snode, NE, nb0,
        object_X, wpo, bo, go, bon, p.obj, NO);

    // ---- join: CSR must be ready before gathers ----
    cudaStreamWaitEvent(0, evJoin, 0);

    // 3) msg = segment_sum(ev[oe_ev], oe_obj)  (from fp16 mirror)
    obj_gather<<<(NO + 7) / 8, 256>>>(p.Xh, p.srcO, p.offO, p.cntO, p.msg, NO);

    // 4+5) fused dual GEMM -> X[NE:NN) (+fp16 mirror) + snode for obj rows
    cudaFuncSetAttribute(tgemm_dual, cudaFuncAttributeMaxDynamicSharedMemorySize, SMEM_SZ);
    tgemm_dual<<<(NO + 127) / 128, 512, SMEM_SZ>>>(p.msg, wpu, bu, p.obj, g1, b1,
                                                   wpl, bl, g2, b2,
                                                   p.X + (size_t)NE * DD,
                                                   p.Xh + (size_t)NE * DD,
                                                   p.wav1, p.snode + NE, NO);

    // 6) HGNN layer 1 -> H (+fp16 mirror); snode2 fused into node_attn_agg
    cudaFuncSetAttribute(tgemm256<F_SNODE>, cudaFuncAttributeMaxDynamicSharedMemorySize, SMEM_SZ);
    edge_gatherX<<<(NE + 7) / 8, 256>>>(p.Xh, p.nodeE, p.offE, p.cntE, p.msg, 0, NE);
    tgemm256<F_SNODE><<<(NE + 127) / 128, 512, SMEM_SZ>>>(p.msg, wph1, ah1 + DD, p.ef, p.sedge, NE);
    node_attn_agg<<<(NN + 7) / 8, 256>>>(p.ef, p.snode, p.sedge, p.edN,
                                         p.permN, p.offN, p.cntN,
                                         nullptr, p.H, p.Hh, p.wav2, p.snode, 0, NN);

    // 7) HGNN layer 2 -> d_out
    float* out = (float*)d_out;
    edge_gatherX<<<(NE + 7) / 8, 256>>>(p.Hh, p.nodeE, p.offE, p.cntE, p.msg, 1, NE);
    tgemm256<F_SNODE><<<(NE + 127) / 128, 512, SMEM_SZ>>>(p.msg, wph2, ah2 + DD, p.ef, p.sedge, NE);
    node_attn_agg<<<(NN + 7) / 8, 256>>>(p.ef, p.snode, p.sedge, p.edN,
                                         p.permN, p.offN, p.cntN,
                                         out + (size_t)NN * DD, out, nullptr, nullptr, nullptr, 1, NN);
}

// round 17
// speedup vs baseline: 1.0835x; 1.0255x over previous
#include <cuda_runtime.h>
#include <cuda_bf16.h>
#include <cuda_fp16.h>
#include <cstdint>

#define DD 256
static const int NE  = 50000;
static const int NO  = 100000;
static const int NN  = 150000;
static const int E1N = 400000;
static const int E2N = 800000;

// -------- device scratch --------
__device__ float    g_X  [(size_t)NN * DD];
__device__ __half   g_Xh [(size_t)NN * DD];
__device__ float    g_obj[(size_t)NO * DD];
__device__ float    g_msg[(size_t)NO * DD];
__device__ float    g_H  [(size_t)NN * DD];
__device__ __half   g_Hh [(size_t)NN * DD];
__device__ __half   g_efh[(size_t)NE * DD];   // ef stored fp16-only
__device__ float    g_snode[NN];
__device__ float    g_sedge[NE];
__device__ float    g_wav1[DD];
__device__ float    g_wav2[DD];
__device__ unsigned char g_Wprep[6 * 4 * 2 * 256 * 128];
// CSR structures (value-direct)
__device__ int g_cntE[NE],  g_offE[NE],  g_nodeE[E2N];
__device__ int g_cntN[NN],  g_offN[NN],  g_permN[E2N], g_edN[E2N];
__device__ int g_cntO[NO],  g_offO[NO],  g_srcO[E1N];
__device__ int g_cur[NE + NN + NO];
__device__ int g_bsum[512];

static const int NBE = (NE + 1023) / 1024;
static const int NBN = (NN + 1023) / 1024;
static const int NBO = (NO + 1023) / 1024;
static const int NBT = NBE + NBN + NBO;

// -------- helpers --------
__device__ __forceinline__ float lrelu_f(float x) { return x >= 0.f ? x : 0.2f * x; }

__device__ __forceinline__ uint32_t smem_to_u32(const void* p) {
    uint32_t a;
    asm("{ .reg .u64 t; cvta.to.shared.u64 t, %1; cvt.u32.u64 %0, t; }" : "=r"(a) : "l"(p));
    return a;
}
__device__ __forceinline__ void ldm_x4(uint32_t addr, uint32_t* r) {
    asm volatile("ldmatrix.sync.aligned.m8n8.x4.shared.b16 {%0,%1,%2,%3}, [%4];"
                 : "=r"(r[0]), "=r"(r[1]), "=r"(r[2]), "=r"(r[3]) : "r"(addr));
}
__device__ __forceinline__ void mma_bf16(float* c, const uint32_t* a, const uint32_t* b) {
    asm volatile("mma.sync.aligned.m16n8k16.row.col.f32.bf16.bf16.f32 "
                 "{%0,%1,%2,%3}, {%4,%5,%6,%7}, {%8,%9}, {%0,%1,%2,%3};"
                 : "+f"(c[0]), "+f"(c[1]), "+f"(c[2]), "+f"(c[3])
                 : "r"(a[0]), "r"(a[1]), "r"(a[2]), "r"(a[3]), "r"(b[0]), "r"(b[1]));
}
__device__ __forceinline__ uint32_t swz(uint32_t row, uint32_t cb) {
    return row * 128u + (cb ^ ((row & 7u) << 4));
}
__device__ __forceinline__ uint32_t swz512(uint32_t row, uint32_t cb) {
    return row * 512u + (cb ^ ((row & 7u) << 4));
}
#define CP_ASYNC16(dst, src) \
    asm volatile("cp.async.cg.shared.global [%0], [%1], 16;" :: "r"(dst), "l"(src) : "memory")
#define CP_COMMIT() asm volatile("cp.async.commit_group;" ::: "memory")
#define CP_WAIT(n)  asm volatile("cp.async.wait_group %0;" :: "n"(n) : "memory")

enum { F_SNODE = 16 };

__device__ __forceinline__ void half8_to_f(uint4 v, float* f, int act) {
    const __half2* hp = reinterpret_cast<const __half2*>(&v);
#pragma unroll
    for (int i = 0; i < 4; i++) {
        float2 t = __half22float2(hp[i]);
        f[i * 2]     = act ? lrelu_f(t.x) : t.x;
        f[i * 2 + 1] = act ? lrelu_f(t.y) : t.y;
    }
}

// ======== condensed CSR build ========
__global__ void zero_misc()
{
    int g = blockIdx.x * blockDim.x + threadIdx.x;
    if (g < NE) g_cntE[g] = 0;
    else if (g < NE + NN) g_cntN[g - NE] = 0;
    else if (g < NE + NN + NO) g_cntO[g - NE - NN] = 0;
    int h = g - (NE + NN + NO);
    if (h >= 0 && h < NE + NN + NO) g_cur[h] = 0;
}
__global__ void count_all(const int* __restrict__ he, const int* __restrict__ hn,
                          const int* __restrict__ oo)
{
    int t = blockIdx.x * blockDim.x + threadIdx.x;
    if (t < E2N) atomicAdd(&g_cntE[he[t]], 1);
    else if (t < 2 * E2N) atomicAdd(&g_cntN[hn[t - E2N]], 1);
    else if (t < 2 * E2N + E1N) atomicAdd(&g_cntO[oo[t - 2 * E2N]], 1);
}
__global__ void scan_all()
{
    __shared__ int sh[1024];
    int b = blockIdx.x;
    const int* cnt; int* off; int nseg; int lb;
    if (b < NBE)            { cnt = g_cntE; off = g_offE; nseg = NE; lb = b; }
    else if (b < NBE + NBN) { cnt = g_cntN; off = g_offN; nseg = NN; lb = b - NBE; }
    else                    { cnt = g_cntO; off = g_offO; nseg = NO; lb = b - NBE - NBN; }
    int g = lb * 1024 + threadIdx.x;
    int v = (g < nseg) ? cnt[g] : 0;
    sh[threadIdx.x] = v;
    __syncthreads();
#pragma unroll
    for (int o = 1; o < 1024; o <<= 1) {
        int t = (threadIdx.x >= o) ? sh[threadIdx.x - o] : 0;
        __syncthreads();
        sh[threadIdx.x] += t;
        __syncthreads();
    }
    if (g < nseg) off[g] = sh[threadIdx.x] - v;
    if (threadIdx.x == 1023) g_bsum[b] = sh[1023];
}
__global__ void scan_small3()
{
    int t = threadIdx.x;
    int s, e;
    if (t == 0)      { s = 0;          e = NBE; }
    else if (t == 1) { s = NBE;        e = NBE + NBN; }
    else if (t == 2) { s = NBE + NBN;  e = NBT; }
    else return;
    int run = 0;
    for (int i = s; i < e; i++) { int v = g_bsum[i]; g_bsum[i] = run; run += v; }
}
__global__ void add_off_all()
{
    int g = blockIdx.x * blockDim.x + threadIdx.x;
    if (g < NE) g_offE[g] += g_bsum[g >> 10];
    else if (g < NE + NN) {
        int l = g - NE; g_offN[l] += g_bsum[NBE + (l >> 10)];
    } else if (g < NE + NN + NO) {
        int l = g - NE - NN; g_offO[l] += g_bsum[NBE + NBN + (l >> 10)];
    }
}
__global__ void fill_all(const int* __restrict__ he, const int* __restrict__ hn,
                         const int* __restrict__ oo, const int* __restrict__ oev)
{
    int t = blockIdx.x * blockDim.x + threadIdx.x;
    if (t < E2N) {
        int s = he[t];
        int pos = g_offE[s] + atomicAdd(&g_cur[s], 1);
        g_nodeE[pos] = hn[t];
    } else if (t < 2 * E2N) {
        int e = t - E2N;
        int s = hn[e];
        int pos = g_offN[s] + atomicAdd(&g_cur[NE + s], 1);
        g_permN[pos] = e;
        g_edN[pos]   = he[e];
    } else if (t < 2 * E2N + E1N) {
        int e = t - 2 * E2N;
        int s = oo[e];
        int pos = g_offO[s] + atomicAdd(&g_cur[NE + NN + s], 1);
        g_srcO[pos] = oev[e];
    }
}

// -------- weight prep --------
__global__ void prep_w(const float* W0, const float* W1, const float* W2,
                       const float* W3, const float* W4, const float* W5)
{
    const float* Ws[6] = {W0, W1, W2, W3, W4, W5};
    const float* W = Ws[blockIdx.y];
    unsigned char* base = g_Wprep + (size_t)blockIdx.y * 262144;
    int g = blockIdx.x * 256 + threadIdx.x;
    int n = g >> 5, kg = g & 31, k0 = kg * 8;
    unsigned short hi[8], lo[8];
#pragma unroll
    for (int i = 0; i < 8; i++) {
        float x = W[(size_t)(k0 + i) * DD + n];
        __nv_bfloat16 h = __float2bfloat16(x);
        __nv_bfloat16 l = __float2bfloat16(x - __bfloat162float(h));
        hi[i] = *reinterpret_cast<unsigned short*>(&h);
        lo[i] = *reinterpret_cast<unsigned short*>(&l);
    }
    int chunk = k0 >> 6, kc = k0 & 63;
    uint32_t off = (uint32_t)n * 128u + (((uint32_t)kc * 2u) ^ (((uint32_t)n & 7u) << 4));
    *reinterpret_cast<uint4*>(base + (size_t)(chunk * 2 + 0) * 32768 + off) =
        *reinterpret_cast<uint4*>(hi);
    *reinterpret_cast<uint4*>(base + (size_t)(chunk * 2 + 1) * 32768 + off) =
        *reinterpret_cast<uint4*>(lo);
}

__global__ void prep_wav2(const float* __restrict__ W1, const float* __restrict__ a1,
                          const float* __restrict__ W2, const float* __restrict__ a2,
                          float* __restrict__ w1, float* __restrict__ w2)
{
    const float* W = (blockIdx.y == 0) ? W1 : W2;
    const float* a = (blockIdx.y == 0) ? a1 : a2;
    float* w = (blockIdx.y == 0) ? w1 : w2;
    int k = blockIdx.x * 8 + (threadIdx.x >> 5);
    if (k >= DD) return;
    int lane = threadIdx.x & 31;
    const float4* rp = reinterpret_cast<const float4*>(W + (size_t)k * DD);
    const float4* ap = reinterpret_cast<const float4*>(a);
    float4 v0 = rp[lane], v1 = rp[lane + 32];
    float4 a0 = ap[lane], a1v = ap[lane + 32];
    float d = v0.x*a0.x + v0.y*a0.y + v0.z*a0.z + v0.w*a0.w
            + v1.x*a1v.x + v1.y*a1v.y + v1.z*a1v.z + v1.w*a1v.w;
#pragma unroll
    for (int o = 16; o; o >>= 1) d += __shfl_xor_sync(0xFFFFFFFFu, d, o);
    if (lane == 0) w[k] = d;
}

static const int SMEM_SZ = 196608;

// ======== combined projection GEMM (+ fp16 mirror write for job0) ========
__global__ __launch_bounds__(512, 1)
void proj_gemm(const float* __restrict__ A0, const unsigned char* __restrict__ Wp0,
               const float* __restrict__ bias0, const float* __restrict__ lng0,
               const float* __restrict__ lnb0, float* __restrict__ C0,
               __half* __restrict__ C0h,
               const float* __restrict__ av0, float* __restrict__ snode0, int M0, int nb0,
               const float* __restrict__ A1, const unsigned char* __restrict__ Wp1,
               const float* __restrict__ bias1, const float* __restrict__ lng1,
               const float* __restrict__ lnb1, float* __restrict__ C1, int M1)
{
    extern __shared__ __align__(128) unsigned char smem[];
    const uint32_t sb = smem_to_u32(smem);
    const int tid = threadIdx.x, lane = tid & 31, wid = tid >> 5;
    const int warpM = wid >> 2, warpN = wid & 3;

    const float* A; const unsigned char* Wp; const float* bias;
    const float* lng; const float* lnb; float* C; __half* Ch;
    const float* av; float* snode; int Mrows, rowBase;
    if ((int)blockIdx.x < nb0) {
        A = A0; Wp = Wp0; bias = bias0; lng = lng0; lnb = lnb0; C = C0; Ch = C0h;
        av = av0; snode = snode0; Mrows = M0; rowBase = blockIdx.x * 128;
    } else {
        A = A1; Wp = Wp1; bias = bias1; lng = lng1; lnb = lnb1; C = C1; Ch = nullptr;
        av = nullptr; snode = nullptr; Mrows = M1; rowBase = (blockIdx.x - nb0) * 128;
    }

    int rA[2], cgA[2];
#pragma unroll
    for (int i = 0; i < 2; i++) {
        int g = tid + i * 512;
        rA[i] = g >> 3; cgA[i] = g & 7;
    }
    float4 pref[4];

    auto issueA = [&](int ch) {
#pragma unroll
        for (int i = 0; i < 2; i++) {
            int row = rowBase + rA[i];
            if (row < Mrows) {
                const float4* src = reinterpret_cast<const float4*>(
                    A + (size_t)row * DD + ch * 64 + cgA[i] * 8);
                pref[i * 2]     = src[0];
                pref[i * 2 + 1] = src[1];
            } else {
                pref[i * 2]     = make_float4(0.f, 0.f, 0.f, 0.f);
                pref[i * 2 + 1] = make_float4(0.f, 0.f, 0.f, 0.f);
            }
        }
    };
    auto storeA = [&](int s) {
#pragma unroll
        for (int i = 0; i < 2; i++) {
            float x[8];
            float4 v0 = pref[i * 2], v1 = pref[i * 2 + 1];
            x[0] = v0.x; x[1] = v0.y; x[2] = v0.z; x[3] = v0.w;
            x[4] = v1.x; x[5] = v1.y; x[6] = v1.z; x[7] = v1.w;
            unsigned short hi[8], lo[8];
#pragma unroll
            for (int j = 0; j < 8; j++) {
                __nv_bfloat16 h = __float2bfloat16(x[j]);
                __nv_bfloat16 l = __float2bfloat16(x[j] - __bfloat162float(h));
                hi[j] = *reinterpret_cast<unsigned short*>(&h);
                lo[j] = *reinterpret_cast<unsigned short*>(&l);
            }
            uint32_t off = s * 32768u + swz((uint32_t)rA[i], (uint32_t)cgA[i] * 16u);
            *reinterpret_cast<uint4*>(smem + off)         = *reinterpret_cast<uint4*>(hi);
            *reinterpret_cast<uint4*>(smem + 16384 + off) = *reinterpret_cast<uint4*>(lo);
        }
    };
    auto issueB = [&](int ch, int s) {
        const unsigned char* bh = Wp + (size_t)(ch * 2 + 0) * 32768;
        const unsigned char* bl = Wp + (size_t)(ch * 2 + 1) * 32768;
        uint32_t dh = sb + 65536u + (uint32_t)s * 65536u;
        uint32_t dl = dh + 32768u;
#pragma unroll
        for (int i = 0; i < 4; i++) {
            int idx = (tid + i * 512) * 16;
            CP_ASYNC16(dh + idx, bh + idx);
            CP_ASYNC16(dl + idx, bl + idx);
        }
        CP_COMMIT();
    };

    float c[2][8][4];
#pragma unroll
    for (int mt = 0; mt < 2; mt++)
#pragma unroll
        for (int nt = 0; nt < 8; nt++)
#pragma unroll
            for (int q = 0; q < 4; q++) c[mt][nt][q] = 0.f;

    issueA(0);
    issueB(0, 0);
    storeA(0);

    for (int ch = 0; ch < 4; ch++) {
        const int s = ch & 1;
        if (ch < 3) {
            issueA(ch + 1);
            issueB(ch + 1, s ^ 1);
            CP_WAIT(1);
        } else {
            CP_WAIT(0);
        }
        __syncthreads();

        const uint32_t aBase = sb + (uint32_t)s * 32768u;
        const uint32_t bBase = sb + 65536u + (uint32_t)s * 65536u;
#pragma unroll
        for (int ks = 0; ks < 4; ks++) {
            uint32_t ah[2][4], al[2][4];
#pragma unroll
            for (int mt = 0; mt < 2; mt++) {
                uint32_t row = (uint32_t)(warpM * 32 + mt * 16 + (lane & 7) + ((lane >> 3) & 1) * 8);
                uint32_t kb  = (uint32_t)(ks * 32 + ((lane >> 4) & 1) * 16);
                uint32_t addr = aBase + swz(row, kb);
                ldm_x4(addr,         ah[mt]);
                ldm_x4(addr + 16384, al[mt]);
            }
#pragma unroll
            for (int p = 0; p < 4; p++) {
                uint32_t nrow = (uint32_t)(warpN * 64 + p * 16 + (lane & 7) + ((lane >> 4) & 1) * 8);
                uint32_t kb   = (uint32_t)(ks * 32 + ((lane >> 3) & 1) * 16);
                uint32_t addr = bBase + swz(nrow, kb);
                uint32_t bh[4], bl[4];
                ldm_x4(addr,         bh);
                ldm_x4(addr + 32768, bl);
#pragma unroll
                for (int t = 0; t < 2; t++) {
#pragma unroll
                    for (int mt = 0; mt < 2; mt++) {
                        float* cc = c[mt][p * 2 + t];
                        mma_bf16(cc, ah[mt], bh + t * 2);
                        mma_bf16(cc, ah[mt], bl + t * 2);
                        mma_bf16(cc, al[mt], bh + t * 2);
                    }
                }
            }
        }
        if (ch < 3) storeA(s ^ 1);
        __syncthreads();
    }

    const int gid = lane >> 2, tig = lane & 3;
    float2* rb = reinterpret_cast<float2*>(smem);

#pragma unroll
    for (int mt = 0; mt < 2; mt++)
#pragma unroll
        for (int nt = 0; nt < 8; nt++) {
            int col = warpN * 64 + nt * 8 + tig * 2;
            float2 bv = *reinterpret_cast<const float2*>(bias + col);
            c[mt][nt][0] = lrelu_f(c[mt][nt][0] + bv.x);
            c[mt][nt][1] = lrelu_f(c[mt][nt][1] + bv.y);
            c[mt][nt][2] = lrelu_f(c[mt][nt][2] + bv.x);
            c[mt][nt][3] = lrelu_f(c[mt][nt][3] + bv.y);
        }

#pragma unroll
    for (int mt = 0; mt < 2; mt++) {
        float s0 = 0.f, q0 = 0.f, s1 = 0.f, q1 = 0.f;
#pragma unroll
        for (int nt = 0; nt < 8; nt++) {
            float o0 = c[mt][nt][0], o1 = c[mt][nt][1];
            float o2 = c[mt][nt][2], o3 = c[mt][nt][3];
            s0 += o0 + o1; q0 += o0 * o0 + o1 * o1;
            s1 += o2 + o3; q1 += o2 * o2 + o3 * o3;
        }
#pragma unroll
        for (int o = 1; o < 4; o <<= 1) {
            s0 += __shfl_xor_sync(0xFFFFFFFFu, s0, o);
            q0 += __shfl_xor_sync(0xFFFFFFFFu, q0, o);
            s1 += __shfl_xor_sync(0xFFFFFFFFu, s1, o);
            q1 += __shfl_xor_sync(0xFFFFFFFFu, q1, o);
        }
        if (tig == 0) {
            int lr0 = warpM * 32 + mt * 16 + gid;
            rb[lr0 * 4 + warpN]       = make_float2(s0, q0);
            rb[(lr0 + 8) * 4 + warpN] = make_float2(s1, q1);
        }
    }
    __syncthreads();

    float sd[2][2] = {{0.f, 0.f}, {0.f, 0.f}};
#pragma unroll
    for (int mt = 0; mt < 2; mt++) {
        int lr0 = warpM * 32 + mt * 16 + gid;
        int lr1 = lr0 + 8;
        float2 p00 = rb[lr0*4+0], p01 = rb[lr0*4+1], p02 = rb[lr0*4+2], p03 = rb[lr0*4+3];
        float2 p10 = rb[lr1*4+0], p11 = rb[lr1*4+1], p12 = rb[lr1*4+2], p13 = rb[lr1*4+3];
        float sum0 = p00.x + p01.x + p02.x + p03.x;
        float sq0  = p00.y + p01.y + p02.y + p03.y;
        float sum1 = p10.x + p11.x + p12.x + p13.x;
        float sq1  = p10.y + p11.y + p12.y + p13.y;
        float mean0 = sum0 * (1.f / 256.f);
        float rstd0 = rsqrtf(sq0 * (1.f / 256.f) - mean0 * mean0 + 1e-5f);
        float mean1 = sum1 * (1.f / 256.f);
        float rstd1 = rsqrtf(sq1 * (1.f / 256.f) - mean1 * mean1 + 1e-5f);
        int r0 = rowBase + lr0, r1 = rowBase + lr1;
        bool v0 = r0 < Mrows, v1 = r1 < Mrows;
#pragma unroll
        for (int nt = 0; nt < 8; nt++) {
            int col = warpN * 64 + nt * 8 + tig * 2;
            float2 gv = *reinterpret_cast<const float2*>(lng + col);
            float2 bv = *reinterpret_cast<const float2*>(lnb + col);
            float o0 = (c[mt][nt][0] - mean0) * rstd0 * gv.x + bv.x;
            float o1 = (c[mt][nt][1] - mean0) * rstd0 * gv.y + bv.y;
            float o2 = (c[mt][nt][2] - mean1) * rstd1 * gv.x + bv.x;
            float o3 = (c[mt][nt][3] - mean1) * rstd1 * gv.y + bv.y;
            if (v0) {
                *reinterpret_cast<float2*>(C + (size_t)r0 * DD + col) = make_float2(o0, o1);
                if (Ch) *reinterpret_cast<__half2*>(Ch + (size_t)r0 * DD + col) = __floats2half2_rn(o0, o1);
            }
            if (v1) {
                *reinterpret_cast<float2*>(C + (size_t)r1 * DD + col) = make_float2(o2, o3);
                if (Ch) *reinterpret_cast<__half2*>(Ch + (size_t)r1 * DD + col) = __floats2half2_rn(o2, o3);
            }
            if (snode != nullptr) {
                float2 avv = *reinterpret_cast<const float2*>(av + col);
                sd[mt][0] += o0 * avv.x + o1 * avv.y;
                sd[mt][1] += o2 * avv.x + o3 * avv.y;
            }
        }
    }

    if (snode != nullptr) {
        __syncthreads();
#pragma unroll
        for (int mt = 0; mt < 2; mt++) {
            float s0 = sd[mt][0], s1 = sd[mt][1];
#pragma unroll
            for (int o = 1; o < 4; o <<= 1) {
                s0 += __shfl_xor_sync(0xFFFFFFFFu, s0, o);
                s1 += __shfl_xor_sync(0xFFFFFFFFu, s1, o);
            }
            if (tig == 0) {
                int lr0 = warpM * 32 + mt * 16 + gid;
                rb[lr0 * 4 + warpN]       = make_float2(s0, 0.f);
                rb[(lr0 + 8) * 4 + warpN] = make_float2(s1, 0.f);
            }
        }
        __syncthreads();
        if (warpN == 0 && tig == 0) {
#pragma unroll
            for (int mt = 0; mt < 2; mt++) {
                int lr0 = warpM * 32 + mt * 16 + gid;
#pragma unroll
                for (int h = 0; h < 2; h++) {
                    int lr = lr0 + h * 8;
                    int row = rowBase + lr;
                    if (row < Mrows) {
                        snode[row] = rb[lr * 4 + 0].x + rb[lr * 4 + 1].x
                                   + rb[lr * 4 + 2].x + rb[lr * 4 + 3].x;
                    }
                }
            }
        }
    }
}

// ======== hgnn edge GEMM (ef written fp16) ========
template <int FLAGS>
__global__ __launch_bounds__(512, 1)
void tgemm256(const float* __restrict__ A, const unsigned char* __restrict__ Wp,
              const float* __restrict__ av, __half* __restrict__ C,
              float* __restrict__ snode, int Mrows)
{
    extern __shared__ __align__(128) unsigned char smem[];
    const uint32_t sb = smem_to_u32(smem);
    const int tid = threadIdx.x, lane = tid & 31, wid = tid >> 5;
    const int warpM = wid >> 2, warpN = wid & 3;
    const int rowBase = blockIdx.x * 128;

    int rA[2], cgA[2];
#pragma unroll
    for (int i = 0; i < 2; i++) {
        int g = tid + i * 512;
        rA[i] = g >> 3; cgA[i] = g & 7;
    }
    float4 pref[4];

    auto issueA = [&](int ch) {
#pragma unroll
        for (int i = 0; i < 2; i++) {
            int row = rowBase + rA[i];
            if (row < Mrows) {
                const float4* src = reinterpret_cast<const float4*>(
                    A + (size_t)row * DD + ch * 64 + cgA[i] * 8);
                pref[i * 2]     = src[0];
                pref[i * 2 + 1] = src[1];
            } else {
                pref[i * 2]     = make_float4(0.f, 0.f, 0.f, 0.f);
                pref[i * 2 + 1] = make_float4(0.f, 0.f, 0.f, 0.f);
            }
        }
    };
    auto storeA = [&](int s) {
#pragma unroll
        for (int i = 0; i < 2; i++) {
            float x[8];
            float4 v0 = pref[i * 2], v1 = pref[i * 2 + 1];
            x[0] = v0.x; x[1] = v0.y; x[2] = v0.z; x[3] = v0.w;
            x[4] = v1.x; x[5] = v1.y; x[6] = v1.z; x[7] = v1.w;
            unsigned short hi[8], lo[8];
#pragma unroll
            for (int j = 0; j < 8; j++) {
                __nv_bfloat16 h = __float2bfloat16(x[j]);
                __nv_bfloat16 l = __float2bfloat16(x[j] - __bfloat162float(h));
                hi[j] = *reinterpret_cast<unsigned short*>(&h);
                lo[j] = *reinterpret_cast<unsigned short*>(&l);
            }
            uint32_t off = s * 32768u + swz((uint32_t)rA[i], (uint32_t)cgA[i] * 16u);
            *reinterpret_cast<uint4*>(smem + off)         = *reinterpret_cast<uint4*>(hi);
            *reinterpret_cast<uint4*>(smem + 16384 + off) = *reinterpret_cast<uint4*>(lo);
        }
    };
    auto issueB = [&](int ch, int s) {
        const unsigned char* bh = Wp + (size_t)(ch * 2 + 0) * 32768;
        const unsigned char* bl = Wp + (size_t)(ch * 2 + 1) * 32768;
        uint32_t dh = sb + 65536u + (uint32_t)s * 65536u;
        uint32_t dl = dh + 32768u;
#pragma unroll
        for (int i = 0; i < 4; i++) {
            int idx = (tid + i * 512) * 16;
            CP_ASYNC16(dh + idx, bh + idx);
            CP_ASYNC16(dl + idx, bl + idx);
        }
        CP_COMMIT();
    };

    float c[2][8][4];
#pragma unroll
    for (int mt = 0; mt < 2; mt++)
#pragma unroll
        for (int nt = 0; nt < 8; nt++)
#pragma unroll
            for (int q = 0; q < 4; q++) c[mt][nt][q] = 0.f;

    issueA(0);
    issueB(0, 0);
    storeA(0);

    for (int ch = 0; ch < 4; ch++) {
        const int s = ch & 1;
        if (ch < 3) {
            issueA(ch + 1);
            issueB(ch + 1, s ^ 1);
            CP_WAIT(1);
        } else {
            CP_WAIT(0);
        }
        __syncthreads();

        const uint32_t aBase = sb + (uint32_t)s * 32768u;
        const uint32_t bBase = sb + 65536u + (uint32_t)s * 65536u;
#pragma unroll
        for (int ks = 0; ks < 4; ks++) {
            uint32_t ah[2][4], al[2][4];
#pragma unroll
            for (int mt = 0; mt < 2; mt++) {
                uint32_t row = (uint32_t)(warpM * 32 + mt * 16 + (lane & 7) + ((lane >> 3) & 1) * 8);
                uint32_t kb  = (uint32_t)(ks * 32 + ((lane >> 4) & 1) * 16);
                uint32_t addr = aBase + swz(row, kb);
                ldm_x4(addr,         ah[mt]);
                ldm_x4(addr + 16384, al[mt]);
            }
#pragma unroll
            for (int p = 0; p < 4; p++) {
                uint32_t nrow = (uint32_t)(warpN * 64 + p * 16 + (lane & 7) + ((lane >> 4) & 1) * 8);
                uint32_t kb   = (uint32_t)(ks * 32 + ((lane >> 3) & 1) * 16);
                uint32_t addr = bBase + swz(nrow, kb);
                uint32_t bh[4], bl[4];
                ldm_x4(addr,         bh);
                ldm_x4(addr + 32768, bl);
#pragma unroll
                for (int t = 0; t < 2; t++) {
#pragma unroll
                    for (int mt = 0; mt < 2; mt++) {
                        float* cc = c[mt][p * 2 + t];
                        mma_bf16(cc, ah[mt], bh + t * 2);
                        mma_bf16(cc, ah[mt], bl + t * 2);
                        mma_bf16(cc, al[mt], bh + t * 2);
                    }
                }
            }
        }
        if (ch < 3) storeA(s ^ 1);
        __syncthreads();
    }

    const int gid = lane >> 2, tig = lane & 3;
    float2* rb = reinterpret_cast<float2*>(smem);

#pragma unroll
    for (int mt = 0; mt < 2; mt++) {
        int r0 = rowBase + warpM * 32 + mt * 16 + gid;
        int r1 = r0 + 8;
        bool v0 = r0 < Mrows, v1 = r1 < Mrows;
#pragma unroll
        for (int nt = 0; nt < 8; nt++) {
            int col = warpN * 64 + nt * 8 + tig * 2;
            if (v0) *reinterpret_cast<__half2*>(C + (size_t)r0 * DD + col)
                        = __floats2half2_rn(c[mt][nt][0], c[mt][nt][1]);
            if (v1) *reinterpret_cast<__half2*>(C + (size_t)r1 * DD + col)
                        = __floats2half2_rn(c[mt][nt][2], c[mt][nt][3]);
        }
    }

    if (FLAGS & F_SNODE) {
#pragma unroll
        for (int mt = 0; mt < 2; mt++) {
            float s0 = 0.f, s1 = 0.f;
#pragma unroll
            for (int nt = 0; nt < 8; nt++) {
                int col = warpN * 64 + nt * 8 + tig * 2;
                float2 avv = *reinterpret_cast<const float2*>(av + col);
                s0 += c[mt][nt][0] * avv.x + c[mt][nt][1] * avv.y;
                s1 += c[mt][nt][2] * avv.x + c[mt][nt][3] * avv.y;
            }
#pragma unroll
            for (int o = 1; o < 4; o <<= 1) {
                s0 += __shfl_xor_sync(0xFFFFFFFFu, s0, o);
                s1 += __shfl_xor_sync(0xFFFFFFFFu, s1, o);
            }
            if (tig == 0) {
                int lr0 = warpM * 32 + mt * 16 + gid;
                rb[lr0 * 4 + warpN]       = make_float2(s0, 0.f);
                rb[(lr0 + 8) * 4 + warpN] = make_float2(s1, 0.f);
            }
        }
        __syncthreads();
        if (warpN == 0 && tig == 0) {
#pragma unroll
            for (int mt = 0; mt < 2; mt++) {
                int lr0 = warpM * 32 + mt * 16 + gid;
#pragma unroll
                for (int h = 0; h < 2; h++) {
                    int lr = lr0 + h * 8;
                    int row = rowBase + lr;
                    if (row < Mrows) {
                        snode[row] = rb[lr * 4 + 0].x + rb[lr * 4 + 1].x
                                   + rb[lr * 4 + 2].x + rb[lr * 4 + 3].x;
                    }
                }
            }
        }
    }
}

// ======== fused dual GEMM (+ fp16 mirror of obj2) ========
__global__ __launch_bounds__(512, 1)
void tgemm_dual(const float* __restrict__ A, const unsigned char* __restrict__ Wp1,
                const float* __restrict__ bias1, const float* __restrict__ R1,
                const float* __restrict__ lng1, const float* __restrict__ lnb1,
                const unsigned char* __restrict__ Wp2, const float* __restrict__ bias2,
                const float* __restrict__ lng2, const float* __restrict__ lnb2,
                float* __restrict__ C2, __half* __restrict__ C2h,
                const float* __restrict__ av,
                float* __restrict__ snode, int Mrows)
{
    extern __shared__ __align__(128) unsigned char smem[];
    const uint32_t sb = smem_to_u32(smem);
    const int tid = threadIdx.x, lane = tid & 31, wid = tid >> 5;
    const int warpM = wid >> 2, warpN = wid & 3;
    const int rowBase = blockIdx.x * 128;

    int rA[2], cgA[2];
#pragma unroll
    for (int i = 0; i < 2; i++) {
        int g = tid + i * 512;
        rA[i] = g >> 3; cgA[i] = g & 7;
    }
    float4 pref[4];

    auto issueA = [&](int ch) {
#pragma unroll
        for (int i = 0; i < 2; i++) {
            int row = rowBase + rA[i];
            if (row < Mrows) {
                const float4* src = reinterpret_cast<const float4*>(
                    A + (size_t)row * DD + ch * 64 + cgA[i] * 8);
                pref[i * 2]     = src[0];
                pref[i * 2 + 1] = src[1];
            } else {
                pref[i * 2]     = make_float4(0.f, 0.f, 0.f, 0.f);
                pref[i * 2 + 1] = make_float4(0.f, 0.f, 0.f, 0.f);
            }
        }
    };
    auto storeA = [&](int s) {
#pragma unroll
        for (int i = 0; i < 2; i++) {
            float x[8];
            float4 v0 = pref[i * 2], v1 = pref[i * 2 + 1];
            x[0] = v0.x; x[1] = v0.y; x[2] = v0.z; x[3] = v0.w;
            x[4] = v1.x; x[5] = v1.y; x[6] = v1.z; x[7] = v1.w;
            unsigned short hi[8], lo[8];
#pragma unroll
            for (int j = 0; j < 8; j++) {
                __nv_bfloat16 h = __float2bfloat16(x[j]);
                __nv_bfloat16 l = __float2bfloat16(x[j] - __bfloat162float(h));
                hi[j] = *reinterpret_cast<unsigned short*>(&h);
                lo[j] = *reinterpret_cast<unsigned short*>(&l);
            }
            uint32_t off = 131072u + s * 32768u + swz((uint32_t)rA[i], (uint32_t)cgA[i] * 16u);
            *reinterpret_cast<uint4*>(smem + off)         = *reinterpret_cast<uint4*>(hi);
            *reinterpret_cast<uint4*>(smem + 16384 + off) = *reinterpret_cast<uint4*>(lo);
        }
    };
    auto issueB1 = [&](int ch, int s) {
        const unsigned char* bh = Wp1 + (size_t)(ch * 2 + 0) * 32768;
        const unsigned char* bl = Wp1 + (size_t)(ch * 2 + 1) * 32768;
        uint32_t dh = sb + (uint32_t)s * 65536u;
        uint32_t dl = dh + 32768u;
#pragma unroll
        for (int i = 0; i < 4; i++) {
            int idx = (tid + i * 512) * 16;
            CP_ASYNC16(dh + idx, bh + idx);
            CP_ASYNC16(dl + idx, bl + idx);
        }
        CP_COMMIT();
    };
    auto issueB2 = [&](int ch) {
        const unsigned char* bh = Wp2 + (size_t)(ch * 2 + 0) * 32768;
        const unsigned char* bl = Wp2 + (size_t)(ch * 2 + 1) * 32768;
        uint32_t dh = sb + 131072u;
        uint32_t dl = dh + 32768u;
#pragma unroll
        for (int i = 0; i < 4; i++) {
            int idx = (tid + i * 512) * 16;
            CP_ASYNC16(dh + idx, bh + idx);
            CP_ASYNC16(dl + idx, bl + idx);
        }
        CP_COMMIT();
    };

    float c[2][8][4];
#pragma unroll
    for (int mt = 0; mt < 2; mt++)
#pragma unroll
        for (int nt = 0; nt < 8; nt++)
#pragma unroll
            for (int q = 0; q < 4; q++) c[mt][nt][q] = 0.f;

    // ---- phase 1 ----
    issueA(0);
    issueB1(0, 0);
    storeA(0);

    for (int ch = 0; ch < 4; ch++) {
        const int s = ch & 1;
        if (ch < 3) {
            issueA(ch + 1);
            issueB1(ch + 1, s ^ 1);
            CP_WAIT(1);
        } else {
            CP_WAIT(0);
        }
        __syncthreads();

        const uint32_t aBase = sb + 131072u + (uint32_t)s * 32768u;
        const uint32_t bBase = sb + (uint32_t)s * 65536u;
#pragma unroll
        for (int ks = 0; ks < 4; ks++) {
            uint32_t ah[2][4], al[2][4];
#pragma unroll
            for (int mt = 0; mt < 2; mt++) {
                uint32_t row = (uint32_t)(warpM * 32 + mt * 16 + (lane & 7) + ((lane >> 3) & 1) * 8);
                uint32_t kb  = (uint32_t)(ks * 32 + ((lane >> 4) & 1) * 16);
                uint32_t addr = aBase + swz(row, kb);
                ldm_x4(addr,         ah[mt]);
                ldm_x4(addr + 16384, al[mt]);
            }
#pragma unroll
            for (int p = 0; p < 4; p++) {
                uint32_t nrow = (uint32_t)(warpN * 64 + p * 16 + (lane & 7) + ((lane >> 4) & 1) * 8);
                uint32_t kb   = (uint32_t)(ks * 32 + ((lane >> 3) & 1) * 16);
                uint32_t addr = bBase + swz(nrow, kb);
                uint32_t bh[4], bl[4];
                ldm_x4(addr,         bh);
                ldm_x4(addr + 32768, bl);
#pragma unroll
                for (int t = 0; t < 2; t++) {
#pragma unroll
                    for (int mt = 0; mt < 2; mt++) {
                        float* cc = c[mt][p * 2 + t];
                        mma_bf16(cc, ah[mt], bh + t * 2);
                        mma_bf16(cc, ah[mt], bl + t * 2);
                        mma_bf16(cc, al[mt], bh + t * 2);
                    }
                }
            }
        }
        if (ch < 3) storeA(s ^ 1);
        __syncthreads();
    }

    // ---- epilogue 1 ----
    const int gid = lane >> 2, tig = lane & 3;
    float2* rb = reinterpret_cast<float2*>(smem + 131072);

#pragma unroll
    for (int mt = 0; mt < 2; mt++) {
        int r0 = rowBase + warpM * 32 + mt * 16 + gid;
        int r1 = r0 + 8;
        bool v0 = r0 < Mrows, v1 = r1 < Mrows;
#pragma unroll
        for (int nt = 0; nt < 8; nt++) {
            int col = warpN * 64 + nt * 8 + tig * 2;
            float2 bv = *reinterpret_cast<const float2*>(bias1 + col);
            float o0 = lrelu_f(c[mt][nt][0] + bv.x), o1 = lrelu_f(c[mt][nt][1] + bv.y);
            float o2 = lrelu_f(c[mt][nt][2] + bv.x), o3 = lrelu_f(c[mt][nt][3] + bv.y);
            if (v0) {
                float2 rv = *reinterpret_cast<const float2*>(R1 + (size_t)r0 * DD + col);
                o0 += rv.x; o1 += rv.y;
            }
            if (v1) {
                float2 rv = *reinterpret_cast<const float2*>(R1 + (size_t)r1 * DD + col);
                o2 += rv.x; o3 += rv.y;
            }
            c[mt][nt][0] = o0; c[mt][nt][1] = o1; c[mt][nt][2] = o2; c[mt][nt][3] = o3;
        }
    }
#pragma unroll
    for (int mt = 0; mt < 2; mt++) {
        float s0 = 0.f, q0 = 0.f, s1 = 0.f, q1 = 0.f;
#pragma unroll
        for (int nt = 0; nt < 8; nt++) {
            float o0 = c[mt][nt][0], o1 = c[mt][nt][1];
            float o2 = c[mt][nt][2], o3 = c[mt][nt][3];
            s0 += o0 + o1; q0 += o0 * o0 + o1 * o1;
            s1 += o2 + o3; q1 += o2 * o2 + o3 * o3;
        }
#pragma unroll
        for (int o = 1; o < 4; o <<= 1) {
            s0 += __shfl_xor_sync(0xFFFFFFFFu, s0, o);
            q0 += __shfl_xor_sync(0xFFFFFFFFu, q0, o);
            s1 += __shfl_xor_sync(0xFFFFFFFFu, s1, o);
            q1 += __shfl_xor_sync(0xFFFFFFFFu, q1, o);
        }
        if (tig == 0) {
            int lr0 = warpM * 32 + mt * 16 + gid;
            rb[lr0 * 4 + warpN]       = make_float2(s0, q0);
            rb[(lr0 + 8) * 4 + warpN] = make_float2(s1, q1);
        }
    }
    __syncthreads();
#pragma unroll
    for (int mt = 0; mt < 2; mt++) {
        int lr0 = warpM * 32 + mt * 16 + gid;
        int lr1 = lr0 + 8;
        float2 p00 = rb[lr0*4+0], p01 = rb[lr0*4+1], p02 = rb[lr0*4+2], p03 = rb[lr0*4+3];
        float2 p10 = rb[lr1*4+0], p11 = rb[lr1*4+1], p12 = rb[lr1*4+2], p13 = rb[lr1*4+3];
        float sum0 = p00.x + p01.x + p02.x + p03.x;
        float sq0  = p00.y + p01.y + p02.y + p03.y;
        float sum1 = p10.x + p11.x + p12.x + p13.x;
        float sq1  = p10.y + p11.y + p12.y + p13.y;
        float mean0 = sum0 * (1.f / 256.f);
        float rstd0 = rsqrtf(sq0 * (1.f / 256.f) - mean0 * mean0 + 1e-5f);
        float mean1 = sum1 * (1.f / 256.f);
        float rstd1 = rsqrtf(sq1 * (1.f / 256.f) - mean1 * mean1 + 1e-5f);
#pragma unroll
        for (int nt = 0; nt < 8; nt++) {
            int col = warpN * 64 + nt * 8 + tig * 2;
            float2 gv = *reinterpret_cast<const float2*>(lng1 + col);
            float2 bv = *reinterpret_cast<const float2*>(lnb1 + col);
            c[mt][nt][0] = (c[mt][nt][0] - mean0) * rstd0 * gv.x + bv.x;
            c[mt][nt][1] = (c[mt][nt][1] - mean0) * rstd0 * gv.y + bv.y;
            c[mt][nt][2] = (c[mt][nt][2] - mean1) * rstd1 * gv.x + bv.x;
            c[mt][nt][3] = (c[mt][nt][3] - mean1) * rstd1 * gv.y + bv.y;
        }
    }
    __syncthreads();

    // ---- store obj1 to A2 smem + issue B2 chunk 0 ----
    issueB2(0);
#pragma unroll
    for (int mt = 0; mt < 2; mt++) {
        uint32_t lr0 = (uint32_t)(warpM * 32 + mt * 16 + gid);
        uint32_t lr1 = lr0 + 8;
#pragma unroll
        for (int nt = 0; nt < 8; nt++) {
            uint32_t cb = (uint32_t)(warpN * 64 + nt * 8 + tig * 2) * 2u;
            float o0 = c[mt][nt][0], o1 = c[mt][nt][1];
            float o2 = c[mt][nt][2], o3 = c[mt][nt][3];
            __nv_bfloat16 h0 = __float2bfloat16(o0), h1 = __float2bfloat16(o1);
            __nv_bfloat16 h2 = __float2bfloat16(o2), h3 = __float2bfloat16(o3);
            __nv_bfloat16 l0 = __float2bfloat16(o0 - __bfloat162float(h0));
            __nv_bfloat16 l1 = __float2bfloat16(o1 - __bfloat162float(h1));
            __nv_bfloat16 l2 = __float2bfloat16(o2 - __bfloat162float(h2));
            __nv_bfloat16 l3 = __float2bfloat16(o3 - __bfloat162float(h3));
            uint32_t hp0 = ((uint32_t)*reinterpret_cast<unsigned short*>(&h1) << 16)
                         |  (uint32_t)*reinterpret_cast<unsigned short*>(&h0);
            uint32_t lp0 = ((uint32_t)*reinterpret_cast<unsigned short*>(&l1) << 16)
                         |  (uint32_t)*reinterpret_cast<unsigned short*>(&l0);
            uint32_t hp1 = ((uint32_t)*reinterpret_cast<unsigned short*>(&h3) << 16)
                         |  (uint32_t)*reinterpret_cast<unsigned short*>(&h2);
            uint32_t lp1 = ((uint32_t)*reinterpret_cast<unsigned short*>(&l3) << 16)
                         |  (uint32_t)*reinterpret_cast<unsigned short*>(&l2);
            *reinterpret_cast<uint32_t*>(smem + swz512(lr0, cb))           = hp0;
            *reinterpret_cast<uint32_t*>(smem + 65536u + swz512(lr0, cb))  = lp0;
            *reinterpret_cast<uint32_t*>(smem + swz512(lr1, cb))           = hp1;
            *reinterpret_cast<uint32_t*>(smem + 65536u + swz512(lr1, cb))  = lp1;
        }
    }
#pragma unroll
    for (int mt = 0; mt < 2; mt++)
#pragma unroll
        for (int nt = 0; nt < 8; nt++)
#pragma unroll
            for (int q = 0; q < 4; q++) c[mt][nt][q] = 0.f;
    __syncthreads();

    // ---- phase 2 ----
    for (int ch = 0; ch < 4; ch++) {
        CP_WAIT(0);
        __syncthreads();
        const uint32_t bBase = sb + 131072u;
#pragma unroll
        for (int ks = 0; ks < 4; ks++) {
            uint32_t ah[2][4], al[2][4];
#pragma unroll
            for (int mt = 0; mt < 2; mt++) {
                uint32_t row = (uint32_t)(warpM * 32 + mt * 16 + (lane & 7) + ((lane >> 3) & 1) * 8);
                uint32_t kb  = (uint32_t)(ch * 128 + ks * 32 + ((lane >> 4) & 1) * 16);
                uint32_t addr = sb + swz512(row, kb);
                ldm_x4(addr,          ah[mt]);
                ldm_x4(addr + 65536u, al[mt]);
            }
#pragma unroll
            for (int p = 0; p < 4; p++) {
                uint32_t nrow = (uint32_t)(warpN * 64 + p * 16 + (lane & 7) + ((lane >> 4) & 1) * 8);
                uint32_t kb   = (uint32_t)(ks * 32 + ((lane >> 3) & 1) * 16);
                uint32_t addr = bBase + swz(nrow, kb);
                uint32_t bh[4], bl[4];
                ldm_x4(addr,          bh);
                ldm_x4(addr + 32768u, bl);
#pragma unroll
                for (int t = 0; t < 2; t++) {
#pragma unroll
                    for (int mt = 0; mt < 2; mt++) {
                        float* cc = c[mt][p * 2 + t];
                        mma_bf16(cc, ah[mt], bh + t * 2);
                        mma_bf16(cc, ah[mt], bl + t * 2);
                        mma_bf16(cc, al[mt], bh + t * 2);
                    }
                }
            }
        }
        __syncthreads();
        if (ch < 3) issueB2(ch + 1);
    }

    // ---- epilogue 2 ----
#pragma unroll
    for (int mt = 0; mt < 2; mt++) {
        uint32_t lr0 = (uint32_t)(warpM * 32 + mt * 16 + gid);
        uint32_t lr1 = lr0 + 8;
#pragma unroll
        for (int nt = 0; nt < 8; nt++) {
            int col = warpN * 64 + nt * 8 + tig * 2;
            uint32_t cb = (uint32_t)col * 2u;
            float2 bv = *reinterpret_cast<const float2*>(bias2 + col);
            float o0 = lrelu_f(c[mt][nt][0] + bv.x), o1 = lrelu_f(c[mt][nt][1] + bv.y);
            float o2 = lrelu_f(c[mt][nt][2] + bv.x), o3 = lrelu_f(c[mt][nt][3] + bv.y);
            uint32_t hp0 = *reinterpret_cast<uint32_t*>(smem + swz512(lr0, cb));
            uint32_t lp0 = *reinterpret_cast<uint32_t*>(smem + 65536u + swz512(lr0, cb));
            uint32_t hp1 = *reinterpret_cast<uint32_t*>(smem + swz512(lr1, cb));
            uint32_t lp1 = *reinterpret_cast<uint32_t*>(smem + 65536u + swz512(lr1, cb));
            unsigned short u;
            u = (unsigned short)(hp0 & 0xFFFF);
            float r0a = __bfloat162float(*reinterpret_cast<__nv_bfloat16*>(&u));
            u = (unsigned short)(lp0 & 0xFFFF);
            r0a += __bfloat162float(*reinterpret_cast<__nv_bfloat16*>(&u));
            u = (unsigned short)(hp0 >> 16);
            float r0b = __bfloat162float(*reinterpret_cast<__nv_bfloat16*>(&u));
            u = (unsigned short)(lp0 >> 16);
            r0b += __bfloat162float(*reinterpret_cast<__nv_bfloat16*>(&u));
            u = (unsigned short)(hp1 & 0xFFFF);
            float r1a = __bfloat162float(*reinterpret_cast<__nv_bfloat16*>(&u));
            u = (unsigned short)(lp1 & 0xFFFF);
            r1a += __bfloat162float(*reinterpret_cast<__nv_bfloat16*>(&u));
            u = (unsigned short)(hp1 >> 16);
            float r1b = __bfloat162float(*reinterpret_cast<__nv_bfloat16*>(&u));
            u = (unsigned short)(lp1 >> 16);
            r1b += __bfloat162float(*reinterpret_cast<__nv_bfloat16*>(&u));
            c[mt][nt][0] = o0 + r0a; c[mt][nt][1] = o1 + r0b;
            c[mt][nt][2] = o2 + r1a; c[mt][nt][3] = o3 + r1b;
        }
    }
#pragma unroll
    for (int mt = 0; mt < 2; mt++) {
        float s0 = 0.f, q0 = 0.f, s1 = 0.f, q1 = 0.f;
#pragma unroll
        for (int nt = 0; nt < 8; nt++) {
            float o0 = c[mt][nt][0], o1 = c[mt][nt][1];
            float o2 = c[mt][nt][2], o3 = c[mt][nt][3];
            s0 += o0 + o1; q0 += o0 * o0 + o1 * o1;
            s1 += o2 + o3; q1 += o2 * o2 + o3 * o3;
        }
#pragma unroll
        for (int o = 1; o < 4; o <<= 1) {
            s0 += __shfl_xor_sync(0xFFFFFFFFu, s0, o);
            q0 += __shfl_xor_sync(0xFFFFFFFFu, q0, o);
            s1 += __shfl_xor_sync(0xFFFFFFFFu, s1, o);
            q1 += __shfl_xor_sync(0xFFFFFFFFu, q1, o);
        }
        if (tig == 0) {
            int lr0 = warpM * 32 + mt * 16 + gid;
            rb[lr0 * 4 + warpN]       = make_float2(s0, q0);
            rb[(lr0 + 8) * 4 + warpN] = make_float2(s1, q1);
        }
    }
    __syncthreads();
    float sd[2][2] = {{0.f, 0.f}, {0.f, 0.f}};
#pragma unroll
    for (int mt = 0; mt < 2; mt++) {
        int lr0 = warpM * 32 + mt * 16 + gid;
        int lr1 = lr0 + 8;
        float2 p00 = rb[lr0*4+0], p01 = rb[lr0*4+1], p02 = rb[lr0*4+2], p03 = rb[lr0*4+3];
        float2 p10 = rb[lr1*4+0], p11 = rb[lr1*4+1], p12 = rb[lr1*4+2], p13 = rb[lr1*4+3];
        float sum0 = p00.x + p01.x + p02.x + p03.x;
        float sq0  = p00.y + p01.y + p02.y + p03.y;
        float sum1 = p10.x + p11.x + p12.x + p13.x;
        float sq1  = p10.y + p11.y + p12.y + p13.y;
        float mean0 = sum0 * (1.f / 256.f);
        float rstd0 = rsqrtf(sq0 * (1.f / 256.f) - mean0 * mean0 + 1e-5f);
        float mean1 = sum1 * (1.f / 256.f);
        float rstd1 = rsqrtf(sq1 * (1.f / 256.f) - mean1 * mean1 + 1e-5f);
        int r0 = rowBase + lr0, r1 = rowBase + lr1;
        bool v0 = r0 < Mrows, v1 = r1 < Mrows;
#pragma unroll
        for (int nt = 0; nt < 8; nt++) {
            int col = warpN * 64 + nt * 8 + tig * 2;
            float2 gv = *reinterpret_cast<const float2*>(lng2 + col);
            float2 bv = *reinterpret_cast<const float2*>(lnb2 + col);
            float o0 = (c[mt][nt][0] - mean0) * rstd0 * gv.x + bv.x;
            float o1 = (c[mt][nt][1] - mean0) * rstd0 * gv.y + bv.y;
            float o2 = (c[mt][nt][2] - mean1) * rstd1 * gv.x + bv.x;
            float o3 = (c[mt][nt][3] - mean1) * rstd1 * gv.y + bv.y;
            if (v0) {
                *reinterpret_cast<float2*>(C2 + (size_t)r0 * DD + col) = make_float2(o0, o1);
                *reinterpret_cast<__half2*>(C2h + (size_t)r0 * DD + col) = __floats2half2_rn(o0, o1);
            }
            if (v1) {
                *reinterpret_cast<float2*>(C2 + (size_t)r1 * DD + col) = make_float2(o2, o3);
                *reinterpret_cast<__half2*>(C2h + (size_t)r1 * DD + col) = __floats2half2_rn(o2, o3);
            }
            float2 avv = *reinterpret_cast<const float2*>(av + col);
            sd[mt][0] += o0 * avv.x + o1 * avv.y;
            sd[mt][1] += o2 * avv.x + o3 * avv.y;
        }
    }
    __syncthreads();
#pragma unroll
    for (int mt = 0; mt < 2; mt++) {
        float s0 = sd[mt][0], s1 = sd[mt][1];
#pragma unroll
        for (int o = 1; o < 4; o <<= 1) {
            s0 += __shfl_xor_sync(0xFFFFFFFFu, s0, o);
            s1 += __shfl_xor_sync(0xFFFFFFFFu, s1, o);
        }
        if (tig == 0) {
            int lr0 = warpM * 32 + mt * 16 + gid;
            rb[lr0 * 4 + warpN]       = make_float2(s0, 0.f);
            rb[(lr0 + 8) * 4 + warpN] = make_float2(s1, 0.f);
        }
    }
    __syncthreads();
    if (warpN == 0 && tig == 0) {
#pragma unroll
        for (int mt = 0; mt < 2; mt++) {
            int lr0 = warpM * 32 + mt * 16 + gid;
#pragma unroll
            for (int h = 0; h < 2; h++) {
                int lr = lr0 + h * 8;
                int row = rowBase + lr;
                if (row < Mrows) {
                    snode[row] = rb[lr * 4 + 0].x + rb[lr * 4 + 1].x
                               + rb[lr * 4 + 2].x + rb[lr * 4 + 3].x;
                }
            }
        }
    }
}

// -------- edge gather from fp16 mirror --------
__global__ void edge_gatherX(const __half* __restrict__ Xh, const int* __restrict__ nodeE,
                             const int* __restrict__ offE, const int* __restrict__ cntE,
                             float* __restrict__ Xmean, int act, int nEdges)
{
    int ed = blockIdx.x * 8 + (threadIdx.x >> 5);
    if (ed >= nEdges) return;
    int lane = threadIdx.x & 31;
    int start = offE[ed], deg = cntE[ed];
    float acc[8] = {0.f, 0.f, 0.f, 0.f, 0.f, 0.f, 0.f, 0.f};
    for (int base = 0; base < deg; base += 32) {
        int m = min(32, deg - base);
        int src = 0;
        if (lane < m) src = nodeE[start + base + lane];
        for (int i = 0; i < m; i++) {
            int node = __shfl_sync(0xFFFFFFFFu, src, i);
            uint4 v = *reinterpret_cast<const uint4*>(Xh + (size_t)node * DD + lane * 8);
            float f[8];
            half8_to_f(v, f, act);
#pragma unroll
            for (int j = 0; j < 8; j++) acc[j] += f[j];
        }
    }
    float inv = 1.f / fmaxf((float)deg, 1.f);
    float4* op = reinterpret_cast<float4*>(Xmean + (size_t)ed * DD + lane * 8);
    op[0] = make_float4(acc[0] * inv, acc[1] * inv, acc[2] * inv, acc[3] * inv);
    op[1] = make_float4(acc[4] * inv, acc[5] * inv, acc[6] * inv, acc[7] * inv);
}

// -------- fused per-node softmax + aggregate (ef read as fp16) --------
__global__ void node_attn_agg(const __half* __restrict__ ef, const float* __restrict__ sn,
                              const float* __restrict__ se, const int* __restrict__ edN,
                              const int* __restrict__ permN, const int* __restrict__ offN,
                              const int* __restrict__ cntN, float* __restrict__ attn,
                              float* __restrict__ out, __half* __restrict__ outHalf,
                              const float* __restrict__ av,
                              float* __restrict__ snodeOut, int doLrelu, int nNodes)
{
    int n = blockIdx.x * 8 + (threadIdx.x >> 5);
    if (n >= nNodes) return;
    int lane = threadIdx.x & 31;
    int st = offN[n], deg = cntN[n];
    float acc[8] = {0.f, 0.f, 0.f, 0.f, 0.f, 0.f, 0.f, 0.f};

    if (deg > 0) {
        float s0 = sn[n];
        if (deg <= 32) {
            int ed = 0;
            float sc = -3.4e38f;
            if (lane < deg) {
                ed = edN[st + lane];
                sc = lrelu_f(s0 + se[ed]);
            }
            float mx = sc;
#pragma unroll
            for (int o = 16; o; o >>= 1) mx = fmaxf(mx, __shfl_xor_sync(0xFFFFFFFFu, mx, o));
            float e = (lane < deg) ? expf(sc - mx) : 0.f;
            float z = e;
#pragma unroll
            for (int o = 16; o; o >>= 1) z += __shfl_xor_sync(0xFFFFFFFFu, z, o);
            float w = e / fmaxf(z, 1e-9f);
            if (lane < deg && attn != nullptr) attn[permN[st + lane]] = w;
            for (int i = 0; i < deg; i++) {
                int e_   = __shfl_sync(0xFFFFFFFFu, ed, i);
                float w_ = __shfl_sync(0xFFFFFFFFu, w, i);
                uint4 v = *reinterpret_cast<const uint4*>(ef + (size_t)e_ * DD + lane * 8);
                float f[8];
                half8_to_f(v, f, 0);
#pragma unroll
                for (int j = 0; j < 8; j++) acc[j] += w_ * f[j];
            }
        } else {
            float mx = -3.4e38f;
            for (int base = 0; base < deg; base += 32) {
                float sc = -3.4e38f;
                if (base + lane < deg)
                    sc = lrelu_f(s0 + se[edN[st + base + lane]]);
                mx = fmaxf(mx, sc);
            }
#pragma unroll
            for (int o = 16; o; o >>= 1) mx = fmaxf(mx, __shfl_xor_sync(0xFFFFFFFFu, mx, o));
            float z = 0.f;
            for (int base = 0; base < deg; base += 32) {
                if (base + lane < deg)
                    z += expf(lrelu_f(s0 + se[edN[st + base + lane]]) - mx);
            }
#pragma unroll
            for (int o = 16; o; o >>= 1) z += __shfl_xor_sync(0xFFFFFFFFu, z, o);
            float invz = 1.f / fmaxf(z, 1e-9f);
            for (int base = 0; base < deg; base += 32) {
                int m = min(32, deg - base);
                int ed = 0; float w = 0.f;
                if (lane < m) {
                    ed = edN[st + base + lane];
                    w = expf(lrelu_f(s0 + se[ed]) - mx) * invz;
                    if (attn != nullptr) attn[permN[st + base + lane]] = w;
                }
                for (int i = 0; i < m; i++) {
                    int e_   = __shfl_sync(0xFFFFFFFFu, ed, i);
                    float w_ = __shfl_sync(0xFFFFFFFFu, w, i);
                    uint4 v = *reinterpret_cast<const uint4*>(ef + (size_t)e_ * DD + lane * 8);
                    float f[8];
                    half8_to_f(v, f, 0);
#pragma unroll
                    for (int j = 0; j < 8; j++) acc[j] += w_ * f[j];
                }
            }
        }
    }
    if (snodeOut != nullptr) {
        const float4* ap = reinterpret_cast<const float4*>(av + lane * 8);
        float4 w0 = ap[0], w1 = ap[1];
        float d = lrelu_f(acc[0])*w0.x + lrelu_f(acc[1])*w0.y + lrelu_f(acc[2])*w0.z + lrelu_f(acc[3])*w0.w
                + lrelu_f(acc[4])*w1.x + lrelu_f(acc[5])*w1.y + lrelu_f(acc[6])*w1.z + lrelu_f(acc[7])*w1.w;
#pragma unroll
        for (int o = 16; o; o >>= 1) d += __shfl_xor_sync(0xFFFFFFFFu, d, o);
        if (lane == 0) snodeOut[n] = d;
    }
    if (doLrelu) {
#pragma unroll
        for (int j = 0; j < 8; j++) acc[j] = lrelu_f(acc[j]);
    }
    float4* op = reinterpret_cast<float4*>(out + (size_t)n * DD + lane * 8);
    op[0] = make_float4(acc[0], acc[1], acc[2], acc[3]);
    op[1] = make_float4(acc[4], acc[5], acc[6], acc[7]);
    if (outHalf != nullptr) {
        uint4 hv;
        __half2* hp = reinterpret_cast<__half2*>(&hv);
        hp[0] = __floats2half2_rn(acc[0], acc[1]);
        hp[1] = __floats2half2_rn(acc[2], acc[3]);
        hp[2] = __floats2half2_rn(acc[4], acc[5]);
        hp[3] = __floats2half2_rn(acc[6], acc[7]);
        *reinterpret_cast<uint4*>(outHalf + (size_t)n * DD + lane * 8) = hv;
    }
}

// -------- object message gather (fp16 mirror source) --------
__global__ void obj_gather(const __half* __restrict__ evh, const int* __restrict__ srcO,
                           const int* __restrict__ offO, const int* __restrict__ cntO,
                           float* __restrict__ msg, int nObj)
{
    int o = blockIdx.x * 8 + (threadIdx.x >> 5);
    if (o >= nObj) return;
    int lane = threadIdx.x & 31;
    int start = offO[o], deg = cntO[o];
    float acc[8] = {0.f, 0.f, 0.f, 0.f, 0.f, 0.f, 0.f, 0.f};
    for (int base = 0; base < deg; base += 32) {
        int m = min(32, deg - base);
        int src = 0;
        if (lane < m) src = srcO[start + base + lane];
        for (int i = 0; i < m; i++) {
            int row = __shfl_sync(0xFFFFFFFFu, src, i);
            uint4 v = *reinterpret_cast<const uint4*>(evh + (size_t)row * DD + lane * 8);
            float f[8];
            half8_to_f(v, f, 0);
#pragma unroll
            for (int j = 0; j < 8; j++) acc[j] += f[j];
        }
    }
    float4* op = reinterpret_cast<float4*>(msg + (size_t)o * DD + lane * 8);
    op[0] = make_float4(acc[0], acc[1], acc[2], acc[3]);
    op[1] = make_float4(acc[4], acc[5], acc[6], acc[7]);
}

// ----------------- host orchestration -----------------
struct Ptrs {
    float *X, *obj, *msg, *H, *snode, *sedge, *wav1, *wav2;
    __half *Xh, *Hh, *efh;
    unsigned char* wp;
    int *cntE, *offE, *nodeE, *cntN, *offN, *permN, *edN, *cntO, *offO, *srcO;
};

static void get_ptrs(Ptrs& p) {
    cudaGetSymbolAddress((void**)&p.X,     g_X);
    cudaGetSymbolAddress((void**)&p.Xh,    g_Xh);
    cudaGetSymbolAddress((void**)&p.obj,   g_obj);
    cudaGetSymbolAddress((void**)&p.msg,   g_msg);
    cudaGetSymbolAddress((void**)&p.H,     g_H);
    cudaGetSymbolAddress((void**)&p.Hh,    g_Hh);
    cudaGetSymbolAddress((void**)&p.efh,   g_efh);
    cudaGetSymbolAddress((void**)&p.snode, g_snode);
    cudaGetSymbolAddress((void**)&p.sedge, g_sedge);
    cudaGetSymbolAddress((void**)&p.wav1,  g_wav1);
    cudaGetSymbolAddress((void**)&p.wav2,  g_wav2);
    cudaGetSymbolAddress((void**)&p.wp,    g_Wprep);
    cudaGetSymbolAddress((void**)&p.cntE,  g_cntE);
    cudaGetSymbolAddress((void**)&p.offE,  g_offE);
    cudaGetSymbolAddress((void**)&p.nodeE, g_nodeE);
    cudaGetSymbolAddress((void**)&p.cntN,  g_cntN);
    cudaGetSymbolAddress((void**)&p.offN,  g_offN);
    cudaGetSymbolAddress((void**)&p.permN, g_permN);
    cudaGetSymbolAddress((void**)&p.edN,   g_edN);
    cudaGetSymbolAddress((void**)&p.cntO,  g_cntO);
    cudaGetSymbolAddress((void**)&p.offO,  g_offO);
    cudaGetSymbolAddress((void**)&p.srcO,  g_srcO);
}

extern "C" void kernel_launch(void* const* d_in, const int* in_sizes, int n_in,
                              void* d_out, int out_size)
{
    const float* object_X = (const float*)d_in[0];
    const float* event_X  = (const float*)d_in[1];
    const float* Wo = (const float*)d_in[2];  const float* bo  = (const float*)d_in[3];
    const float* go = (const float*)d_in[4];  const float* bon = (const float*)d_in[5];
    const float* We = (const float*)d_in[6];  const float* be  = (const float*)d_in[7];
    const float* ge = (const float*)d_in[8];  const float* ben = (const float*)d_in[9];
    const float* Wu = (const float*)d_in[10]; const float* bu  = (const float*)d_in[11];
    const float* Wl = (const float*)d_in[12]; const float* bl  = (const float*)d_in[13];
    const float* g1 = (const float*)d_in[14]; const float* b1  = (const float*)d_in[15];
    const float* g2 = (const float*)d_in[16]; const float* b2  = (const float*)d_in[17];
    const float* Wh1 = (const float*)d_in[18]; const float* ah1 = (const float*)d_in[19];
    const float* Wh2 = (const float*)d_in[20]; const float* ah2 = (const float*)d_in[21];
    const int* oe_ev   = (const int*)d_in[22];
    const int* oe_obj  = (const int*)d_in[23];
    const int* hg_node = (const int*)d_in[24];
    const int* hg_edge = (const int*)d_in[25];

    Ptrs p; get_ptrs(p);

    static cudaStream_t s2 = nullptr;
    static cudaEvent_t evFork = nullptr, evJoin = nullptr;
    if (s2 == nullptr) {
        cudaStreamCreateWithFlags(&s2, cudaStreamNonBlocking);
        cudaEventCreateWithFlags(&evFork, cudaEventDisableTiming);
        cudaEventCreateWithFlags(&evJoin, cudaEventDisableTiming);
    }

    // ---- fork: CSR build on side stream, overlapped with weight prep + proj GEMM ----
    cudaEventRecord(evFork, 0);
    cudaStreamWaitEvent(s2, evFork, 0);
    zero_misc<<<(2 * (NE + NN + NO) + 255) / 256, 256, 0, s2>>>();
    count_all<<<(2 * E2N + E1N + 255) / 256, 256, 0, s2>>>(hg_edge, hg_node, oe_obj);
    scan_all<<<NBT, 1024, 0, s2>>>();
    scan_small3<<<1, 32, 0, s2>>>();
    add_off_all<<<(NE + NN + NO + 255) / 256, 256, 0, s2>>>();
    fill_all<<<(2 * E2N + E1N + 255) / 256, 256, 0, s2>>>(hg_edge, hg_node, oe_obj, oe_ev);
    cudaEventRecord(evJoin, s2);

    // ---- main stream: weight prep + projections ----
    prep_w<<<dim3(32, 6), 256>>>(We, Wo, Wu, Wl, Wh1, Wh2);
    prep_wav2<<<dim3((DD + 7) / 8, 2), 256>>>(Wh1, ah1, Wh2, ah2, p.wav1, p.wav2);

    const unsigned char *wpe = p.wp, *wpo = p.wp + 262144, *wpu = p.wp + 2 * 262144,
                        *wpl = p.wp + 3 * 262144, *wph1 = p.wp + 4 * 262144,
                        *wph2 = p.wp + 5 * 262144;

    cudaFuncSetAttribute(proj_gemm, cudaFuncAttributeMaxDynamicSharedMemorySize, SMEM_SZ);
    int nb0 = (NE + 127) / 128, nb1 = (NO + 127) / 128;
    proj_gemm<<<nb0 + nb1, 512, SMEM_SZ>>>(
        event_X, wpe, be, ge, ben, p.X, p.Xh, p.wav1, p.snode, NE, nb0,
        object_X, wpo, bo, go, bon, p.obj, NO);

    // ---- join: CSR must be ready before gathers ----
    cudaStreamWaitEvent(0, evJoin, 0);

    // 3) msg = segment_sum(ev[oe_ev], oe_obj)  (from fp16 mirror)
    obj_gather<<<(NO + 7) / 8, 256>>>(p.Xh, p.srcO, p.offO, p.cntO, p.msg, NO);

    // 4+5) fused dual GEMM -> X[NE:NN) (+fp16 mirror) + snode for obj rows
    cudaFuncSetAttribute(tgemm_dual, cudaFuncAttributeMaxDynamicSharedMemorySize, SMEM_SZ);
    tgemm_dual<<<(NO + 127) / 128, 512, SMEM_SZ>>>(p.msg, wpu, bu, p.obj, g1, b1,
                                                   wpl, bl, g2, b2,
                                                   p.X + (size_t)NE * DD,
                                                   p.Xh + (size_t)NE * DD,
                                                   p.wav1, p.snode + NE, NO);

    // 6) HGNN layer 1 -> H (+fp16 mirror); snode2 fused into node_attn_agg
    cudaFuncSetAttribute(tgemm256<F_SNODE>, cudaFuncAttributeMaxDynamicSharedMemorySize, SMEM_SZ);
    edge_gatherX<<<(NE + 7) / 8, 256>>>(p.Xh, p.nodeE, p.offE, p.cntE, p.msg, 0, NE);
    tgemm256<F_SNODE><<<(NE + 127) / 128, 512, SMEM_SZ>>>(p.msg, wph1, ah1 + DD, p.efh, p.sedge, NE);
    node_attn_agg<<<(NN + 7) / 8, 256>>>(p.efh, p.snode, p.sedge, p.edN,
                                         p.permN, p.offN, p.cntN,
                                         nullptr, p.H, p.Hh, p.wav2, p.snode, 0, NN);

    // 7) HGNN layer 2 -> d_out
    float* out = (float*)d_out;
    edge_gatherX<<<(NE + 7) / 8, 256>>>(p.Hh, p.nodeE, p.offE, p.cntE, p.msg, 1, NE);
    tgemm256<F_SNODE><<<(NE + 127) / 128, 512, SMEM_SZ>>>(p.msg, wph2, ah2 + DD, p.efh, p.sedge, NE);
    node_attn_agg<<<(NN + 7) / 8, 256>>>(p.efh, p.snode, p.sedge, p.edN,
                                         p.permN, p.offN, p.cntN,
                                         out + (size_t)NN * DD, out, nullptr, nullptr, nullptr, 1, NN);
}